// round 7
// baseline (speedup 1.0000x reference)
#include <cuda_runtime.h>
#include <math.h>
#include <stdint.h>

#define R_TOT 131072   // BS*N*G rows
#define TOKS  2048     // BS*N tokens

static constexpr size_t OFF_XOUT = 0;
static constexpr size_t OFF_Z    = 16777216;
static constexpr size_t OFF_ZH   = 25165824;
static constexpr size_t OFF_S    = 33554432;
static constexpr size_t OFF_KC   = 33685504;
static constexpr size_t OFF_VP   = 50462720;
static constexpr size_t OFF_G    = 67239936;
static constexpr size_t OFF_QN   = 67371008;
static constexpr size_t OFF_VC   = 84148224;
static constexpr size_t OFF_WN   = 100925440;

// Scratch
__device__ float g_xa[16777216];

// tf32 weights, n-major, k-interleaved (kpm) layouts
__device__ uint32_t gw_qkvo[65536];       // [sel][n128][kpos128]
__device__ uint32_t gw_enc [524288];      // [g][n64][kpos128]
__device__ uint32_t gw_pred[262144];      // [g][n64][kpos64]
__device__ uint32_t gw_gain[524288];      // [g][n128][kpos64]
__device__ uint32_t gw_up  [4194304];     // [g][ch8][n64][kpos128]  (8192/chunk)
__device__ uint32_t gw_down[4194304];     // [g][ch8][n128][kpos64]  (8192/chunk)
__device__ uint32_t gw_post[4194304];     // [g][ch4][n128][kpos128] (16384/chunk)
__device__ float    gw_plast[8192];       // [g][kpos128]

// ===========================================================================
__device__ __forceinline__ int kpm(int j) {
    return (j & ~7) | ((j & 3) << 1) | ((j >> 2) & 1);
}
__device__ __forceinline__ uint32_t cvt_tf32(float f) {
    uint32_t r;
    asm("cvt.rna.tf32.f32 %0, %1;" : "=r"(r) : "f"(f));
    return r;
}
__device__ __forceinline__ void mma8(float* c, const uint32_t* a,
                                     uint32_t b0, uint32_t b1) {
    asm volatile(
        "mma.sync.aligned.m16n8k8.row.col.f32.tf32.tf32.f32 "
        "{%0,%1,%2,%3}, {%4,%5,%6,%7}, {%8,%9}, {%0,%1,%2,%3};"
        : "+f"(c[0]), "+f"(c[1]), "+f"(c[2]), "+f"(c[3])
        : "r"(a[0]), "r"(a[1]), "r"(a[2]), "r"(a[3]), "r"(b0), "r"(b1));
}
__device__ __forceinline__ void cp16(void* smem, const void* gmem) {
    uint32_t s = (uint32_t)__cvta_generic_to_shared(smem);
    asm volatile("cp.async.cg.shared.global [%0], [%1], 16;" :: "r"(s), "l"(gmem));
}
__device__ __forceinline__ void cp_commit() {
    asm volatile("cp.async.commit_group;" ::: "memory");
}
template<int N> __device__ __forceinline__ void cp_wait() {
    asm volatile("cp.async.wait_group %0;" :: "n"(N) : "memory");
}
// rows x 128-word gmem rows -> smem stride 136
__device__ __forceinline__ void cpy136(uint32_t* dst, const uint32_t* src,
                                       int rows, int tid) {
    for (int i = tid; i < rows * 32; i += 256) {
        int k = i >> 5, n = (i & 31) * 4;
        cp16(dst + k * 136 + n, src + k * 128 + n);
    }
}
// rows x 64-word gmem rows -> smem stride 72
__device__ __forceinline__ void cpy72(uint32_t* dst, const uint32_t* src,
                                      int rows, int tid) {
    for (int i = tid; i < rows * 16; i += 256) {
        int k = i >> 4, n = (i & 15) * 4;
        cp16(dst + k * 72 + n, src + k * 64 + n);
    }
}
// 16xNT*8 warp tile, interleaved operands (LDS.64 fragments)
template<int LDA, int LDB, int NT>
__device__ __forceinline__ void gemm_i(float acc[NT][4],
        const uint32_t* __restrict__ As, const uint32_t* __restrict__ Bs,
        int mbase, int nbase, int K, int q, int t) {
#pragma unroll 2
    for (int kb = 0; kb < K; kb += 8) {
        uint2 al = *(const uint2*)(As + (mbase + q) * LDA + kb + 2 * t);
        uint2 ah = *(const uint2*)(As + (mbase + q + 8) * LDA + kb + 2 * t);
        uint32_t a[4] = {al.x, ah.x, al.y, ah.y};
#pragma unroll
        for (int nt = 0; nt < NT; nt++) {
            uint2 b = *(const uint2*)(Bs + (nbase + nt * 8 + q) * LDB + kb + 2 * t);
            mma8(acc[nt], a, b.x, b.y);
        }
    }
}
// 32x64 warp tile sharing b-fragments across 2 m-tiles
template<int LDA, int LDB>
__device__ __forceinline__ void gemm_i32(float acc[2][8][4],
        const uint32_t* __restrict__ As, const uint32_t* __restrict__ Bs,
        int mbase, int nbase, int K, int q, int t) {
#pragma unroll 2
    for (int kb = 0; kb < K; kb += 8) {
        uint2 a0l = *(const uint2*)(As + (mbase + q) * LDA + kb + 2 * t);
        uint2 a0h = *(const uint2*)(As + (mbase + q + 8) * LDA + kb + 2 * t);
        uint2 a1l = *(const uint2*)(As + (mbase + 16 + q) * LDA + kb + 2 * t);
        uint2 a1h = *(const uint2*)(As + (mbase + 24 + q) * LDA + kb + 2 * t);
        uint32_t a0[4] = {a0l.x, a0h.x, a0l.y, a0h.y};
        uint32_t a1[4] = {a1l.x, a1h.x, a1l.y, a1h.y};
#pragma unroll
        for (int nt = 0; nt < 8; nt++) {
            uint2 b = *(const uint2*)(Bs + (nbase + nt * 8 + q) * LDB + kb + 2 * t);
            mma8(acc[0][nt], a0, b.x, b.y);
            mma8(acc[1][nt], a1, b.x, b.y);
        }
    }
}
__device__ __forceinline__ void zero_acc(float* a, int n) {
#pragma unroll
    for (int i = 0; i < n; i++) a[i] = 0.f;
}

// ===========================================================================
// Transpose-convert weight prep: src [K][N] fp32 -> dst n-major k-interleaved
// dst idx = g*GS + (n>>NS)*NCHS + (k>>KS)*KCHS + (n&CM)*LDN + kpm(k&KM)
// ===========================================================================
__global__ void k_tcvt(const float* __restrict__ src, uint32_t* __restrict__ dst,
                       long sgs, int sld, long gs,
                       int ns, int nchs, int ks, int kchs,
                       int cm, int ldn, int km) {
    __shared__ float tile[32][33];
    int g = blockIdx.z;
    int k0 = blockIdx.x * 32, n0 = blockIdx.y * 32;
    int tr = threadIdx.x >> 5, tc = threadIdx.x & 31;
    const float* s = src + (size_t)g * sgs;
#pragma unroll
    for (int i = 0; i < 4; i++)
        tile[tr + i * 8][tc] = s[(size_t)(k0 + tr + i * 8) * sld + n0 + tc];
    __syncthreads();
    uint32_t* d = dst + (size_t)g * gs;
#pragma unroll
    for (int i = 0; i < 4; i++) {
        int n = n0 + tr + i * 8, k = k0 + tc;
        d[(size_t)(n >> ns) * nchs + (size_t)(k >> ks) * kchs
          + (n & cm) * ldn + kpm(k & km)] = cvt_tf32(tile[tc][tr + i * 8]);
    }
}
__global__ void k_tcvt_qkvo(const float* __restrict__ wq, const float* __restrict__ wk,
                            const float* __restrict__ wv, const float* __restrict__ wo) {
    __shared__ float tile[32][33];
    int sel = blockIdx.z;
    const float* s = (sel == 0) ? wq : (sel == 1) ? wk : (sel == 2) ? wv : wo;
    int k0 = blockIdx.x * 32, n0 = blockIdx.y * 32;
    int tr = threadIdx.x >> 5, tc = threadIdx.x & 31;
#pragma unroll
    for (int i = 0; i < 4; i++)
        tile[tr + i * 8][tc] = s[(size_t)(k0 + tr + i * 8) * 128 + n0 + tc];
    __syncthreads();
    uint32_t* d = gw_qkvo + sel * 16384;
#pragma unroll
    for (int i = 0; i < 4; i++) {
        int n = n0 + tr + i * 8, k = k0 + tc;
        d[n * 128 + kpm(k)] = cvt_tf32(tile[tc][tr + i * 8]);
    }
}
__global__ void k_plast(const float* __restrict__ pw) {
    int i = blockIdx.x * 256 + threadIdx.x;
    if (i < 8192) {
        int g = i >> 7, k = i & 127;
        gw_plast[g * 128 + kpm(k)] = pw[(size_t)(g * 128 + k) * 513 + 512];
    }
}

// ===========================================================================
// K1: fused LN + QKV + attention + wo.  grid 2048 (64 rows), 256 thr.
// ===========================================================================
__global__ __launch_bounds__(256, 1)
void k_fattn(const float* __restrict__ x,
             const float* __restrict__ latg, const float* __restrict__ latb,
             const float* __restrict__ bq, const float* __restrict__ bk,
             const float* __restrict__ bv, const float* __restrict__ bo) {
    extern __shared__ uint32_t sm[];
    uint32_t* As = sm;                   // 8704 (64 x 136)
    uint32_t* W0 = As + 8704;            // 17408
    uint32_t* QK = W0 + 17408;           // 17408: V at +0, K at +8704
    uint32_t* Qb = QK + 17408;           // 8448 (64 x 132, fp32)
    float* sc = (float*)(Qb + 8448);     // 512
    float* sg = sc + 512;                // 128
    float* sb = sg + 128;                // 128
    const int tid = threadIdx.x;
    const size_t rowbase = (size_t)blockIdx.x * 64;

    cpy136(W0, gw_qkvo, 128, tid);          cp_commit();  // wq
    cpy136(QK, gw_qkvo + 16384, 128, tid);  cp_commit();  // wk

    if (tid < 128) { sg[tid] = latg[tid]; sb[tid] = latb[tid]; }
    const int r = tid >> 2, qt = tid & 3;
    {
        const float* xr = x + (rowbase + r) * 128 + qt * 32;
        uint32_t* ar = As + r * 136;
        float s = 0.f, s2 = 0.f;
        for (int j = 0; j < 32; j += 4) {
            float4 v = *(const float4*)&xr[j];
            s += v.x + v.y + v.z + v.w;
            s2 += v.x * v.x + v.y * v.y + v.z * v.z + v.w * v.w;
            int c = qt * 32 + j;
            ar[kpm(c)]     = __float_as_uint(v.x);
            ar[kpm(c + 1)] = __float_as_uint(v.y);
            ar[kpm(c + 2)] = __float_as_uint(v.z);
            ar[kpm(c + 3)] = __float_as_uint(v.w);
        }
        s  += __shfl_xor_sync(0xffffffffu, s, 1);
        s  += __shfl_xor_sync(0xffffffffu, s, 2);
        s2 += __shfl_xor_sync(0xffffffffu, s2, 1);
        s2 += __shfl_xor_sync(0xffffffffu, s2, 2);
        float mu = s * (1.f / 128.f);
        float rs = rsqrtf(s2 * (1.f / 128.f) - mu * mu + 1e-5f);
        __syncthreads();   // sg/sb + all As writes
        for (int j = 0; j < 32; j++) {
            int c = qt * 32 + j;
            uint32_t* p = ar + kpm(c);
            float v = __uint_as_float(*p);
            *p = cvt_tf32((v - mu) * rs * sg[c] + sb[c]);
        }
    }
    __syncthreads();       // As final
    cp_wait<1>();          // wq done
    __syncthreads();

    const int w = tid >> 5, lane = tid & 31, q = lane >> 2, t = lane & 3;
    const int mbase = (w >> 1) * 16, nbase = (w & 1) * 64;

    {   // Q gemm -> Qb (fp32, stride 132)
        float acc[8][4];
        zero_acc(&acc[0][0], 32);
        gemm_i<136, 136, 8>(acc, As, W0, mbase, nbase, 128, q, t);
#pragma unroll
        for (int nt = 0; nt < 8; nt++) {
            int rr = mbase + q, cc = nbase + nt * 8 + 2 * t;
            float b0 = bq[cc], b1 = bq[cc + 1];
            Qb[rr * 132 + cc]           = __float_as_uint(acc[nt][0] + b0);
            Qb[rr * 132 + cc + 1]       = __float_as_uint(acc[nt][1] + b1);
            Qb[(rr + 8) * 132 + cc]     = __float_as_uint(acc[nt][2] + b0);
            Qb[(rr + 8) * 132 + cc + 1] = __float_as_uint(acc[nt][3] + b1);
        }
    }
    __syncthreads();                            // W0 reads done
    cpy136(W0, gw_qkvo + 32768, 128, tid);      // wv
    cp_commit();
    cp_wait<1>();                               // wk done
    __syncthreads();
    {   // K gemm -> regs -> overwrite QK upper half
        float acc[8][4];
        zero_acc(&acc[0][0], 32);
        gemm_i<136, 136, 8>(acc, As, QK, mbase, nbase, 128, q, t);
        __syncthreads();                        // all reads of wk done
        uint32_t* Ks = QK + 8704;
#pragma unroll
        for (int nt = 0; nt < 8; nt++) {
            int rr = mbase + q, cc = nbase + nt * 8 + 2 * t;
            float b0 = bk[cc], b1 = bk[cc + 1];
            Ks[rr * 136 + cc]           = __float_as_uint(acc[nt][0] + b0);
            Ks[rr * 136 + cc + 1]       = __float_as_uint(acc[nt][1] + b1);
            Ks[(rr + 8) * 136 + cc]     = __float_as_uint(acc[nt][2] + b0);
            Ks[(rr + 8) * 136 + cc + 1] = __float_as_uint(acc[nt][3] + b1);
        }
    }
    __syncthreads();
    {   // scores
        const float* Ks = (const float*)(QK + 8704);
#pragma unroll
        for (int i = 0; i < 2; i++) {
            int p = tid + 256 * i;
            int rowq = p >> 3;
            int grp = p >> 6, e = p & 7;
            const float* qp = (const float*)Qb + rowq * 132;
            const float* kp = Ks + (grp * 8 + e) * 136;
            float s = 0.f;
#pragma unroll 8
            for (int d = 0; d < 128; d += 4) {
                float4 a = *(const float4*)&qp[d];
                float4 b = *(const float4*)&kp[d];
                s += a.x * b.x + a.y * b.y + a.z * b.z + a.w * b.w;
            }
            sc[p] = s * 0.088388347648318447f;
        }
    }
    __syncthreads();
    if (tid < 64) {    // softmax
        float* row = sc + tid * 8;
        float m = row[0];
#pragma unroll
        for (int e = 1; e < 8; e++) m = fmaxf(m, row[e]);
        float ex[8], ssum = 0.f;
#pragma unroll
        for (int e = 0; e < 8; e++) { ex[e] = expf(row[e] - m); ssum += ex[e]; }
        float inv = 1.0f / ssum;
#pragma unroll
        for (int e = 0; e < 8; e++) row[e] = ex[e] * inv;
    }
    cp_wait<0>();                               // wv done
    __syncthreads();
    {   // V gemm -> overwrite QK lower half
        float acc[8][4];
        zero_acc(&acc[0][0], 32);
        gemm_i<136, 136, 8>(acc, As, W0, mbase, nbase, 128, q, t);
        __syncthreads();
        uint32_t* Vs = QK;
#pragma unroll
        for (int nt = 0; nt < 8; nt++) {
            int rr = mbase + q, cc = nbase + nt * 8 + 2 * t;
            float b0 = bv[cc], b1 = bv[cc + 1];
            Vs[rr * 136 + cc]           = __float_as_uint(acc[nt][0] + b0);
            Vs[rr * 136 + cc + 1]       = __float_as_uint(acc[nt][1] + b1);
            Vs[(rr + 8) * 136 + cc]     = __float_as_uint(acc[nt][2] + b0);
            Vs[(rr + 8) * 136 + cc + 1] = __float_as_uint(acc[nt][3] + b1);
        }
    }
    __syncthreads();                            // wv reads done; Vs final
    cpy136(W0, gw_qkvo + 49152, 128, tid);      // wo
    cp_commit();
    {   // o = attn @ V -> As (tf32, interleaved), in place
        const float* Vs = (const float*)QK;
        int rr = tid >> 2, d0 = (tid & 3) * 32;
        int vb = (rr & ~7) * 136;
        float a[8];
#pragma unroll
        for (int e = 0; e < 8; e++) a[e] = sc[rr * 8 + e];
        for (int j = 0; j < 32; j += 4) {
            float4 o = make_float4(0.f, 0.f, 0.f, 0.f);
#pragma unroll
            for (int e = 0; e < 8; e++) {
                float4 v = *(const float4*)&Vs[vb + e * 136 + d0 + j];
                o.x += a[e] * v.x; o.y += a[e] * v.y;
                o.z += a[e] * v.z; o.w += a[e] * v.w;
            }
            int c = d0 + j;
            As[rr * 136 + kpm(c)]     = cvt_tf32(o.x);
            As[rr * 136 + kpm(c + 1)] = cvt_tf32(o.y);
            As[rr * 136 + kpm(c + 2)] = cvt_tf32(o.z);
            As[rr * 136 + kpm(c + 3)] = cvt_tf32(o.w);
        }
    }
    cp_wait<0>();                               // wo done
    __syncthreads();                            // As(o) final
    {   // wo gemm + residual -> g_xa
        float acc[8][4];
        zero_acc(&acc[0][0], 32);
        gemm_i<136, 136, 8>(acc, As, W0, mbase, nbase, 128, q, t);
#pragma unroll
        for (int nt = 0; nt < 8; nt++) {
            int rr = mbase + q, cc = nbase + nt * 8 + 2 * t;
            float b0 = bo[cc], b1 = bo[cc + 1];
            size_t o0 = (rowbase + rr) * 128 + cc;
            size_t o1 = (rowbase + rr + 8) * 128 + cc;
            float2 x0 = *(const float2*)&x[o0];
            float2 x1 = *(const float2*)&x[o1];
            *(float2*)&g_xa[o0] = make_float2(x0.x + acc[nt][0] + b0,
                                              x0.y + acc[nt][1] + b1);
            *(float2*)&g_xa[o1] = make_float2(x1.x + acc[nt][2] + b0,
                                              x1.y + acc[nt][3] + b1);
        }
    }
}

// ===========================================================================
// K2: mega per-group kernel: small + MLP + post.  grid (16, 64), 256 thr.
// words: As@0(17408) Zs@17408(9216) Ds@26624(9216) B0@35840(8704)
//        B1@44544(9216) misc@53760(512)
// post overlays: B0p=Zs (17408 <= 18432), B1p=B0 (17408 <= 17920)
// ===========================================================================
__global__ __launch_bounds__(256, 1)
void k_mega(const float* __restrict__ zhp,
            const float* __restrict__ lng, const float* __restrict__ lnb,
            const float* __restrict__ encb, const float* __restrict__ predb,
            const float* __restrict__ gainb, const float* __restrict__ upb,
            const float* __restrict__ dwb, const float* __restrict__ pb,
            float* out) {
    extern __shared__ uint32_t sm[];
    uint32_t* As = sm;
    uint32_t* Zs = As + 17408;
    uint32_t* Ds = Zs + 9216;
    uint32_t* B0 = Ds + 9216;
    uint32_t* B1 = B0 + 8704;
    float* smu = (float*)(B1 + 9216);
    float* srs = smu + 128;
    float* pr  = srs + 128;
    uint32_t* B0p = Zs;
    uint32_t* B1p = B0;
    const int tid = threadIdx.x;
    const int g = blockIdx.y, p0 = blockIdx.x * 128;

    cpy136(B0, gw_enc + (size_t)g * 8192, 64, tid);  cp_commit();
    cpy72(B1, gw_pred + (size_t)g * 4096, 64, tid);  cp_commit();

    {   // As = tf32(x_attn) interleaved, stats
        const int r = tid >> 1, h = tid & 1;
        const float* xr = g_xa + ((size_t)(p0 + r) * 64 + g) * 128 + h * 64;
        uint32_t* ar = As + r * 136;
        float s = 0.f, s2 = 0.f;
        for (int j = 0; j < 64; j += 4) {
            float4 v = *(const float4*)&xr[j];
            s += v.x + v.y + v.z + v.w;
            s2 += v.x * v.x + v.y * v.y + v.z * v.z + v.w * v.w;
            int c = h * 64 + j;
            ar[kpm(c)]     = cvt_tf32(v.x);
            ar[kpm(c + 1)] = cvt_tf32(v.y);
            ar[kpm(c + 2)] = cvt_tf32(v.z);
            ar[kpm(c + 3)] = cvt_tf32(v.w);
        }
        s  += __shfl_xor_sync(0xffffffffu, s, 1);
        s2 += __shfl_xor_sync(0xffffffffu, s2, 1);
        float mu = s * (1.f / 128.f);
        if (h == 0) {
            smu[r] = mu;
            srs[r] = rsqrtf(s2 * (1.f / 128.f) - mu * mu + 1e-5f);
        }
    }
    cp_wait<1>();     // enc ready
    __syncthreads();

    const int w = tid >> 5, lane = tid & 31, q = lane >> 2, t = lane & 3;
    const int mbase = w * 16;

    {   // enc GEMM: z = x @ enc_w
        float acc[8][4];
        zero_acc(&acc[0][0], 32);
        gemm_i<136, 136, 8>(acc, As, B0, mbase, 0, 128, q, t);
        float sl = 0.f, sh = 0.f;
#pragma unroll
        for (int nt = 0; nt < 8; nt++) {
            int cc = nt * 8 + 2 * t;
            int rlo = mbase + q, rhi = rlo + 8;
            float z0 = acc[nt][0] + encb[g * 64 + cc];
            float z1 = acc[nt][1] + encb[g * 64 + cc + 1];
            float z2 = acc[nt][2] + encb[g * 64 + cc];
            float z3 = acc[nt][3] + encb[g * 64 + cc + 1];
            size_t qlo = (size_t)(p0 + rlo) * 64 + g;
            size_t qhi = (size_t)(p0 + rhi) * 64 + g;
            *(float2*)&out[OFF_Z + qlo * 64 + cc] = make_float2(z0, z1);
            *(float2*)&out[OFF_Z + qhi * 64 + cc] = make_float2(z2, z3);
            float2 plo = *(const float2*)&zhp[qlo * 64 + cc];
            float2 phi = *(const float2*)&zhp[qhi * 64 + cc];
            float d0 = z0 - plo.x, d1 = z1 - plo.y;
            float d2 = z2 - phi.x, d3 = z3 - phi.y;
            int p0c = kpm(cc), p1c = kpm(cc + 1);
            Zs[rlo * 72 + p0c] = cvt_tf32(z0);
            Zs[rlo * 72 + p1c] = cvt_tf32(z1);
            Zs[rhi * 72 + p0c] = cvt_tf32(z2);
            Zs[rhi * 72 + p1c] = cvt_tf32(z3);
            Ds[rlo * 72 + p0c] = cvt_tf32(d0);
            Ds[rlo * 72 + p1c] = cvt_tf32(d1);
            Ds[rhi * 72 + p0c] = cvt_tf32(d2);
            Ds[rhi * 72 + p1c] = cvt_tf32(d3);
            sl += d0 * d0 + d1 * d1;
            sh += d2 * d2 + d3 * d3;
        }
        sl += __shfl_xor_sync(0xffffffffu, sl, 1);
        sl += __shfl_xor_sync(0xffffffffu, sl, 2);
        sh += __shfl_xor_sync(0xffffffffu, sh, 1);
        sh += __shfl_xor_sync(0xffffffffu, sh, 2);
        if (t == 0) {
            float splo = sqrtf(sl), sphi = sqrtf(sh);
            size_t qlo = (size_t)(p0 + mbase + q) * 64 + g;
            size_t qhi = (size_t)(p0 + mbase + q + 8) * 64 + g;
            out[OFF_S + qlo] = splo;
            out[OFF_G + qlo] = fminf(splo, 1.0f);
            out[OFF_S + qhi] = sphi;
            out[OFF_G + qhi] = fminf(sphi, 1.0f);
        }
    }
    __syncthreads();                                   // Zs/Ds visible; B0 free
    cpy136(B0, gw_up + (size_t)g * 65536, 64, tid);    cp_commit();   // up0
    cp_wait<1>();                                      // pred ready
    __syncthreads();
    {   // pred GEMM
        float acc[8][4];
        zero_acc(&acc[0][0], 32);
        gemm_i<72, 72, 8>(acc, Zs, B1, mbase, 0, 64, q, t);
#pragma unroll
        for (int nt = 0; nt < 8; nt++) {
            int cc = nt * 8 + 2 * t;
            size_t qlo = (size_t)(p0 + mbase + q) * 64 + g;
            size_t qhi = (size_t)(p0 + mbase + q + 8) * 64 + g;
            float b0 = predb[g * 64 + cc], b1 = predb[g * 64 + cc + 1];
            *(float2*)&out[OFF_ZH + qlo * 64 + cc] =
                make_float2(acc[nt][0] + b0, acc[nt][1] + b1);
            *(float2*)&out[OFF_ZH + qhi * 64 + cc] =
                make_float2(acc[nt][2] + b0, acc[nt][3] + b1);
        }
    }
    __syncthreads();                                   // B1 free
    cpy72(B1, gw_gain + (size_t)g * 8192, 128, tid);   cp_commit();   // gain
    cp_wait<0>();                                      // up0 + gain ready
    __syncthreads();
    {   // gain GEMM + GLN epilogue -> As := tf32(hh) in place
        float acc[16][4];
        zero_acc(&acc[0][0], 64);
        gemm_i<72, 72, 16>(acc, Ds, B1, mbase, 0, 64, q, t);
        int rlo = mbase + q, rhi = rlo + 8;
        float mlo = smu[rlo], rslo = srs[rlo];
        float mhi = smu[rhi], rshi = srs[rhi];
#pragma unroll
        for (int nt = 0; nt < 16; nt++) {
            int cc = nt * 8 + 2 * t;
#pragma unroll
            for (int jj = 0; jj < 2; jj++) {
                int c = cc + jj, cp = kpm(c);
                float lg = lng[(size_t)g * 128 + c], lb = lnb[(size_t)g * 128 + c];
                float gb = gainb[(size_t)g * 128 + c];
                float gn0 = 1.0f + 0.1f * tanhf(acc[nt][jj] + gb);
                float gn1 = 1.0f + 0.1f * tanhf(acc[nt][2 + jj] + gb);
                float x0 = __uint_as_float(As[rlo * 136 + cp]);
                float x1 = __uint_as_float(As[rhi * 136 + cp]);
                As[rlo * 136 + cp] = cvt_tf32(((x0 - mlo) * rslo * lg + lb) * gn0);
                As[rhi * 136 + cp] = cvt_tf32(((x1 - mhi) * rshi * lg + lb) * gn1);
            }
        }
    }
    __syncthreads();                                   // As(hh); B1/Ds free
    cpy72(B1, gw_down + (size_t)g * 65536, 128, tid);  cp_commit();   // down0

    uint32_t* Us = Zs;
    float oacc[16][4];
    zero_acc(&oacc[0][0], 64);
    for (int ch = 0; ch < 8; ch++) {
        float uacc[8][4];
        zero_acc(&uacc[0][0], 32);
        gemm_i<136, 136, 8>(uacc, As, B0, mbase, 0, 128, q, t);
#pragma unroll
        for (int nt = 0; nt < 8; nt++) {
            int cc = nt * 8 + 2 * t;
            int rlo = mbase + q, rhi = rlo + 8;
#pragma unroll
            for (int jj = 0; jj < 2; jj++) {
                float bb = upb[(size_t)g * 512 + ch * 64 + cc + jj];
                float u0 = uacc[nt][jj] + bb;
                float u1 = uacc[nt][2 + jj] + bb;
                u0 = 0.5f * u0 * (1.0f + erff(u0 * 0.70710678118654752f));
                u1 = 0.5f * u1 * (1.0f + erff(u1 * 0.70710678118654752f));
                int cp = kpm(cc + jj);
                Us[rlo * 72 + cp] = cvt_tf32(u0);
                Us[rhi * 72 + cp] = cvt_tf32(u1);
            }
        }
        __syncthreads();                 // Us visible; B0 reads done
        if (ch < 7) {
            cpy136(B0, gw_up + (size_t)g * 65536 + (ch + 1) * 8192, 64, tid);
            cp_commit();
            cp_wait<1>();                // down_ch ready
        } else {
            cp_wait<0>();
        }
        __syncthreads();
        gemm_i<72, 72, 16>(oacc, Us, B1, mbase, 0, 64, q, t);
        if (ch < 7) {
            __syncthreads();             // B1 reads done
            cpy72(B1, gw_down + (size_t)g * 65536 + (ch + 1) * 8192, 128, tid);
            cp_commit();
            cp_wait<1>();                // up_{ch+1} ready
            __syncthreads();
        }
    }
    __syncthreads();                     // last down gemm reads done
    {   // MLP epilogue -> gmem x_out AND As := tf32(x_out)
#pragma unroll
        for (int nt = 0; nt < 16; nt++) {
            int cc = nt * 8 + 2 * t;
            int rlo = mbase + q, rhi = rlo + 8;
            float b0 = dwb[(size_t)g * 128 + cc], b1 = dwb[(size_t)g * 128 + cc + 1];
            size_t o0 = ((size_t)(p0 + rlo) * 64 + g) * 128 + cc;
            size_t o1 = ((size_t)(p0 + rhi) * 64 + g) * 128 + cc;
            float2 x0 = *(const float2*)&g_xa[o0];
            float2 x1 = *(const float2*)&g_xa[o1];
            float v00 = x0.x + oacc[nt][0] + b0, v01 = x0.y + oacc[nt][1] + b1;
            float v10 = x1.x + oacc[nt][2] + b0, v11 = x1.y + oacc[nt][3] + b1;
            *(float2*)&out[OFF_XOUT + o0] = make_float2(v00, v01);
            *(float2*)&out[OFF_XOUT + o1] = make_float2(v10, v11);
            int p0c = kpm(cc), p1c = kpm(cc + 1);
            As[rlo * 136 + p0c] = cvt_tf32(v00);
            As[rlo * 136 + p1c] = cvt_tf32(v01);
            As[rhi * 136 + p0c] = cvt_tf32(v10);
            As[rhi * 136 + p1c] = cvt_tf32(v11);
        }
    }
    __syncthreads();                     // As(x_out); Zs/Ds/B0/B1 dead
    cpy136(B0p, gw_post + (size_t)g * 65536, 128, tid);          cp_commit();
    cpy136(B1p, gw_post + (size_t)g * 65536 + 16384, 128, tid);  cp_commit();

    if (tid < 128) {   // w_nov (permuted plast matches As interleave)
        const float* wl = gw_plast + g * 128;
        float s = 0.f;
        for (int k = 0; k < 128; k++)
            s += __uint_as_float(As[tid * 136 + k]) * wl[k];
        s += pb[(size_t)g * 513 + 512];
        out[OFF_WN + (size_t)(p0 + tid) * 64 + g] = 1.0f / (1.0f + expf(-s));
    }
    const int mb2 = (w >> 1) * 32, nb2 = (w & 1) * 64, wc = w & 1;

    for (int ch = 0; ch < 4; ch++) {
        if (ch < 3) cp_wait<1>(); else cp_wait<0>();
        __syncthreads();
        uint32_t* Bs = (ch & 1) ? B1p : B0p;
        float acc[2][8][4];
        zero_acc(&acc[0][0][0], 64);
        gemm_i32<136, 136>(acc, As, Bs, mb2, nb2, 128, q, t);
#pragma unroll
        for (int mi = 0; mi < 2; mi++)
#pragma unroll
            for (int nt = 0; nt < 8; nt++) {
                int cc = nb2 + nt * 8 + 2 * t;
                float b0 = pb[(size_t)g * 513 + ch * 128 + cc];
                float b1 = pb[(size_t)g * 513 + ch * 128 + cc + 1];
                acc[mi][nt][0] += b0; acc[mi][nt][1] += b1;
                acc[mi][nt][2] += b0; acc[mi][nt][3] += b1;
            }
        if (ch == 1 || ch == 3) {
            size_t off = (ch == 1) ? OFF_VP : OFF_VC;
#pragma unroll
            for (int mi = 0; mi < 2; mi++)
#pragma unroll
                for (int nt = 0; nt < 8; nt++) {
                    int rr = mb2 + mi * 16 + q, cc = nb2 + nt * 8 + 2 * t;
                    size_t o0 = off + ((size_t)(p0 + rr) * 64 + g) * 128 + cc;
                    size_t o1 = off + ((size_t)(p0 + rr + 8) * 64 + g) * 128 + cc;
                    *(float2*)&out[o0] = make_float2(acc[mi][nt][0], acc[mi][nt][1]);
                    *(float2*)&out[o1] = make_float2(acc[mi][nt][2], acc[mi][nt][3]);
                }
        } else {
            float sl[2] = {0.f, 0.f}, sh[2] = {0.f, 0.f};
#pragma unroll
            for (int mi = 0; mi < 2; mi++)
#pragma unroll
                for (int nt = 0; nt < 8; nt++) {
                    sl[mi] += acc[mi][nt][0] * acc[mi][nt][0] + acc[mi][nt][1] * acc[mi][nt][1];
                    sh[mi] += acc[mi][nt][2] * acc[mi][nt][2] + acc[mi][nt][3] * acc[mi][nt][3];
                }
#pragma unroll
            for (int mi = 0; mi < 2; mi++) {
                sl[mi] += __shfl_xor_sync(0xffffffffu, sl[mi], 1);
                sl[mi] += __shfl_xor_sync(0xffffffffu, sl[mi], 2);
                sh[mi] += __shfl_xor_sync(0xffffffffu, sh[mi], 1);
                sh[mi] += __shfl_xor_sync(0xffffffffu, sh[mi], 2);
            }
            if (t == 0) {
#pragma unroll
                for (int mi = 0; mi < 2; mi++) {
                    pr[wc * 128 + mb2 + mi * 16 + q] = sl[mi];
                    pr[wc * 128 + mb2 + mi * 16 + q + 8] = sh[mi];
                }
            }
            __syncthreads();
            size_t off = (ch == 0) ? OFF_KC : OFF_QN;
#pragma unroll
            for (int mi = 0; mi < 2; mi++)
#pragma unroll
                for (int nt = 0; nt < 8; nt++) {
                    int rr = mb2 + mi * 16 + q, cc = nb2 + nt * 8 + 2 * t;
                    float i0 = 1.0f / fmaxf(sqrtf(pr[rr] + pr[128 + rr]), 1e-6f);
                    float i1 = 1.0f / fmaxf(sqrtf(pr[rr + 8] + pr[128 + rr + 8]), 1e-6f);
                    size_t o0 = off + ((size_t)(p0 + rr) * 64 + g) * 128 + cc;
                    size_t o1 = off + ((size_t)(p0 + rr + 8) * 64 + g) * 128 + cc;
                    *(float2*)&out[o0] = make_float2(acc[mi][nt][0] * i0, acc[mi][nt][1] * i0);
                    *(float2*)&out[o1] = make_float2(acc[mi][nt][2] * i1, acc[mi][nt][3] * i1);
                }
        }
        if (ch < 2) {
            __syncthreads();
            cpy136((ch & 1) ? B1p : B0p,
                   gw_post + (size_t)g * 65536 + (ch + 2) * 16384, 128, tid);
            cp_commit();
        }
    }
}

// ===========================================================================
extern "C" void kernel_launch(void* const* d_in, const int* in_sizes, int n_in,
                              void* d_out, int out_size) {
    const float* x_col  = (const float*)d_in[0];
    const float* zhp    = (const float*)d_in[1];
    const float* ln_g   = (const float*)d_in[2];
    const float* ln_b   = (const float*)d_in[3];
    const float* up_w   = (const float*)d_in[4];
    const float* up_b   = (const float*)d_in[5];
    const float* down_w = (const float*)d_in[6];
    const float* down_b = (const float*)d_in[7];
    const float* lat_g  = (const float*)d_in[8];
    const float* lat_b  = (const float*)d_in[9];
    const float* wq     = (const float*)d_in[10];
    const float* bq     = (const float*)d_in[11];
    const float* wk     = (const float*)d_in[12];
    const float* bk     = (const float*)d_in[13];
    const float* wv     = (const float*)d_in[14];
    const float* bv     = (const float*)d_in[15];
    const float* wo     = (const float*)d_in[16];
    const float* bo     = (const float*)d_in[17];
    const float* post_w = (const float*)d_in[18];
    const float* post_b = (const float*)d_in[19];
    const float* enc_w  = (const float*)d_in[20];
    const float* enc_b  = (const float*)d_in[21];
    const float* pred_w = (const float*)d_in[22];
    const float* pred_b = (const float*)d_in[23];
    const float* gain_w = (const float*)d_in[24];
    const float* gain_b = (const float*)d_in[25];
    float* out = (float*)d_out;

    const int SM_FA   = 52736 * 4;   // 210944
    const int SM_MEGA = 54272 * 4;   // 217088

    cudaFuncSetAttribute(k_fattn, cudaFuncAttributeMaxDynamicSharedMemorySize, SM_FA);
    cudaFuncSetAttribute(k_mega,  cudaFuncAttributeMaxDynamicSharedMemorySize, SM_MEGA);

    // weight prep: transpose-convert into n-major interleaved layouts
    uint32_t* d_enc;  cudaGetSymbolAddress((void**)&d_enc,  gw_enc);
    uint32_t* d_pred; cudaGetSymbolAddress((void**)&d_pred, gw_pred);
    uint32_t* d_gain; cudaGetSymbolAddress((void**)&d_gain, gw_gain);
    uint32_t* d_up;   cudaGetSymbolAddress((void**)&d_up,   gw_up);
    uint32_t* d_down; cudaGetSymbolAddress((void**)&d_down, gw_down);
    uint32_t* d_post; cudaGetSymbolAddress((void**)&d_post, gw_post);

    k_tcvt_qkvo<<<dim3(4, 4, 4), 256>>>(wq, wk, wv, wo);
    k_tcvt<<<dim3(4, 2, 64), 256>>>(enc_w, d_enc, 8192, 64, 8192,
                                    6, 0, 7, 0, 63, 128, 127);
    k_tcvt<<<dim3(2, 2, 64), 256>>>(pred_w, d_pred, 4096, 64, 4096,
                                    6, 0, 6, 0, 63, 64, 63);
    k_tcvt<<<dim3(2, 4, 64), 256>>>(gain_w, d_gain, 8192, 128, 8192,
                                    7, 0, 6, 0, 127, 64, 63);
    k_tcvt<<<dim3(4, 16, 64), 256>>>(up_w, d_up, 65536, 512, 65536,
                                     6, 8192, 7, 0, 63, 128, 127);
    k_tcvt<<<dim3(16, 4, 64), 256>>>(down_w, d_down, 65536, 128, 65536,
                                     7, 0, 6, 8192, 127, 64, 63);
    k_tcvt<<<dim3(4, 16, 64), 256>>>(post_w, d_post, 65664, 513, 65536,
                                     7, 16384, 7, 0, 127, 128, 127);
    k_plast<<<32, 256>>>(post_w);

    k_fattn<<<R_TOT / 64, 256, SM_FA>>>(x_col, lat_g, lat_b, bq, bk, bv, bo);
    k_mega<<<dim3(TOKS / 128, 64), 256, SM_MEGA>>>(zhp, ln_g, ln_b,
                                                   enc_b, pred_b, gain_b,
                                                   up_b, down_b, post_b, out);
}

// round 8
// speedup vs baseline: 1.0144x; 1.0144x over previous
#include <cuda_runtime.h>
#include <math.h>
#include <stdint.h>

#define R_TOT 131072   // BS*N*G rows
#define TOKS  2048     // BS*N tokens

static constexpr size_t OFF_XOUT = 0;
static constexpr size_t OFF_Z    = 16777216;
static constexpr size_t OFF_ZH   = 25165824;
static constexpr size_t OFF_S    = 33554432;
static constexpr size_t OFF_KC   = 33685504;
static constexpr size_t OFF_VP   = 50462720;
static constexpr size_t OFF_G    = 67239936;
static constexpr size_t OFF_QN   = 67371008;
static constexpr size_t OFF_VC   = 84148224;
static constexpr size_t OFF_WN   = 100925440;

// Scratch
__device__ float g_xa[16777216];

// tf32 weights, n-major, k-interleaved (kpm) layouts
__device__ uint32_t gw_qkvo[65536];       // [sel][n128][kpos128]
__device__ uint32_t gw_enc [524288];      // [g][n64][kpos128]
__device__ uint32_t gw_pred[262144];      // [g][n64][kpos64]
__device__ uint32_t gw_gain[524288];      // [g][n128][kpos64]
__device__ uint32_t gw_up  [4194304];     // [g][ch8][n64][kpos128]  (8192/chunk)
__device__ uint32_t gw_down[4194304];     // [g][ch8][n128][kpos64]  (8192/chunk)
__device__ uint32_t gw_post[4194304];     // [g][ch4][n128][kpos128] (16384/chunk)
__device__ float    gw_plast[8192];       // [g][kpos128]

// ===========================================================================
__device__ __forceinline__ int kpm(int j) {
    return (j & ~7) | ((j & 3) << 1) | ((j >> 2) & 1);
}
__device__ __forceinline__ uint32_t cvt_tf32(float f) {
    uint32_t r;
    asm("cvt.rna.tf32.f32 %0, %1;" : "=r"(r) : "f"(f));
    return r;
}
__device__ __forceinline__ void mma8(float* c, const uint32_t* a,
                                     uint32_t b0, uint32_t b1) {
    asm volatile(
        "mma.sync.aligned.m16n8k8.row.col.f32.tf32.tf32.f32 "
        "{%0,%1,%2,%3}, {%4,%5,%6,%7}, {%8,%9}, {%0,%1,%2,%3};"
        : "+f"(c[0]), "+f"(c[1]), "+f"(c[2]), "+f"(c[3])
        : "r"(a[0]), "r"(a[1]), "r"(a[2]), "r"(a[3]), "r"(b0), "r"(b1));
}
__device__ __forceinline__ void cp16(void* smem, const void* gmem) {
    uint32_t s = (uint32_t)__cvta_generic_to_shared(smem);
    asm volatile("cp.async.cg.shared.global [%0], [%1], 16;" :: "r"(s), "l"(gmem));
}
__device__ __forceinline__ void cp_commit() {
    asm volatile("cp.async.commit_group;" ::: "memory");
}
template<int N> __device__ __forceinline__ void cp_wait() {
    asm volatile("cp.async.wait_group %0;" :: "n"(N) : "memory");
}
// rows x 128-word gmem rows -> smem stride 136  (512-thread blocks)
__device__ __forceinline__ void cpy136(uint32_t* dst, const uint32_t* src,
                                       int rows, int tid) {
    for (int i = tid; i < rows * 32; i += 512) {
        int k = i >> 5, n = (i & 31) * 4;
        cp16(dst + k * 136 + n, src + k * 128 + n);
    }
}
// rows x 64-word gmem rows -> smem stride 72
__device__ __forceinline__ void cpy72(uint32_t* dst, const uint32_t* src,
                                      int rows, int tid) {
    for (int i = tid; i < rows * 16; i += 512) {
        int k = i >> 4, n = (i & 15) * 4;
        cp16(dst + k * 72 + n, src + k * 64 + n);
    }
}
// 16 x NT*8 warp tile, interleaved operands (LDS.64 fragments)
template<int LDA, int LDB, int NT>
__device__ __forceinline__ void gemm_i(float acc[NT][4],
        const uint32_t* __restrict__ As, const uint32_t* __restrict__ Bs,
        int mbase, int nbase, int K, int q, int t) {
#pragma unroll 2
    for (int kb = 0; kb < K; kb += 8) {
        uint2 al = *(const uint2*)(As + (mbase + q) * LDA + kb + 2 * t);
        uint2 ah = *(const uint2*)(As + (mbase + q + 8) * LDA + kb + 2 * t);
        uint32_t a[4] = {al.x, ah.x, al.y, ah.y};
#pragma unroll
        for (int nt = 0; nt < NT; nt++) {
            uint2 b = *(const uint2*)(Bs + (nbase + nt * 8 + q) * LDB + kb + 2 * t);
            mma8(acc[nt], a, b.x, b.y);
        }
    }
}
__device__ __forceinline__ void zero_acc(float* a, int n) {
#pragma unroll
    for (int i = 0; i < n; i++) a[i] = 0.f;
}

// ===========================================================================
// Transpose-convert weight prep
// ===========================================================================
__global__ void k_tcvt(const float* __restrict__ src, uint32_t* __restrict__ dst,
                       long sgs, int sld, long gs,
                       int ns, int nchs, int ks, int kchs,
                       int cm, int ldn, int km) {
    __shared__ float tile[32][33];
    int g = blockIdx.z;
    int k0 = blockIdx.x * 32, n0 = blockIdx.y * 32;
    int tr = threadIdx.x >> 5, tc = threadIdx.x & 31;
    const float* s = src + (size_t)g * sgs;
#pragma unroll
    for (int i = 0; i < 4; i++)
        tile[tr + i * 8][tc] = s[(size_t)(k0 + tr + i * 8) * sld + n0 + tc];
    __syncthreads();
    uint32_t* d = dst + (size_t)g * gs;
#pragma unroll
    for (int i = 0; i < 4; i++) {
        int n = n0 + tr + i * 8, k = k0 + tc;
        d[(size_t)(n >> ns) * nchs + (size_t)(k >> ks) * kchs
          + (n & cm) * ldn + kpm(k & km)] = cvt_tf32(tile[tc][tr + i * 8]);
    }
}
__global__ void k_tcvt_qkvo(const float* __restrict__ wq, const float* __restrict__ wk,
                            const float* __restrict__ wv, const float* __restrict__ wo) {
    __shared__ float tile[32][33];
    int sel = blockIdx.z;
    const float* s = (sel == 0) ? wq : (sel == 1) ? wk : (sel == 2) ? wv : wo;
    int k0 = blockIdx.x * 32, n0 = blockIdx.y * 32;
    int tr = threadIdx.x >> 5, tc = threadIdx.x & 31;
#pragma unroll
    for (int i = 0; i < 4; i++)
        tile[tr + i * 8][tc] = s[(size_t)(k0 + tr + i * 8) * 128 + n0 + tc];
    __syncthreads();
    uint32_t* d = gw_qkvo + sel * 16384;
#pragma unroll
    for (int i = 0; i < 4; i++) {
        int n = n0 + tr + i * 8, k = k0 + tc;
        d[n * 128 + kpm(k)] = cvt_tf32(tile[tc][tr + i * 8]);
    }
}
__global__ void k_plast(const float* __restrict__ pw) {
    int i = blockIdx.x * 256 + threadIdx.x;
    if (i < 8192) {
        int g = i >> 7, k = i & 127;
        gw_plast[g * 128 + kpm(k)] = pw[(size_t)(g * 128 + k) * 513 + 512];
    }
}

// ===========================================================================
// K1: fused LN + QKV + attention + wo.  grid 2048 (64 rows), 512 thr.
// ===========================================================================
__global__ __launch_bounds__(512, 1)
void k_fattn(const float* __restrict__ x,
             const float* __restrict__ latg, const float* __restrict__ latb,
             const float* __restrict__ bq, const float* __restrict__ bk,
             const float* __restrict__ bv, const float* __restrict__ bo) {
    extern __shared__ uint32_t sm[];
    uint32_t* As = sm;                   // 8704 (64 x 136)
    uint32_t* W0 = As + 8704;            // 17408
    uint32_t* QK = W0 + 17408;           // 17408: V at +0, K at +8704
    uint32_t* Qb = QK + 17408;           // 8448 (64 x 132, fp32)
    float* sc = (float*)(Qb + 8448);     // 512
    float* sg = sc + 512;                // 128
    float* sb = sg + 128;                // 128
    const int tid = threadIdx.x;
    const size_t rowbase = (size_t)blockIdx.x * 64;

    cpy136(W0, gw_qkvo, 128, tid);          cp_commit();  // wq
    cpy136(QK, gw_qkvo + 16384, 128, tid);  cp_commit();  // wk

    if (tid < 128) { sg[tid] = latg[tid]; sb[tid] = latb[tid]; }
    const int r = tid >> 3, qt = tid & 7;   // 64 rows x 8 thr, 16 cols each
    {
        const float* xr = x + (rowbase + r) * 128 + qt * 16;
        uint32_t* ar = As + r * 136;
        float s = 0.f, s2 = 0.f;
        for (int j = 0; j < 16; j += 4) {
            float4 v = *(const float4*)&xr[j];
            s += v.x + v.y + v.z + v.w;
            s2 += v.x * v.x + v.y * v.y + v.z * v.z + v.w * v.w;
            int c = qt * 16 + j;
            ar[kpm(c)]     = __float_as_uint(v.x);
            ar[kpm(c + 1)] = __float_as_uint(v.y);
            ar[kpm(c + 2)] = __float_as_uint(v.z);
            ar[kpm(c + 3)] = __float_as_uint(v.w);
        }
        s  += __shfl_xor_sync(0xffffffffu, s, 1);
        s  += __shfl_xor_sync(0xffffffffu, s, 2);
        s  += __shfl_xor_sync(0xffffffffu, s, 4);
        s2 += __shfl_xor_sync(0xffffffffu, s2, 1);
        s2 += __shfl_xor_sync(0xffffffffu, s2, 2);
        s2 += __shfl_xor_sync(0xffffffffu, s2, 4);
        float mu = s * (1.f / 128.f);
        float rs = rsqrtf(s2 * (1.f / 128.f) - mu * mu + 1e-5f);
        __syncthreads();   // sg/sb + all As writes
        for (int j = 0; j < 16; j++) {
            int c = qt * 16 + j;
            uint32_t* p = ar + kpm(c);
            float v = __uint_as_float(*p);
            *p = cvt_tf32((v - mu) * rs * sg[c] + sb[c]);
        }
    }
    __syncthreads();       // As final
    cp_wait<1>();          // wq done
    __syncthreads();

    const int w = tid >> 5, lane = tid & 31, q = lane >> 2, t = lane & 3;
    const int mbase = (w & 3) * 16, nbase = (w >> 2) * 32;   // 4 slabs x 4 n-quarters

    {   // Q gemm -> Qb (fp32, stride 132)
        float acc[4][4];
        zero_acc(&acc[0][0], 16);
        gemm_i<136, 136, 4>(acc, As, W0, mbase, nbase, 128, q, t);
#pragma unroll
        for (int nt = 0; nt < 4; nt++) {
            int rr = mbase + q, cc = nbase + nt * 8 + 2 * t;
            float b0 = bq[cc], b1 = bq[cc + 1];
            Qb[rr * 132 + cc]           = __float_as_uint(acc[nt][0] + b0);
            Qb[rr * 132 + cc + 1]       = __float_as_uint(acc[nt][1] + b1);
            Qb[(rr + 8) * 132 + cc]     = __float_as_uint(acc[nt][2] + b0);
            Qb[(rr + 8) * 132 + cc + 1] = __float_as_uint(acc[nt][3] + b1);
        }
    }
    __syncthreads();                            // W0 reads done
    cpy136(W0, gw_qkvo + 32768, 128, tid);      // wv
    cp_commit();
    cp_wait<1>();                               // wk done
    __syncthreads();
    {   // K gemm -> regs -> overwrite QK upper half
        float acc[4][4];
        zero_acc(&acc[0][0], 16);
        gemm_i<136, 136, 4>(acc, As, QK, mbase, nbase, 128, q, t);
        __syncthreads();                        // all reads of wk done
        uint32_t* Ks = QK + 8704;
#pragma unroll
        for (int nt = 0; nt < 4; nt++) {
            int rr = mbase + q, cc = nbase + nt * 8 + 2 * t;
            float b0 = bk[cc], b1 = bk[cc + 1];
            Ks[rr * 136 + cc]           = __float_as_uint(acc[nt][0] + b0);
            Ks[rr * 136 + cc + 1]       = __float_as_uint(acc[nt][1] + b1);
            Ks[(rr + 8) * 136 + cc]     = __float_as_uint(acc[nt][2] + b0);
            Ks[(rr + 8) * 136 + cc + 1] = __float_as_uint(acc[nt][3] + b1);
        }
    }
    __syncthreads();
    {   // scores: 512 (grp,c,e) pairs, one per thread
        const float* Ks = (const float*)(QK + 8704);
        int rowq = tid >> 3;
        int grp = tid >> 6, e = tid & 7;
        const float* qp = (const float*)Qb + rowq * 132;
        const float* kp = Ks + (grp * 8 + e) * 136;
        float s = 0.f;
#pragma unroll 8
        for (int d = 0; d < 128; d += 4) {
            float4 a = *(const float4*)&qp[d];
            float4 b = *(const float4*)&kp[d];
            s += a.x * b.x + a.y * b.y + a.z * b.z + a.w * b.w;
        }
        sc[tid] = s * 0.088388347648318447f;
    }
    __syncthreads();
    if (tid < 64) {    // softmax over e per (grp,c)
        float* row = sc + tid * 8;
        float m = row[0];
#pragma unroll
        for (int e = 1; e < 8; e++) m = fmaxf(m, row[e]);
        float ex[8], ssum = 0.f;
#pragma unroll
        for (int e = 0; e < 8; e++) { ex[e] = expf(row[e] - m); ssum += ex[e]; }
        float inv = 1.0f / ssum;
#pragma unroll
        for (int e = 0; e < 8; e++) row[e] = ex[e] * inv;
    }
    cp_wait<0>();                               // wv done
    __syncthreads();
    {   // V gemm -> overwrite QK lower half
        float acc[4][4];
        zero_acc(&acc[0][0], 16);
        gemm_i<136, 136, 4>(acc, As, W0, mbase, nbase, 128, q, t);
        __syncthreads();
        uint32_t* Vs = QK;
#pragma unroll
        for (int nt = 0; nt < 4; nt++) {
            int rr = mbase + q, cc = nbase + nt * 8 + 2 * t;
            float b0 = bv[cc], b1 = bv[cc + 1];
            Vs[rr * 136 + cc]           = __float_as_uint(acc[nt][0] + b0);
            Vs[rr * 136 + cc + 1]       = __float_as_uint(acc[nt][1] + b1);
            Vs[(rr + 8) * 136 + cc]     = __float_as_uint(acc[nt][2] + b0);
            Vs[(rr + 8) * 136 + cc + 1] = __float_as_uint(acc[nt][3] + b1);
        }
    }
    __syncthreads();                            // wv reads done; Vs final
    cpy136(W0, gw_qkvo + 49152, 128, tid);      // wo
    cp_commit();
    {   // o = attn @ V -> As (tf32, interleaved), in place
        const float* Vs = (const float*)QK;
        int rr = tid >> 3, d0 = (tid & 7) * 16;
        int vb = (rr & ~7) * 136;
        float a[8];
#pragma unroll
        for (int e = 0; e < 8; e++) a[e] = sc[rr * 8 + e];
        for (int j = 0; j < 16; j += 4) {
            float4 o = make_float4(0.f, 0.f, 0.f, 0.f);
#pragma unroll
            for (int e = 0; e < 8; e++) {
                float4 v = *(const float4*)&Vs[vb + e * 136 + d0 + j];
                o.x += a[e] * v.x; o.y += a[e] * v.y;
                o.z += a[e] * v.z; o.w += a[e] * v.w;
            }
            int c = d0 + j;
            As[rr * 136 + kpm(c)]     = cvt_tf32(o.x);
            As[rr * 136 + kpm(c + 1)] = cvt_tf32(o.y);
            As[rr * 136 + kpm(c + 2)] = cvt_tf32(o.z);
            As[rr * 136 + kpm(c + 3)] = cvt_tf32(o.w);
        }
    }
    cp_wait<0>();                               // wo done
    __syncthreads();                            // As(o) final
    {   // wo gemm + residual -> g_xa
        float acc[4][4];
        zero_acc(&acc[0][0], 16);
        gemm_i<136, 136, 4>(acc, As, W0, mbase, nbase, 128, q, t);
#pragma unroll
        for (int nt = 0; nt < 4; nt++) {
            int rr = mbase + q, cc = nbase + nt * 8 + 2 * t;
            float b0 = bo[cc], b1 = bo[cc + 1];
            size_t o0 = (rowbase + rr) * 128 + cc;
            size_t o1 = (rowbase + rr + 8) * 128 + cc;
            float2 x0 = *(const float2*)&x[o0];
            float2 x1 = *(const float2*)&x[o1];
            *(float2*)&g_xa[o0] = make_float2(x0.x + acc[nt][0] + b0,
                                              x0.y + acc[nt][1] + b1);
            *(float2*)&g_xa[o1] = make_float2(x1.x + acc[nt][2] + b0,
                                              x1.y + acc[nt][3] + b1);
        }
    }
}

// ===========================================================================
// K2: mega per-group kernel: small + MLP + post.  grid (16, 64), 512 thr.
// 16 warps: wm = w&7 (16-row slab), wn = w>>3 (n half).
// ===========================================================================
__global__ __launch_bounds__(512, 1)
void k_mega(const float* __restrict__ zhp,
            const float* __restrict__ lng, const float* __restrict__ lnb,
            const float* __restrict__ encb, const float* __restrict__ predb,
            const float* __restrict__ gainb, const float* __restrict__ upb,
            const float* __restrict__ dwb, const float* __restrict__ pb,
            float* out) {
    extern __shared__ uint32_t sm[];
    uint32_t* As = sm;                  // 17408
    uint32_t* Zs = As + 17408;          // 9216
    uint32_t* Ds = Zs + 9216;           // 9216
    uint32_t* B0 = Ds + 9216;           // 8704
    uint32_t* B1 = B0 + 8704;           // 9216
    float* smu = (float*)(B1 + 9216);   // 128
    float* srs = smu + 128;             // 128
    float* pr  = srs + 128;             // 256
    uint32_t* B0p = Zs;                 // post overlay (Zs+Ds = 18432 >= 17408)
    uint32_t* B1p = B0;                 // post overlay (B0+B1 = 17920 >= 17408)
    const int tid = threadIdx.x;
    const int g = blockIdx.y, p0 = blockIdx.x * 128;

    cpy136(B0, gw_enc + (size_t)g * 8192, 64, tid);  cp_commit();
    cpy72(B1, gw_pred + (size_t)g * 4096, 64, tid);  cp_commit();

    {   // As = tf32(x_attn) interleaved, stats: 128 rows x 4 thr, 32 cols each
        const int r = tid >> 2, h = tid & 3;
        const float* xr = g_xa + ((size_t)(p0 + r) * 64 + g) * 128 + h * 32;
        uint32_t* ar = As + r * 136;
        float s = 0.f, s2 = 0.f;
        for (int j = 0; j < 32; j += 4) {
            float4 v = *(const float4*)&xr[j];
            s += v.x + v.y + v.z + v.w;
            s2 += v.x * v.x + v.y * v.y + v.z * v.z + v.w * v.w;
            int c = h * 32 + j;
            ar[kpm(c)]     = cvt_tf32(v.x);
            ar[kpm(c + 1)] = cvt_tf32(v.y);
            ar[kpm(c + 2)] = cvt_tf32(v.z);
            ar[kpm(c + 3)] = cvt_tf32(v.w);
        }
        s  += __shfl_xor_sync(0xffffffffu, s, 1);
        s  += __shfl_xor_sync(0xffffffffu, s, 2);
        s2 += __shfl_xor_sync(0xffffffffu, s2, 1);
        s2 += __shfl_xor_sync(0xffffffffu, s2, 2);
        float mu = s * (1.f / 128.f);
        if (h == 0) {
            smu[r] = mu;
            srs[r] = rsqrtf(s2 * (1.f / 128.f) - mu * mu + 1e-5f);
        }
    }
    cp_wait<1>();     // enc ready
    __syncthreads();

    const int w = tid >> 5, lane = tid & 31, q = lane >> 2, t = lane & 3;
    const int mbase = (w & 7) * 16, wn = w >> 3;

    {   // enc GEMM: z = x @ enc_w  (each warp: 16 rows x 32 cols)
        float acc[4][4];
        zero_acc(&acc[0][0], 16);
        gemm_i<136, 136, 4>(acc, As, B0, mbase, wn * 32, 128, q, t);
        float sl = 0.f, sh = 0.f;
#pragma unroll
        for (int nt = 0; nt < 4; nt++) {
            int cc = wn * 32 + nt * 8 + 2 * t;
            int rlo = mbase + q, rhi = rlo + 8;
            float z0 = acc[nt][0] + encb[g * 64 + cc];
            float z1 = acc[nt][1] + encb[g * 64 + cc + 1];
            float z2 = acc[nt][2] + encb[g * 64 + cc];
            float z3 = acc[nt][3] + encb[g * 64 + cc + 1];
            size_t qlo = (size_t)(p0 + rlo) * 64 + g;
            size_t qhi = (size_t)(p0 + rhi) * 64 + g;
            *(float2*)&out[OFF_Z + qlo * 64 + cc] = make_float2(z0, z1);
            *(float2*)&out[OFF_Z + qhi * 64 + cc] = make_float2(z2, z3);
            float2 plo = *(const float2*)&zhp[qlo * 64 + cc];
            float2 phi = *(const float2*)&zhp[qhi * 64 + cc];
            float d0 = z0 - plo.x, d1 = z1 - plo.y;
            float d2 = z2 - phi.x, d3 = z3 - phi.y;
            int p0c = kpm(cc), p1c = kpm(cc + 1);
            Zs[rlo * 72 + p0c] = cvt_tf32(z0);
            Zs[rlo * 72 + p1c] = cvt_tf32(z1);
            Zs[rhi * 72 + p0c] = cvt_tf32(z2);
            Zs[rhi * 72 + p1c] = cvt_tf32(z3);
            Ds[rlo * 72 + p0c] = cvt_tf32(d0);
            Ds[rlo * 72 + p1c] = cvt_tf32(d1);
            Ds[rhi * 72 + p0c] = cvt_tf32(d2);
            Ds[rhi * 72 + p1c] = cvt_tf32(d3);
            sl += d0 * d0 + d1 * d1;
            sh += d2 * d2 + d3 * d3;
        }
        sl += __shfl_xor_sync(0xffffffffu, sl, 1);
        sl += __shfl_xor_sync(0xffffffffu, sl, 2);
        sh += __shfl_xor_sync(0xffffffffu, sh, 1);
        sh += __shfl_xor_sync(0xffffffffu, sh, 2);
        if (t == 0) {   // per-half partials
            pr[wn * 128 + mbase + q] = sl;
            pr[wn * 128 + mbase + q + 8] = sh;
        }
    }
    __syncthreads();                                   // Zs/Ds/pr visible; B0 free
    if (tid < 128) {   // surprise + gate (combine halves)
        float sp = sqrtf(pr[tid] + pr[128 + tid]);
        size_t qq = (size_t)(p0 + tid) * 64 + g;
        out[OFF_S + qq] = sp;
        out[OFF_G + qq] = fminf(sp, 1.0f);
    }
    cpy136(B0, gw_up + (size_t)g * 65536, 64, tid);    cp_commit();   // up0
    cp_wait<1>();                                      // pred ready
    __syncthreads();
    {   // pred GEMM (16 x 32 per warp)
        float acc[4][4];
        zero_acc(&acc[0][0], 16);
        gemm_i<72, 72, 4>(acc, Zs, B1, mbase, wn * 32, 64, q, t);
#pragma unroll
        for (int nt = 0; nt < 4; nt++) {
            int cc = wn * 32 + nt * 8 + 2 * t;
            size_t qlo = (size_t)(p0 + mbase + q) * 64 + g;
            size_t qhi = (size_t)(p0 + mbase + q + 8) * 64 + g;
            float b0 = predb[g * 64 + cc], b1 = predb[g * 64 + cc + 1];
            *(float2*)&out[OFF_ZH + qlo * 64 + cc] =
                make_float2(acc[nt][0] + b0, acc[nt][1] + b1);
            *(float2*)&out[OFF_ZH + qhi * 64 + cc] =
                make_float2(acc[nt][2] + b0, acc[nt][3] + b1);
        }
    }
    __syncthreads();                                   // B1 free
    cpy72(B1, gw_gain + (size_t)g * 8192, 128, tid);   cp_commit();   // gain
    cp_wait<0>();                                      // up0 + gain ready
    __syncthreads();
    {   // gain GEMM (16 x 64 per warp, K=64) + GLN epilogue -> As := tf32(hh)
        float acc[8][4];
        zero_acc(&acc[0][0], 32);
        gemm_i<72, 72, 8>(acc, Ds, B1, mbase, wn * 64, 64, q, t);
        int rlo = mbase + q, rhi = rlo + 8;
        float mlo = smu[rlo], rslo = srs[rlo];
        float mhi = smu[rhi], rshi = srs[rhi];
#pragma unroll
        for (int nt = 0; nt < 8; nt++) {
            int cc = wn * 64 + nt * 8 + 2 * t;
#pragma unroll
            for (int jj = 0; jj < 2; jj++) {
                int c = cc + jj, cp = kpm(c);
                float lg = lng[(size_t)g * 128 + c], lb = lnb[(size_t)g * 128 + c];
                float gb = gainb[(size_t)g * 128 + c];
                float gn0 = 1.0f + 0.1f * tanhf(acc[nt][jj] + gb);
                float gn1 = 1.0f + 0.1f * tanhf(acc[nt][2 + jj] + gb);
                float x0 = __uint_as_float(As[rlo * 136 + cp]);
                float x1 = __uint_as_float(As[rhi * 136 + cp]);
                As[rlo * 136 + cp] = cvt_tf32(((x0 - mlo) * rslo * lg + lb) * gn0);
                As[rhi * 136 + cp] = cvt_tf32(((x1 - mhi) * rshi * lg + lb) * gn1);
            }
        }
    }
    __syncthreads();                                   // As(hh); B1/Ds free
    cpy72(B1, gw_down + (size_t)g * 65536, 128, tid);  cp_commit();   // down0

    uint32_t* Us = Zs;
    float oacc[8][4];
    zero_acc(&oacc[0][0], 32);
    for (int ch = 0; ch < 8; ch++) {
        float uacc[4][4];
        zero_acc(&uacc[0][0], 16);
        gemm_i<136, 136, 4>(uacc, As, B0, mbase, wn * 32, 128, q, t);
#pragma unroll
        for (int nt = 0; nt < 4; nt++) {
            int cc = wn * 32 + nt * 8 + 2 * t;
            int rlo = mbase + q, rhi = rlo + 8;
#pragma unroll
            for (int jj = 0; jj < 2; jj++) {
                float bb = upb[(size_t)g * 512 + ch * 64 + cc + jj];
                float u0 = uacc[nt][jj] + bb;
                float u1 = uacc[nt][2 + jj] + bb;
                u0 = 0.5f * u0 * (1.0f + erff(u0 * 0.70710678118654752f));
                u1 = 0.5f * u1 * (1.0f + erff(u1 * 0.70710678118654752f));
                int cp = kpm(cc + jj);
                Us[rlo * 72 + cp] = cvt_tf32(u0);
                Us[rhi * 72 + cp] = cvt_tf32(u1);
            }
        }
        __syncthreads();                 // Us visible; B0 reads done
        if (ch < 7) {
            cpy136(B0, gw_up + (size_t)g * 65536 + (ch + 1) * 8192, 64, tid);
            cp_commit();
            cp_wait<1>();                // down_ch ready
        } else {
            cp_wait<0>();
        }
        __syncthreads();
        gemm_i<72, 72, 8>(oacc, Us, B1, mbase, wn * 64, 64, q, t);
        if (ch < 7) {
            __syncthreads();             // B1 reads done
            cpy72(B1, gw_down + (size_t)g * 65536 + (ch + 1) * 8192, 128, tid);
            cp_commit();
            cp_wait<1>();                // up_{ch+1} ready
            __syncthreads();
        }
    }
    __syncthreads();                     // last down gemm reads done
    {   // MLP epilogue -> gmem x_out AND As := tf32(x_out)
#pragma unroll
        for (int nt = 0; nt < 8; nt++) {
            int cc = wn * 64 + nt * 8 + 2 * t;
            int rlo = mbase + q, rhi = rlo + 8;
            float b0 = dwb[(size_t)g * 128 + cc], b1 = dwb[(size_t)g * 128 + cc + 1];
            size_t o0 = ((size_t)(p0 + rlo) * 64 + g) * 128 + cc;
            size_t o1 = ((size_t)(p0 + rhi) * 64 + g) * 128 + cc;
            float2 x0 = *(const float2*)&g_xa[o0];
            float2 x1 = *(const float2*)&g_xa[o1];
            float v00 = x0.x + oacc[nt][0] + b0, v01 = x0.y + oacc[nt][1] + b1;
            float v10 = x1.x + oacc[nt][2] + b0, v11 = x1.y + oacc[nt][3] + b1;
            *(float2*)&out[OFF_XOUT + o0] = make_float2(v00, v01);
            *(float2*)&out[OFF_XOUT + o1] = make_float2(v10, v11);
            int p0c = kpm(cc), p1c = kpm(cc + 1);
            As[rlo * 136 + p0c] = cvt_tf32(v00);
            As[rlo * 136 + p1c] = cvt_tf32(v01);
            As[rhi * 136 + p0c] = cvt_tf32(v10);
            As[rhi * 136 + p1c] = cvt_tf32(v11);
        }
    }
    __syncthreads();                     // As(x_out); Zs/Ds/B0/B1 dead
    cpy136(B0p, gw_post + (size_t)g * 65536, 128, tid);          cp_commit();
    cpy136(B1p, gw_post + (size_t)g * 65536 + 16384, 128, tid);  cp_commit();

    if (tid < 128) {   // w_nov (permuted plast matches As interleave)
        const float* wl = gw_plast + g * 128;
        float s = 0.f;
        for (int k = 0; k < 128; k++)
            s += __uint_as_float(As[tid * 136 + k]) * wl[k];
        s += pb[(size_t)g * 513 + 512];
        out[OFF_WN + (size_t)(p0 + tid) * 64 + g] = 1.0f / (1.0f + expf(-s));
    }

    for (int ch = 0; ch < 4; ch++) {
        if (ch < 3) cp_wait<1>(); else cp_wait<0>();
        __syncthreads();
        uint32_t* Bs = (ch & 1) ? B1p : B0p;
        float acc[8][4];
        zero_acc(&acc[0][0], 32);
        gemm_i<136, 136, 8>(acc, As, Bs, mbase, wn * 64, 128, q, t);
#pragma unroll
        for (int nt = 0; nt < 8; nt++) {
            int cc = wn * 64 + nt * 8 + 2 * t;
            float b0 = pb[(size_t)g * 513 + ch * 128 + cc];
            float b1 = pb[(size_t)g * 513 + ch * 128 + cc + 1];
            acc[nt][0] += b0; acc[nt][1] += b1;
            acc[nt][2] += b0; acc[nt][3] += b1;
        }
        if (ch == 1 || ch == 3) {
            size_t off = (ch == 1) ? OFF_VP : OFF_VC;
#pragma unroll
            for (int nt = 0; nt < 8; nt++) {
                int rr = mbase + q, cc = wn * 64 + nt * 8 + 2 * t;
                size_t o0 = off + ((size_t)(p0 + rr) * 64 + g) * 128 + cc;
                size_t o1 = off + ((size_t)(p0 + rr + 8) * 64 + g) * 128 + cc;
                *(float2*)&out[o0] = make_float2(acc[nt][0], acc[nt][1]);
                *(float2*)&out[o1] = make_float2(acc[nt][2], acc[nt][3]);
            }
        } else {
            float sl = 0.f, sh = 0.f;
#pragma unroll
            for (int nt = 0; nt < 8; nt++) {
                sl += acc[nt][0] * acc[nt][0] + acc[nt][1] * acc[nt][1];
                sh += acc[nt][2] * acc[nt][2] + acc[nt][3] * acc[nt][3];
            }
            sl += __shfl_xor_sync(0xffffffffu, sl, 1);
            sl += __shfl_xor_sync(0xffffffffu, sl, 2);
            sh += __shfl_xor_sync(0xffffffffu, sh, 1);
            sh += __shfl_xor_sync(0xffffffffu, sh, 2);
            if (t == 0) {
                pr[wn * 128 + mbase + q] = sl;
                pr[wn * 128 + mbase + q + 8] = sh;
            }
            __syncthreads();
            size_t off = (ch == 0) ? OFF_KC : OFF_QN;
#pragma unroll
            for (int nt = 0; nt < 8; nt++) {
                int rr = mbase + q, cc = wn * 64 + nt * 8 + 2 * t;
                float i0 = 1.0f / fmaxf(sqrtf(pr[rr] + pr[128 + rr]), 1e-6f);
                float i1 = 1.0f / fmaxf(sqrtf(pr[rr + 8] + pr[128 + rr + 8]), 1e-6f);
                size_t o0 = off + ((size_t)(p0 + rr) * 64 + g) * 128 + cc;
                size_t o1 = off + ((size_t)(p0 + rr + 8) * 64 + g) * 128 + cc;
                *(float2*)&out[o0] = make_float2(acc[nt][0] * i0, acc[nt][1] * i0);
                *(float2*)&out[o1] = make_float2(acc[nt][2] * i1, acc[nt][3] * i1);
            }
        }
        if (ch < 2) {
            __syncthreads();
            cpy136((ch & 1) ? B1p : B0p,
                   gw_post + (size_t)g * 65536 + (ch + 2) * 16384, 128, tid);
            cp_commit();
        }
    }
}

// ===========================================================================
extern "C" void kernel_launch(void* const* d_in, const int* in_sizes, int n_in,
                              void* d_out, int out_size) {
    const float* x_col  = (const float*)d_in[0];
    const float* zhp    = (const float*)d_in[1];
    const float* ln_g   = (const float*)d_in[2];
    const float* ln_b   = (const float*)d_in[3];
    const float* up_w   = (const float*)d_in[4];
    const float* up_b   = (const float*)d_in[5];
    const float* down_w = (const float*)d_in[6];
    const float* down_b = (const float*)d_in[7];
    const float* lat_g  = (const float*)d_in[8];
    const float* lat_b  = (const float*)d_in[9];
    const float* wq     = (const float*)d_in[10];
    const float* bq     = (const float*)d_in[11];
    const float* wk     = (const float*)d_in[12];
    const float* bk     = (const float*)d_in[13];
    const float* wv     = (const float*)d_in[14];
    const float* bv     = (const float*)d_in[15];
    const float* wo     = (const float*)d_in[16];
    const float* bo     = (const float*)d_in[17];
    const float* post_w = (const float*)d_in[18];
    const float* post_b = (const float*)d_in[19];
    const float* enc_w  = (const float*)d_in[20];
    const float* enc_b  = (const float*)d_in[21];
    const float* pred_w = (const float*)d_in[22];
    const float* pred_b = (const float*)d_in[23];
    const float* gain_w = (const float*)d_in[24];
    const float* gain_b = (const float*)d_in[25];
    float* out = (float*)d_out;

    const int SM_FA   = 52736 * 4;   // 210944
    const int SM_MEGA = 54272 * 4;   // 217088

    cudaFuncSetAttribute(k_fattn, cudaFuncAttributeMaxDynamicSharedMemorySize, SM_FA);
    cudaFuncSetAttribute(k_mega,  cudaFuncAttributeMaxDynamicSharedMemorySize, SM_MEGA);

    uint32_t* d_enc;  cudaGetSymbolAddress((void**)&d_enc,  gw_enc);
    uint32_t* d_pred; cudaGetSymbolAddress((void**)&d_pred, gw_pred);
    uint32_t* d_gain; cudaGetSymbolAddress((void**)&d_gain, gw_gain);
    uint32_t* d_up;   cudaGetSymbolAddress((void**)&d_up,   gw_up);
    uint32_t* d_down; cudaGetSymbolAddress((void**)&d_down, gw_down);
    uint32_t* d_post; cudaGetSymbolAddress((void**)&d_post, gw_post);

    k_tcvt_qkvo<<<dim3(4, 4, 4), 256>>>(wq, wk, wv, wo);
    k_tcvt<<<dim3(4, 2, 64), 256>>>(enc_w, d_enc, 8192, 64, 8192,
                                    6, 0, 7, 0, 63, 128, 127);
    k_tcvt<<<dim3(2, 2, 64), 256>>>(pred_w, d_pred, 4096, 64, 4096,
                                    6, 0, 6, 0, 63, 64, 63);
    k_tcvt<<<dim3(2, 4, 64), 256>>>(gain_w, d_gain, 8192, 128, 8192,
                                    7, 0, 6, 0, 127, 64, 63);
    k_tcvt<<<dim3(4, 16, 64), 256>>>(up_w, d_up, 65536, 512, 65536,
                                     6, 8192, 7, 0, 63, 128, 127);
    k_tcvt<<<dim3(16, 4, 64), 256>>>(down_w, d_down, 65536, 128, 65536,
                                     7, 0, 6, 8192, 127, 64, 63);
    k_tcvt<<<dim3(4, 16, 64), 256>>>(post_w, d_post, 65664, 513, 65536,
                                     7, 16384, 7, 0, 127, 128, 127);
    k_plast<<<32, 256>>>(post_w);

    k_fattn<<<R_TOT / 64, 512, SM_FA>>>(x_col, lat_g, lat_b, bq, bk, bv, bo);
    k_mega<<<dim3(TOKS / 128, 64), 512, SM_MEGA>>>(zhp, ln_g, ln_b,
                                                   enc_b, pred_b, gain_b,
                                                   up_b, down_b, post_b, out);
}

// round 10
// speedup vs baseline: 1.3947x; 1.3750x over previous
#include <cuda_runtime.h>
#include <cuda_fp16.h>
#include <math.h>
#include <stdint.h>

#define R_TOT 131072   // BS*N*G rows
#define TOKS  2048     // BS*N tokens

static constexpr size_t OFF_XOUT = 0;
static constexpr size_t OFF_Z    = 16777216;
static constexpr size_t OFF_ZH   = 25165824;
static constexpr size_t OFF_S    = 33554432;
static constexpr size_t OFF_KC   = 33685504;
static constexpr size_t OFF_VP   = 50462720;
static constexpr size_t OFF_G    = 67239936;
static constexpr size_t OFF_QN   = 67371008;
static constexpr size_t OFF_VC   = 84148224;
static constexpr size_t OFF_WN   = 100925440;

// Scratch
__device__ float g_xa[16777216];

// fp16 weights (half2-packed uint32), n-major [n][k]
__device__ uint32_t gw_qkvo[32768];       // [sel][n128][k128/2]
__device__ uint32_t gw_enc [262144];      // [g][n64][k128/2]
__device__ uint32_t gw_pred[131072];      // [g][n64][k64/2]
__device__ uint32_t gw_gain[262144];      // [g][n128][k64/2]
__device__ uint32_t gw_up  [2097152];     // [g][ch8][n64][k128/2]  (4096/chunk)
__device__ uint32_t gw_down[2097152];     // [g][ch8][n128][k64/2]  (4096/chunk)
__device__ uint32_t gw_post[2097152];     // [g][ch4][n128][k128/2] (8192/chunk)
__device__ float    gw_plast[8192];       // [g][k128]

// ===========================================================================
__device__ __forceinline__ uint32_t pack2(float lo, float hi) {
    uint32_t r;
    asm("cvt.rn.f16x2.f32 %0, %1, %2;" : "=r"(r) : "f"(hi), "f"(lo));
    return r;
}
__device__ __forceinline__ float2 unp2(uint32_t v) {
    __half2 h = *reinterpret_cast<__half2*>(&v);
    return __half22float2(h);
}
__device__ __forceinline__ void mma_h(float* c, uint32_t a0, uint32_t a1,
                                      uint32_t a2, uint32_t a3,
                                      uint32_t b0, uint32_t b1) {
    asm volatile(
        "mma.sync.aligned.m16n8k16.row.col.f32.f16.f16.f32 "
        "{%0,%1,%2,%3}, {%4,%5,%6,%7}, {%8,%9}, {%0,%1,%2,%3};"
        : "+f"(c[0]), "+f"(c[1]), "+f"(c[2]), "+f"(c[3])
        : "r"(a0), "r"(a1), "r"(a2), "r"(a3), "r"(b0), "r"(b1));
}
__device__ __forceinline__ void cp16(void* smem, const void* gmem) {
    uint32_t s = (uint32_t)__cvta_generic_to_shared(smem);
    asm volatile("cp.async.cg.shared.global [%0], [%1], 16;" :: "r"(s), "l"(gmem));
}
__device__ __forceinline__ void cp_commit() {
    asm volatile("cp.async.commit_group;" ::: "memory");
}
template<int N> __device__ __forceinline__ void cp_wait() {
    asm volatile("cp.async.wait_group %0;" :: "n"(N) : "memory");
}
// rows of 64 uint (k128 halfs) -> smem stride 68 words  (512-thread blocks)
__device__ __forceinline__ void cpy68(uint32_t* dst, const uint32_t* src,
                                      int rows, int tid) {
    for (int i = tid; i < rows * 16; i += 512) {
        int r = i >> 4, c = (i & 15) * 4;
        cp16(dst + r * 68 + c, src + r * 64 + c);
    }
}
// rows of 32 uint (k64 halfs) -> smem stride 36 words
__device__ __forceinline__ void cpy36(uint32_t* dst, const uint32_t* src,
                                      int rows, int tid) {
    for (int i = tid; i < rows * 8; i += 512) {
        int r = i >> 3, c = (i & 7) * 4;
        cp16(dst + r * 36 + c, src + r * 32 + c);
    }
}
// fp16 GEMM: warp computes 16 x NT*8 tile. As/Bs word strides LDA/LDB.
// Kw = K in words (K halfs / 2).
template<int LDA, int LDB, int NT>
__device__ __forceinline__ void gemm_h(float acc[NT][4],
        const uint32_t* __restrict__ As, const uint32_t* __restrict__ Bs,
        int mbase, int nbase, int Kw, int q, int t) {
#pragma unroll 2
    for (int kw = 0; kw < Kw; kw += 8) {
        const uint32_t* ap0 = As + (mbase + q) * LDA + kw + t;
        const uint32_t* ap1 = As + (mbase + q + 8) * LDA + kw + t;
        uint32_t a0 = ap0[0], a2 = ap0[4];
        uint32_t a1 = ap1[0], a3 = ap1[4];
#pragma unroll
        for (int nt = 0; nt < NT; nt++) {
            const uint32_t* bp = Bs + (nbase + nt * 8 + q) * LDB + kw + t;
            mma_h(acc[nt], a0, a1, a2, a3, bp[0], bp[4]);
        }
    }
}
__device__ __forceinline__ void zero_acc(float* a, int n) {
#pragma unroll
    for (int i = 0; i < n; i++) a[i] = 0.f;
}

// ===========================================================================
// Weight prep: src [K][N] fp32 -> dst n-major half2-packed
// ===========================================================================
__global__ void k_tcvt2(const float* __restrict__ src, uint32_t* __restrict__ dst,
                        long sgs, int sld, long gs,
                        int ns, int nchs, int ks, int kchs,
                        int cm, int ldn, int km) {
    __shared__ float tile[32][33];
    int g = blockIdx.z;
    int k0 = blockIdx.x * 32, n0 = blockIdx.y * 32;
    int tr = threadIdx.x >> 5, tc = threadIdx.x & 31;
    const float* s = src + (size_t)g * sgs;
#pragma unroll
    for (int i = 0; i < 4; i++)
        tile[tr + i * 8][tc] = s[(size_t)(k0 + tr + i * 8) * sld + n0 + tc];
    __syncthreads();
    uint32_t* d = dst + (size_t)g * gs;
    int np = threadIdx.x >> 4, kp = threadIdx.x & 15;
#pragma unroll
    for (int ii = 0; ii < 2; ii++) {
        int n = n0 + np + ii * 16, k = k0 + 2 * kp;
        uint32_t v = pack2(tile[2 * kp][np + ii * 16], tile[2 * kp + 1][np + ii * 16]);
        d[(size_t)(n >> ns) * nchs + (size_t)(k >> ks) * kchs
          + (n & cm) * ldn + ((k & km) >> 1)] = v;
    }
}
__global__ void k_tcvt_qkvo2(const float* __restrict__ wq, const float* __restrict__ wk,
                             const float* __restrict__ wv, const float* __restrict__ wo) {
    __shared__ float tile[32][33];
    int sel = blockIdx.z;
    const float* s = (sel == 0) ? wq : (sel == 1) ? wk : (sel == 2) ? wv : wo;
    int k0 = blockIdx.x * 32, n0 = blockIdx.y * 32;
    int tr = threadIdx.x >> 5, tc = threadIdx.x & 31;
#pragma unroll
    for (int i = 0; i < 4; i++)
        tile[tr + i * 8][tc] = s[(size_t)(k0 + tr + i * 8) * 128 + n0 + tc];
    __syncthreads();
    uint32_t* d = gw_qkvo + sel * 8192;
    int np = threadIdx.x >> 4, kp = threadIdx.x & 15;
#pragma unroll
    for (int ii = 0; ii < 2; ii++) {
        int n = n0 + np + ii * 16, k = k0 + 2 * kp;
        d[n * 64 + (k >> 1)] =
            pack2(tile[2 * kp][np + ii * 16], tile[2 * kp + 1][np + ii * 16]);
    }
}
__global__ void k_plast(const float* __restrict__ pw) {
    int i = blockIdx.x * 256 + threadIdx.x;
    if (i < 8192)
        gw_plast[i] = pw[(size_t)i * 513 + 512];
}

// ===========================================================================
// K1: fused LN + QKV + attention + wo.  grid 2048 (64 rows), 512 thr.
// words: As 4352 | W0 8704 | W1 8704 | Kf 8704 | Vf 8704 | Qb 8448 | misc 768
// ===========================================================================
__global__ __launch_bounds__(512, 1)
void k_fattn(const float* __restrict__ x,
             const float* __restrict__ latg, const float* __restrict__ latb,
             const float* __restrict__ bq, const float* __restrict__ bk,
             const float* __restrict__ bv, const float* __restrict__ bo) {
    extern __shared__ uint32_t sm[];
    uint32_t* As = sm;                   // 64 x 68 (half)
    uint32_t* W0 = As + 4352;            // 128 x 68 (half)
    uint32_t* W1 = W0 + 8704;            // 128 x 68 (half)
    float* Kf = (float*)(W1 + 8704);     // 64 x 136 fp32
    float* Vf = Kf + 8704;               // 64 x 136 fp32
    float* Qb = Vf + 8704;               // 64 x 132 fp32
    float* sc = Qb + 8448;               // 512
    float* sg = sc + 512;                // 128
    float* sb = sg + 128;                // 128
    const int tid = threadIdx.x;
    const size_t rowbase = (size_t)blockIdx.x * 64;

    cpy68(W0, gw_qkvo, 128, tid);         cp_commit();  // wq
    cpy68(W1, gw_qkvo + 8192, 128, tid);  cp_commit();  // wk

    if (tid < 128) { sg[tid] = latg[tid]; sb[tid] = latb[tid]; }
    const int r = tid >> 3, qt = tid & 7;   // 64 rows x 8 thr, 16 cols each
    {
        const float* xr = x + (rowbase + r) * 128 + qt * 16;
        float xv[16];
        float s = 0.f, s2 = 0.f;
#pragma unroll
        for (int j = 0; j < 16; j += 4) {
            float4 v = *(const float4*)&xr[j];
            xv[j] = v.x; xv[j + 1] = v.y; xv[j + 2] = v.z; xv[j + 3] = v.w;
            s += v.x + v.y + v.z + v.w;
            s2 += v.x * v.x + v.y * v.y + v.z * v.z + v.w * v.w;
        }
        s  += __shfl_xor_sync(0xffffffffu, s, 1);
        s  += __shfl_xor_sync(0xffffffffu, s, 2);
        s  += __shfl_xor_sync(0xffffffffu, s, 4);
        s2 += __shfl_xor_sync(0xffffffffu, s2, 1);
        s2 += __shfl_xor_sync(0xffffffffu, s2, 2);
        s2 += __shfl_xor_sync(0xffffffffu, s2, 4);
        float mu = s * (1.f / 128.f);
        float rs = rsqrtf(s2 * (1.f / 128.f) - mu * mu + 1e-5f);
        __syncthreads();   // sg/sb visible
        uint32_t* ar = As + r * 68 + qt * 8;
#pragma unroll
        for (int j = 0; j < 16; j += 2) {
            int c = qt * 16 + j;
            float h0 = (xv[j] - mu) * rs * sg[c] + sb[c];
            float h1 = (xv[j + 1] - mu) * rs * sg[c + 1] + sb[c + 1];
            ar[j >> 1] = pack2(h0, h1);
        }
    }
    __syncthreads();       // As final
    cp_wait<1>();          // wq arrived
    __syncthreads();

    const int w = tid >> 5, lane = tid & 31, q = lane >> 2, t = lane & 3;
    const int mbase = (w & 3) * 16, nbase = (w >> 2) * 32;

    {   // Q gemm -> Qb fp32
        float acc[4][4];
        zero_acc(&acc[0][0], 16);
        gemm_h<68, 68, 4>(acc, As, W0, mbase, nbase, 64, q, t);
#pragma unroll
        for (int nt = 0; nt < 4; nt++) {
            int rr = mbase + q, cc = nbase + nt * 8 + 2 * t;
            float b0 = bq[cc], b1 = bq[cc + 1];
            Qb[rr * 132 + cc]           = acc[nt][0] + b0;
            Qb[rr * 132 + cc + 1]       = acc[nt][1] + b1;
            Qb[(rr + 8) * 132 + cc]     = acc[nt][2] + b0;
            Qb[(rr + 8) * 132 + cc + 1] = acc[nt][3] + b1;
        }
    }
    __syncthreads();                          // W0 reads done
    cpy68(W0, gw_qkvo + 16384, 128, tid);     // wv
    cp_commit();
    cp_wait<1>();                             // wk arrived
    __syncthreads();
    {   // K gemm (W1) -> Kf fp32
        float acc[4][4];
        zero_acc(&acc[0][0], 16);
        gemm_h<68, 68, 4>(acc, As, W1, mbase, nbase, 64, q, t);
#pragma unroll
        for (int nt = 0; nt < 4; nt++) {
            int rr = mbase + q, cc = nbase + nt * 8 + 2 * t;
            float b0 = bk[cc], b1 = bk[cc + 1];
            Kf[rr * 136 + cc]           = acc[nt][0] + b0;
            Kf[rr * 136 + cc + 1]       = acc[nt][1] + b1;
            Kf[(rr + 8) * 136 + cc]     = acc[nt][2] + b0;
            Kf[(rr + 8) * 136 + cc + 1] = acc[nt][3] + b1;
        }
    }
    __syncthreads();                          // W1 reads done; Kf final
    cpy68(W1, gw_qkvo + 24576, 128, tid);     // wo
    cp_commit();
    {   // scores: one (grp,c,e) per thread
        int rowq = tid >> 3;
        int grp = tid >> 6, e = tid & 7;
        const float* qp = Qb + rowq * 132;
        const float* kp = Kf + (grp * 8 + e) * 136;
        float s = 0.f;
#pragma unroll 8
        for (int d = 0; d < 128; d += 4) {
            float4 a = *(const float4*)&qp[d];
            float4 b = *(const float4*)&kp[d];
            s += a.x * b.x + a.y * b.y + a.z * b.z + a.w * b.w;
        }
        sc[tid] = s * 0.088388347648318447f;
    }
    __syncthreads();
    if (tid < 64) {    // softmax over e
        float* row = sc + tid * 8;
        float m = row[0];
#pragma unroll
        for (int e = 1; e < 8; e++) m = fmaxf(m, row[e]);
        float ex[8], ssum = 0.f;
#pragma unroll
        for (int e = 0; e < 8; e++) { ex[e] = expf(row[e] - m); ssum += ex[e]; }
        float inv = 1.0f / ssum;
#pragma unroll
        for (int e = 0; e < 8; e++) row[e] = ex[e] * inv;
    }
    cp_wait<1>();                             // wv arrived
    __syncthreads();
    {   // V gemm (W0) -> Vf fp32
        float acc[4][4];
        zero_acc(&acc[0][0], 16);
        gemm_h<68, 68, 4>(acc, As, W0, mbase, nbase, 64, q, t);
#pragma unroll
        for (int nt = 0; nt < 4; nt++) {
            int rr = mbase + q, cc = nbase + nt * 8 + 2 * t;
            float b0 = bv[cc], b1 = bv[cc + 1];
            Vf[rr * 136 + cc]           = acc[nt][0] + b0;
            Vf[rr * 136 + cc + 1]       = acc[nt][1] + b1;
            Vf[(rr + 8) * 136 + cc]     = acc[nt][2] + b0;
            Vf[(rr + 8) * 136 + cc + 1] = acc[nt][3] + b1;
        }
    }
    __syncthreads();                          // Vf final
    {   // o = attn @ V -> As (fp16), in place
        int rr = tid >> 3, d0 = (tid & 7) * 16;
        const float* vb = Vf + (rr & ~7) * 136;
        float a[8];
#pragma unroll
        for (int e = 0; e < 8; e++) a[e] = sc[rr * 8 + e];
        uint32_t* ar = As + rr * 68 + (d0 >> 1);
#pragma unroll
        for (int j = 0; j < 16; j += 4) {
            float4 o = make_float4(0.f, 0.f, 0.f, 0.f);
#pragma unroll
            for (int e = 0; e < 8; e++) {
                float4 v = *(const float4*)&vb[e * 136 + d0 + j];
                o.x += a[e] * v.x; o.y += a[e] * v.y;
                o.z += a[e] * v.z; o.w += a[e] * v.w;
            }
            ar[(j >> 1)]     = pack2(o.x, o.y);
            ar[(j >> 1) + 1] = pack2(o.z, o.w);
        }
    }
    cp_wait<0>();                             // wo arrived
    __syncthreads();                          // As(o) final
    {   // wo gemm (W1) + residual -> g_xa
        float acc[4][4];
        zero_acc(&acc[0][0], 16);
        gemm_h<68, 68, 4>(acc, As, W1, mbase, nbase, 64, q, t);
#pragma unroll
        for (int nt = 0; nt < 4; nt++) {
            int rr = mbase + q, cc = nbase + nt * 8 + 2 * t;
            float b0 = bo[cc], b1 = bo[cc + 1];
            size_t o0 = (rowbase + rr) * 128 + cc;
            size_t o1 = (rowbase + rr + 8) * 128 + cc;
            float2 x0 = *(const float2*)&x[o0];
            float2 x1 = *(const float2*)&x[o1];
            *(float2*)&g_xa[o0] = make_float2(x0.x + acc[nt][0] + b0,
                                              x0.y + acc[nt][1] + b1);
            *(float2*)&g_xa[o1] = make_float2(x1.x + acc[nt][2] + b0,
                                              x1.y + acc[nt][3] + b1);
        }
    }
}

// ===========================================================================
// K2: mega per-group kernel: small + MLP + post.  grid (16, 64), 512 thr.
// words: As 8704 | Zs 4608 | Ds 4608 | B0 8704 | B1 8704 | misc 512
// ===========================================================================
__global__ __launch_bounds__(512, 1)
void k_mega(const float* __restrict__ zhp,
            const float* __restrict__ lng, const float* __restrict__ lnb,
            const float* __restrict__ encb, const float* __restrict__ predb,
            const float* __restrict__ gainb, const float* __restrict__ upb,
            const float* __restrict__ dwb, const float* __restrict__ pb,
            float* out) {
    extern __shared__ uint32_t sm[];
    uint32_t* As = sm;                  // 128 x 68 (half)
    uint32_t* Zs = As + 8704;           // 128 x 36 (half)
    uint32_t* Ds = Zs + 4608;           // 128 x 36 (half)
    uint32_t* B0 = Ds + 4608;           // 8704
    uint32_t* B1 = B0 + 8704;           // 8704
    float* smu = (float*)(B1 + 8704);   // 128
    float* srs = smu + 128;             // 128
    float* pr  = srs + 128;             // 256
    const int tid = threadIdx.x;
    const int g = blockIdx.y, p0 = blockIdx.x * 128;

    cpy68(B0, gw_enc + (size_t)g * 4096, 64, tid);   cp_commit();
    cpy36(B1, gw_pred + (size_t)g * 2048, 64, tid);  cp_commit();

    {   // As = fp16(x_attn), stats: 128 rows x 4 thr, 32 cols each
        const int r = tid >> 2, h = tid & 3;
        const float* xr = g_xa + ((size_t)(p0 + r) * 64 + g) * 128 + h * 32;
        float xv[32];
        float s = 0.f, s2 = 0.f;
#pragma unroll
        for (int j = 0; j < 32; j += 4) {
            float4 v = *(const float4*)&xr[j];
            xv[j] = v.x; xv[j + 1] = v.y; xv[j + 2] = v.z; xv[j + 3] = v.w;
            s += v.x + v.y + v.z + v.w;
            s2 += v.x * v.x + v.y * v.y + v.z * v.z + v.w * v.w;
        }
        uint32_t* ar = As + r * 68 + h * 16;
#pragma unroll
        for (int j = 0; j < 32; j += 2)
            ar[j >> 1] = pack2(xv[j], xv[j + 1]);
        s  += __shfl_xor_sync(0xffffffffu, s, 1);
        s  += __shfl_xor_sync(0xffffffffu, s, 2);
        s2 += __shfl_xor_sync(0xffffffffu, s2, 1);
        s2 += __shfl_xor_sync(0xffffffffu, s2, 2);
        float mu = s * (1.f / 128.f);
        if (h == 0) {
            smu[r] = mu;
            srs[r] = rsqrtf(s2 * (1.f / 128.f) - mu * mu + 1e-5f);
        }
    }
    cp_wait<1>();     // enc ready
    __syncthreads();

    const int w = tid >> 5, lane = tid & 31, q = lane >> 2, t = lane & 3;
    const int mbase = (w & 7) * 16, wn = w >> 3;

    {   // enc GEMM: z = x @ enc_w  (16 x 32 per warp, Kw=64)
        float acc[4][4];
        zero_acc(&acc[0][0], 16);
        gemm_h<68, 68, 4>(acc, As, B0, mbase, wn * 32, 64, q, t);
        float sl = 0.f, sh = 0.f;
#pragma unroll
        for (int nt = 0; nt < 4; nt++) {
            int cc = wn * 32 + nt * 8 + 2 * t;
            int rlo = mbase + q, rhi = rlo + 8;
            float z0 = acc[nt][0] + encb[g * 64 + cc];
            float z1 = acc[nt][1] + encb[g * 64 + cc + 1];
            float z2 = acc[nt][2] + encb[g * 64 + cc];
            float z3 = acc[nt][3] + encb[g * 64 + cc + 1];
            size_t qlo = (size_t)(p0 + rlo) * 64 + g;
            size_t qhi = (size_t)(p0 + rhi) * 64 + g;
            *(float2*)&out[OFF_Z + qlo * 64 + cc] = make_float2(z0, z1);
            *(float2*)&out[OFF_Z + qhi * 64 + cc] = make_float2(z2, z3);
            float2 plo = *(const float2*)&zhp[qlo * 64 + cc];
            float2 phi = *(const float2*)&zhp[qhi * 64 + cc];
            float d0 = z0 - plo.x, d1 = z1 - plo.y;
            float d2 = z2 - phi.x, d3 = z3 - phi.y;
            int wi = cc >> 1;
            Zs[rlo * 36 + wi] = pack2(z0, z1);
            Zs[rhi * 36 + wi] = pack2(z2, z3);
            Ds[rlo * 36 + wi] = pack2(d0, d1);
            Ds[rhi * 36 + wi] = pack2(d2, d3);
            sl += d0 * d0 + d1 * d1;
            sh += d2 * d2 + d3 * d3;
        }
        sl += __shfl_xor_sync(0xffffffffu, sl, 1);
        sl += __shfl_xor_sync(0xffffffffu, sl, 2);
        sh += __shfl_xor_sync(0xffffffffu, sh, 1);
        sh += __shfl_xor_sync(0xffffffffu, sh, 2);
        if (t == 0) {
            pr[wn * 128 + mbase + q] = sl;
            pr[wn * 128 + mbase + q + 8] = sh;
        }
    }
    __syncthreads();                                    // Zs/Ds/pr visible; B0 free
    if (tid < 128) {   // surprise + gate
        float sp = sqrtf(pr[tid] + pr[128 + tid]);
        size_t qq = (size_t)(p0 + tid) * 64 + g;
        out[OFF_S + qq] = sp;
        out[OFF_G + qq] = fminf(sp, 1.0f);
    }
    cpy68(B0, gw_up + (size_t)g * 32768, 64, tid);      cp_commit();   // up0
    cp_wait<1>();                                       // pred ready
    __syncthreads();
    {   // pred GEMM (Zs @ pred, Kw=32)
        float acc[4][4];
        zero_acc(&acc[0][0], 16);
        gemm_h<36, 36, 4>(acc, Zs, B1, mbase, wn * 32, 32, q, t);
#pragma unroll
        for (int nt = 0; nt < 4; nt++) {
            int cc = wn * 32 + nt * 8 + 2 * t;
            size_t qlo = (size_t)(p0 + mbase + q) * 64 + g;
            size_t qhi = (size_t)(p0 + mbase + q + 8) * 64 + g;
            float b0 = predb[g * 64 + cc], b1 = predb[g * 64 + cc + 1];
            *(float2*)&out[OFF_ZH + qlo * 64 + cc] =
                make_float2(acc[nt][0] + b0, acc[nt][1] + b1);
            *(float2*)&out[OFF_ZH + qhi * 64 + cc] =
                make_float2(acc[nt][2] + b0, acc[nt][3] + b1);
        }
    }
    __syncthreads();                                    // B1 free
    cpy36(B1, gw_gain + (size_t)g * 4096, 128, tid);    cp_commit();   // gain
    cp_wait<0>();                                       // up0 + gain ready
    __syncthreads();
    {   // gain GEMM (Ds @ gain, 16x64, Kw=32) + GLN epilogue -> As := fp16(hh)
        float acc[8][4];
        zero_acc(&acc[0][0], 32);
        gemm_h<36, 36, 8>(acc, Ds, B1, mbase, wn * 64, 32, q, t);
        int rlo = mbase + q, rhi = rlo + 8;
        float mlo = smu[rlo], rslo = srs[rlo];
        float mhi = smu[rhi], rshi = srs[rhi];
#pragma unroll
        for (int nt = 0; nt < 8; nt++) {
            int cc = wn * 64 + nt * 8 + 2 * t, wi = cc >> 1;
            float lg0 = lng[(size_t)g * 128 + cc], lb0 = lnb[(size_t)g * 128 + cc];
            float lg1 = lng[(size_t)g * 128 + cc + 1], lb1 = lnb[(size_t)g * 128 + cc + 1];
            float gb0 = gainb[(size_t)g * 128 + cc], gb1 = gainb[(size_t)g * 128 + cc + 1];
            float2 xlo = unp2(As[rlo * 68 + wi]);
            float2 xhi = unp2(As[rhi * 68 + wi]);
            float h00 = ((xlo.x - mlo) * rslo * lg0 + lb0)
                        * (1.0f + 0.1f * tanhf(acc[nt][0] + gb0));
            float h01 = ((xlo.y - mlo) * rslo * lg1 + lb1)
                        * (1.0f + 0.1f * tanhf(acc[nt][1] + gb1));
            float h10 = ((xhi.x - mhi) * rshi * lg0 + lb0)
                        * (1.0f + 0.1f * tanhf(acc[nt][2] + gb0));
            float h11 = ((xhi.y - mhi) * rshi * lg1 + lb1)
                        * (1.0f + 0.1f * tanhf(acc[nt][3] + gb1));
            As[rlo * 68 + wi] = pack2(h00, h01);
            As[rhi * 68 + wi] = pack2(h10, h11);
        }
    }
    __syncthreads();                                    // As(hh); B1/Ds free
    cpy36(B1, gw_down + (size_t)g * 32768, 128, tid);   cp_commit();   // down0

    uint32_t* Us = Zs;
    float oacc[8][4];
    zero_acc(&oacc[0][0], 32);
    for (int ch = 0; ch < 8; ch++) {
        float uacc[4][4];
        zero_acc(&uacc[0][0], 16);
        gemm_h<68, 68, 4>(uacc, As, B0, mbase, wn * 32, 64, q, t);
#pragma unroll
        for (int nt = 0; nt < 4; nt++) {
            int cc = wn * 32 + nt * 8 + 2 * t, wi = cc >> 1;
            int rlo = mbase + q, rhi = rlo + 8;
            float b0 = upb[(size_t)g * 512 + ch * 64 + cc];
            float b1 = upb[(size_t)g * 512 + ch * 64 + cc + 1];
            float u00 = uacc[nt][0] + b0, u01 = uacc[nt][1] + b1;
            float u10 = uacc[nt][2] + b0, u11 = uacc[nt][3] + b1;
            u00 = 0.5f * u00 * (1.0f + erff(u00 * 0.70710678118654752f));
            u01 = 0.5f * u01 * (1.0f + erff(u01 * 0.70710678118654752f));
            u10 = 0.5f * u10 * (1.0f + erff(u10 * 0.70710678118654752f));
            u11 = 0.5f * u11 * (1.0f + erff(u11 * 0.70710678118654752f));
            Us[rlo * 36 + wi] = pack2(u00, u01);
            Us[rhi * 36 + wi] = pack2(u10, u11);
        }
        __syncthreads();                 // Us visible; B0 reads done
        if (ch < 7) {
            cpy68(B0, gw_up + (size_t)g * 32768 + (ch + 1) * 4096, 64, tid);
            cp_commit();
            cp_wait<1>();                // down_ch ready
        } else {
            cp_wait<0>();
        }
        __syncthreads();
        gemm_h<36, 36, 8>(oacc, Us, B1, mbase, wn * 64, 32, q, t);
        if (ch < 7) {
            __syncthreads();             // B1 reads done
            cpy36(B1, gw_down + (size_t)g * 32768 + (ch + 1) * 4096, 128, tid);
            cp_commit();
            cp_wait<1>();                // up_{ch+1} ready
            __syncthreads();
        }
    }
    __syncthreads();                     // last down gemm reads done
    {   // MLP epilogue -> gmem x_out AND As := fp16(x_out)
#pragma unroll
        for (int nt = 0; nt < 8; nt++) {
            int cc = wn * 64 + nt * 8 + 2 * t, wi = cc >> 1;
            int rlo = mbase + q, rhi = rlo + 8;
            float b0 = dwb[(size_t)g * 128 + cc], b1 = dwb[(size_t)g * 128 + cc + 1];
            size_t o0 = ((size_t)(p0 + rlo) * 64 + g) * 128 + cc;
            size_t o1 = ((size_t)(p0 + rhi) * 64 + g) * 128 + cc;
            float2 x0 = *(const float2*)&g_xa[o0];
            float2 x1 = *(const float2*)&g_xa[o1];
            float v00 = x0.x + oacc[nt][0] + b0, v01 = x0.y + oacc[nt][1] + b1;
            float v10 = x1.x + oacc[nt][2] + b0, v11 = x1.y + oacc[nt][3] + b1;
            *(float2*)&out[OFF_XOUT + o0] = make_float2(v00, v01);
            *(float2*)&out[OFF_XOUT + o1] = make_float2(v10, v11);
            As[rlo * 68 + wi] = pack2(v00, v01);
            As[rhi * 68 + wi] = pack2(v10, v11);
        }
    }
    __syncthreads();                     // As(x_out); B0/B1 free
    cpy68(B0, gw_post + (size_t)g * 32768, 128, tid);         cp_commit();
    cpy68(B1, gw_post + (size_t)g * 32768 + 8192, 128, tid);  cp_commit();

    if (tid < 128) {   // w_nov
        const float* wl = gw_plast + g * 128;
        float s = 0.f;
        for (int kw = 0; kw < 64; kw++) {
            float2 xv = unp2(As[tid * 68 + kw]);
            s += xv.x * wl[2 * kw] + xv.y * wl[2 * kw + 1];
        }
        s += pb[(size_t)g * 513 + 512];
        out[OFF_WN + (size_t)(p0 + tid) * 64 + g] = 1.0f / (1.0f + expf(-s));
    }

    for (int ch = 0; ch < 4; ch++) {
        if (ch < 3) cp_wait<1>(); else cp_wait<0>();
        __syncthreads();
        uint32_t* Bs = (ch & 1) ? B1 : B0;
        float acc[8][4];
        zero_acc(&acc[0][0], 32);
        gemm_h<68, 68, 8>(acc, As, Bs, mbase, wn * 64, 64, q, t);
#pragma unroll
        for (int nt = 0; nt < 8; nt++) {
            int cc = wn * 64 + nt * 8 + 2 * t;
            float b0 = pb[(size_t)g * 513 + ch * 128 + cc];
            float b1 = pb[(size_t)g * 513 + ch * 128 + cc + 1];
            acc[nt][0] += b0; acc[nt][1] += b1;
            acc[nt][2] += b0; acc[nt][3] += b1;
        }
        if (ch == 1 || ch == 3) {
            size_t off = (ch == 1) ? OFF_VP : OFF_VC;
#pragma unroll
            for (int nt = 0; nt < 8; nt++) {
                int rr = mbase + q, cc = wn * 64 + nt * 8 + 2 * t;
                size_t o0 = off + ((size_t)(p0 + rr) * 64 + g) * 128 + cc;
                size_t o1 = off + ((size_t)(p0 + rr + 8) * 64 + g) * 128 + cc;
                *(float2*)&out[o0] = make_float2(acc[nt][0], acc[nt][1]);
                *(float2*)&out[o1] = make_float2(acc[nt][2], acc[nt][3]);
            }
        } else {
            float sl = 0.f, sh = 0.f;
#pragma unroll
            for (int nt = 0; nt < 8; nt++) {
                sl += acc[nt][0] * acc[nt][0] + acc[nt][1] * acc[nt][1];
                sh += acc[nt][2] * acc[nt][2] + acc[nt][3] * acc[nt][3];
            }
            sl += __shfl_xor_sync(0xffffffffu, sl, 1);
            sl += __shfl_xor_sync(0xffffffffu, sl, 2);
            sh += __shfl_xor_sync(0xffffffffu, sh, 1);
            sh += __shfl_xor_sync(0xffffffffu, sh, 2);
            if (t == 0) {
                pr[wn * 128 + mbase + q] = sl;
                pr[wn * 128 + mbase + q + 8] = sh;
            }
            __syncthreads();
            size_t off = (ch == 0) ? OFF_KC : OFF_QN;
#pragma unroll
            for (int nt = 0; nt < 8; nt++) {
                int rr = mbase + q, cc = wn * 64 + nt * 8 + 2 * t;
                float i0 = 1.0f / fmaxf(sqrtf(pr[rr] + pr[128 + rr]), 1e-6f);
                float i1 = 1.0f / fmaxf(sqrtf(pr[rr + 8] + pr[128 + rr + 8]), 1e-6f);
                size_t o0 = off + ((size_t)(p0 + rr) * 64 + g) * 128 + cc;
                size_t o1 = off + ((size_t)(p0 + rr + 8) * 64 + g) * 128 + cc;
                *(float2*)&out[o0] = make_float2(acc[nt][0] * i0, acc[nt][1] * i0);
                *(float2*)&out[o1] = make_float2(acc[nt][2] * i1, acc[nt][3] * i1);
            }
        }
        if (ch < 2) {
            __syncthreads();
            cpy68((ch & 1) ? B1 : B0,
                  gw_post + (size_t)g * 32768 + (ch + 2) * 8192, 128, tid);
            cp_commit();
        }
    }
}

// ===========================================================================
extern "C" void kernel_launch(void* const* d_in, const int* in_sizes, int n_in,
                              void* d_out, int out_size) {
    const float* x_col  = (const float*)d_in[0];
    const float* zhp    = (const float*)d_in[1];
    const float* ln_g   = (const float*)d_in[2];
    const float* ln_b   = (const float*)d_in[3];
    const float* up_w   = (const float*)d_in[4];
    const float* up_b   = (const float*)d_in[5];
    const float* down_w = (const float*)d_in[6];
    const float* down_b = (const float*)d_in[7];
    const float* lat_g  = (const float*)d_in[8];
    const float* lat_b  = (const float*)d_in[9];
    const float* wq     = (const float*)d_in[10];
    const float* bq     = (const float*)d_in[11];
    const float* wk     = (const float*)d_in[12];
    const float* bk     = (const float*)d_in[13];
    const float* wv     = (const float*)d_in[14];
    const float* bv     = (const float*)d_in[15];
    const float* wo     = (const float*)d_in[16];
    const float* bo     = (const float*)d_in[17];
    const float* post_w = (const float*)d_in[18];
    const float* post_b = (const float*)d_in[19];
    const float* enc_w  = (const float*)d_in[20];
    const float* enc_b  = (const float*)d_in[21];
    const float* pred_w = (const float*)d_in[22];
    const float* pred_b = (const float*)d_in[23];
    const float* gain_w = (const float*)d_in[24];
    const float* gain_b = (const float*)d_in[25];
    float* out = (float*)d_out;

    const int SM_FA   = 48384 * 4;   // 193536
    const int SM_MEGA = 35840 * 4;   // 143360

    cudaFuncSetAttribute(k_fattn, cudaFuncAttributeMaxDynamicSharedMemorySize, SM_FA);
    cudaFuncSetAttribute(k_mega,  cudaFuncAttributeMaxDynamicSharedMemorySize, SM_MEGA);

    uint32_t* d_enc;  cudaGetSymbolAddress((void**)&d_enc,  gw_enc);
    uint32_t* d_pred; cudaGetSymbolAddress((void**)&d_pred, gw_pred);
    uint32_t* d_gain; cudaGetSymbolAddress((void**)&d_gain, gw_gain);
    uint32_t* d_up;   cudaGetSymbolAddress((void**)&d_up,   gw_up);
    uint32_t* d_down; cudaGetSymbolAddress((void**)&d_down, gw_down);
    uint32_t* d_post; cudaGetSymbolAddress((void**)&d_post, gw_post);

    k_tcvt_qkvo2<<<dim3(4, 4, 4), 256>>>(wq, wk, wv, wo);
    k_tcvt2<<<dim3(4, 2, 64), 256>>>(enc_w, d_enc, 8192, 64, 4096,
                                     6, 0, 7, 0, 63, 64, 127);
    k_tcvt2<<<dim3(2, 2, 64), 256>>>(pred_w, d_pred, 4096, 64, 2048,
                                     6, 0, 6, 0, 63, 32, 63);
    k_tcvt2<<<dim3(2, 4, 64), 256>>>(gain_w, d_gain, 8192, 128, 4096,
                                     7, 0, 6, 0, 127, 32, 63);
    k_tcvt2<<<dim3(4, 16, 64), 256>>>(up_w, d_up, 65536, 512, 32768,
                                      6, 4096, 7, 0, 63, 64, 127);
    k_tcvt2<<<dim3(16, 4, 64), 256>>>(down_w, d_down, 65536, 128, 32768,
                                      7, 0, 6, 4096, 127, 32, 63);
    k_tcvt2<<<dim3(4, 16, 64), 256>>>(post_w, d_post, 65664, 513, 32768,
                                      7, 8192, 7, 0, 127, 64, 127);
    k_plast<<<32, 256>>>(post_w);

    k_fattn<<<R_TOT / 64, 512, SM_FA>>>(x_col, lat_g, lat_b, bq, bk, bv, bo);
    k_mega<<<dim3(TOKS / 128, 64), 512, SM_MEGA>>>(zhp, ln_g, ln_b,
                                                   enc_b, pred_b, gain_b,
                                                   up_b, down_b, post_b, out);
}

// round 11
// speedup vs baseline: 1.4295x; 1.0249x over previous
#include <cuda_runtime.h>
#include <cuda_fp16.h>
#include <math.h>
#include <stdint.h>

#define R_TOT 131072   // BS*N*G rows
#define TOKS  2048     // BS*N tokens

static constexpr size_t OFF_XOUT = 0;
static constexpr size_t OFF_Z    = 16777216;
static constexpr size_t OFF_ZH   = 25165824;
static constexpr size_t OFF_S    = 33554432;
static constexpr size_t OFF_KC   = 33685504;
static constexpr size_t OFF_VP   = 50462720;
static constexpr size_t OFF_G    = 67239936;
static constexpr size_t OFF_QN   = 67371008;
static constexpr size_t OFF_VC   = 84148224;
static constexpr size_t OFF_WN   = 100925440;

// Scratch
__device__ float g_xa[16777216];

// fp16 weights (half2-packed uint32), n-major [n][k]
__device__ uint32_t gw_qkvo[32768];       // [sel][n128][k128/2]
__device__ uint32_t gw_enc [262144];      // [g][n64][k128/2]
__device__ uint32_t gw_pred[131072];      // [g][n64][k64/2]
__device__ uint32_t gw_gain[262144];      // [g][n128][k64/2]
__device__ uint32_t gw_up  [2097152];     // [g][ch4][n128][k128/2]  (8192/chunk)
__device__ uint32_t gw_down[2097152];     // [g][ch4][n128][k128/2]  (8192/chunk)
__device__ uint32_t gw_post[2097152];     // [g][ch4][n128][k128/2]  (8192/chunk)
__device__ float    gw_plast[8192];       // [g][k128]

// ===========================================================================
__device__ __forceinline__ uint32_t pack2(float lo, float hi) {
    uint32_t r;
    asm("cvt.rn.f16x2.f32 %0, %1, %2;" : "=r"(r) : "f"(hi), "f"(lo));
    return r;
}
__device__ __forceinline__ float2 unp2(uint32_t v) {
    __half2 h = *reinterpret_cast<__half2*>(&v);
    return __half22float2(h);
}
__device__ __forceinline__ void mma_h(float* c, uint32_t a0, uint32_t a1,
                                      uint32_t a2, uint32_t a3,
                                      uint32_t b0, uint32_t b1) {
    asm volatile(
        "mma.sync.aligned.m16n8k16.row.col.f32.f16.f16.f32 "
        "{%0,%1,%2,%3}, {%4,%5,%6,%7}, {%8,%9}, {%0,%1,%2,%3};"
        : "+f"(c[0]), "+f"(c[1]), "+f"(c[2]), "+f"(c[3])
        : "r"(a0), "r"(a1), "r"(a2), "r"(a3), "r"(b0), "r"(b1));
}
__device__ __forceinline__ void cp16(void* smem, const void* gmem) {
    uint32_t s = (uint32_t)__cvta_generic_to_shared(smem);
    asm volatile("cp.async.cg.shared.global [%0], [%1], 16;" :: "r"(s), "l"(gmem));
}
__device__ __forceinline__ void cp_commit() {
    asm volatile("cp.async.commit_group;" ::: "memory");
}
template<int N> __device__ __forceinline__ void cp_wait() {
    asm volatile("cp.async.wait_group %0;" :: "n"(N) : "memory");
}
// rows of 64 uint (k128 halfs) -> smem stride 68 words  (512-thread blocks)
__device__ __forceinline__ void cpy68(uint32_t* dst, const uint32_t* src,
                                      int rows, int tid) {
    for (int i = tid; i < rows * 16; i += 512) {
        int r = i >> 4, c = (i & 15) * 4;
        cp16(dst + r * 68 + c, src + r * 64 + c);
    }
}
// rows of 32 uint (k64 halfs) -> smem stride 36 words
__device__ __forceinline__ void cpy36(uint32_t* dst, const uint32_t* src,
                                      int rows, int tid) {
    for (int i = tid; i < rows * 8; i += 512) {
        int r = i >> 3, c = (i & 7) * 4;
        cp16(dst + r * 36 + c, src + r * 32 + c);
    }
}
// fp16 GEMM: warp computes 16 x NT*8 tile. As/Bs word strides LDA/LDB.
template<int LDA, int LDB, int NT>
__device__ __forceinline__ void gemm_h(float acc[NT][4],
        const uint32_t* __restrict__ As, const uint32_t* __restrict__ Bs,
        int mbase, int nbase, int Kw, int q, int t) {
#pragma unroll 2
    for (int kw = 0; kw < Kw; kw += 8) {
        const uint32_t* ap0 = As + (mbase + q) * LDA + kw + t;
        const uint32_t* ap1 = As + (mbase + q + 8) * LDA + kw + t;
        uint32_t a0 = ap0[0], a2 = ap0[4];
        uint32_t a1 = ap1[0], a3 = ap1[4];
#pragma unroll
        for (int nt = 0; nt < NT; nt++) {
            const uint32_t* bp = Bs + (nbase + nt * 8 + q) * LDB + kw + t;
            mma_h(acc[nt], a0, a1, a2, a3, bp[0], bp[4]);
        }
    }
}
__device__ __forceinline__ void zero_acc(float* a, int n) {
#pragma unroll
    for (int i = 0; i < n; i++) a[i] = 0.f;
}

// ===========================================================================
// Weight prep: src [K][N] fp32 -> dst n-major half2-packed
// ===========================================================================
__global__ void k_tcvt2(const float* __restrict__ src, uint32_t* __restrict__ dst,
                        long sgs, int sld, long gs,
                        int ns, int nchs, int ks, int kchs,
                        int cm, int ldn, int km) {
    __shared__ float tile[32][33];
    int g = blockIdx.z;
    int k0 = blockIdx.x * 32, n0 = blockIdx.y * 32;
    int tr = threadIdx.x >> 5, tc = threadIdx.x & 31;
    const float* s = src + (size_t)g * sgs;
#pragma unroll
    for (int i = 0; i < 4; i++)
        tile[tr + i * 8][tc] = s[(size_t)(k0 + tr + i * 8) * sld + n0 + tc];
    __syncthreads();
    uint32_t* d = dst + (size_t)g * gs;
    int np = threadIdx.x >> 4, kp = threadIdx.x & 15;
#pragma unroll
    for (int ii = 0; ii < 2; ii++) {
        int n = n0 + np + ii * 16, k = k0 + 2 * kp;
        uint32_t v = pack2(tile[2 * kp][np + ii * 16], tile[2 * kp + 1][np + ii * 16]);
        d[(size_t)(n >> ns) * nchs + (size_t)(k >> ks) * kchs
          + (n & cm) * ldn + ((k & km) >> 1)] = v;
    }
}
__global__ void k_tcvt_qkvo2(const float* __restrict__ wq, const float* __restrict__ wk,
                             const float* __restrict__ wv, const float* __restrict__ wo) {
    __shared__ float tile[32][33];
    int sel = blockIdx.z;
    const float* s = (sel == 0) ? wq : (sel == 1) ? wk : (sel == 2) ? wv : wo;
    int k0 = blockIdx.x * 32, n0 = blockIdx.y * 32;
    int tr = threadIdx.x >> 5, tc = threadIdx.x & 31;
#pragma unroll
    for (int i = 0; i < 4; i++)
        tile[tr + i * 8][tc] = s[(size_t)(k0 + tr + i * 8) * 128 + n0 + tc];
    __syncthreads();
    uint32_t* d = gw_qkvo + sel * 8192;
    int np = threadIdx.x >> 4, kp = threadIdx.x & 15;
#pragma unroll
    for (int ii = 0; ii < 2; ii++) {
        int n = n0 + np + ii * 16, k = k0 + 2 * kp;
        d[n * 64 + (k >> 1)] =
            pack2(tile[2 * kp][np + ii * 16], tile[2 * kp + 1][np + ii * 16]);
    }
}
__global__ void k_plast(const float* __restrict__ pw) {
    int i = blockIdx.x * 256 + threadIdx.x;
    if (i < 8192)
        gw_plast[i] = pw[(size_t)i * 513 + 512];
}

// ===========================================================================
// K1: fused LN + QKV + attention + wo.  grid 2048 (64 rows), 512 thr.
// ===========================================================================
__global__ __launch_bounds__(512, 1)
void k_fattn(const float* __restrict__ x,
             const float* __restrict__ latg, const float* __restrict__ latb,
             const float* __restrict__ bq, const float* __restrict__ bk,
             const float* __restrict__ bv, const float* __restrict__ bo) {
    extern __shared__ uint32_t sm[];
    uint32_t* As = sm;                   // 64 x 68 (half)
    uint32_t* W0 = As + 4352;            // 128 x 68 (half)
    uint32_t* W1 = W0 + 8704;            // 128 x 68 (half)
    float* Kf = (float*)(W1 + 8704);     // 64 x 136 fp32
    float* Vf = Kf + 8704;               // 64 x 136 fp32
    float* Qb = Vf + 8704;               // 64 x 132 fp32
    float* sc = Qb + 8448;               // 512
    float* sg = sc + 512;                // 128
    float* sb = sg + 128;                // 128
    const int tid = threadIdx.x;
    const size_t rowbase = (size_t)blockIdx.x * 64;

    cpy68(W0, gw_qkvo, 128, tid);         cp_commit();  // wq
    cpy68(W1, gw_qkvo + 8192, 128, tid);  cp_commit();  // wk

    if (tid < 128) { sg[tid] = latg[tid]; sb[tid] = latb[tid]; }
    const int r = tid >> 3, qt = tid & 7;
    {
        const float* xr = x + (rowbase + r) * 128 + qt * 16;
        float xv[16];
        float s = 0.f, s2 = 0.f;
#pragma unroll
        for (int j = 0; j < 16; j += 4) {
            float4 v = *(const float4*)&xr[j];
            xv[j] = v.x; xv[j + 1] = v.y; xv[j + 2] = v.z; xv[j + 3] = v.w;
            s += v.x + v.y + v.z + v.w;
            s2 += v.x * v.x + v.y * v.y + v.z * v.z + v.w * v.w;
        }
        s  += __shfl_xor_sync(0xffffffffu, s, 1);
        s  += __shfl_xor_sync(0xffffffffu, s, 2);
        s  += __shfl_xor_sync(0xffffffffu, s, 4);
        s2 += __shfl_xor_sync(0xffffffffu, s2, 1);
        s2 += __shfl_xor_sync(0xffffffffu, s2, 2);
        s2 += __shfl_xor_sync(0xffffffffu, s2, 4);
        float mu = s * (1.f / 128.f);
        float rs = rsqrtf(s2 * (1.f / 128.f) - mu * mu + 1e-5f);
        __syncthreads();   // sg/sb visible
        uint32_t* ar = As + r * 68 + qt * 8;
#pragma unroll
        for (int j = 0; j < 16; j += 2) {
            int c = qt * 16 + j;
            float h0 = (xv[j] - mu) * rs * sg[c] + sb[c];
            float h1 = (xv[j + 1] - mu) * rs * sg[c + 1] + sb[c + 1];
            ar[j >> 1] = pack2(h0, h1);
        }
    }
    __syncthreads();       // As final
    cp_wait<1>();          // wq arrived
    __syncthreads();

    const int w = tid >> 5, lane = tid & 31, q = lane >> 2, t = lane & 3;
    const int mbase = (w & 3) * 16, nbase = (w >> 2) * 32;

    {   // Q gemm -> Qb fp32
        float acc[4][4];
        zero_acc(&acc[0][0], 16);
        gemm_h<68, 68, 4>(acc, As, W0, mbase, nbase, 64, q, t);
#pragma unroll
        for (int nt = 0; nt < 4; nt++) {
            int rr = mbase + q, cc = nbase + nt * 8 + 2 * t;
            float b0 = bq[cc], b1 = bq[cc + 1];
            Qb[rr * 132 + cc]           = acc[nt][0] + b0;
            Qb[rr * 132 + cc + 1]       = acc[nt][1] + b1;
            Qb[(rr + 8) * 132 + cc]     = acc[nt][2] + b0;
            Qb[(rr + 8) * 132 + cc + 1] = acc[nt][3] + b1;
        }
    }
    __syncthreads();                          // W0 reads done
    cpy68(W0, gw_qkvo + 16384, 128, tid);     // wv
    cp_commit();
    cp_wait<1>();                             // wk arrived
    __syncthreads();
    {   // K gemm (W1) -> Kf fp32
        float acc[4][4];
        zero_acc(&acc[0][0], 16);
        gemm_h<68, 68, 4>(acc, As, W1, mbase, nbase, 64, q, t);
#pragma unroll
        for (int nt = 0; nt < 4; nt++) {
            int rr = mbase + q, cc = nbase + nt * 8 + 2 * t;
            float b0 = bk[cc], b1 = bk[cc + 1];
            Kf[rr * 136 + cc]           = acc[nt][0] + b0;
            Kf[rr * 136 + cc + 1]       = acc[nt][1] + b1;
            Kf[(rr + 8) * 136 + cc]     = acc[nt][2] + b0;
            Kf[(rr + 8) * 136 + cc + 1] = acc[nt][3] + b1;
        }
    }
    __syncthreads();                          // W1 reads done; Kf final
    cpy68(W1, gw_qkvo + 24576, 128, tid);     // wo
    cp_commit();
    {   // scores
        int rowq = tid >> 3;
        int grp = tid >> 6, e = tid & 7;
        const float* qp = Qb + rowq * 132;
        const float* kp = Kf + (grp * 8 + e) * 136;
        float s = 0.f;
#pragma unroll 8
        for (int d = 0; d < 128; d += 4) {
            float4 a = *(const float4*)&qp[d];
            float4 b = *(const float4*)&kp[d];
            s += a.x * b.x + a.y * b.y + a.z * b.z + a.w * b.w;
        }
        sc[tid] = s * 0.088388347648318447f;
    }
    __syncthreads();
    if (tid < 64) {    // softmax over e
        float* row = sc + tid * 8;
        float m = row[0];
#pragma unroll
        for (int e = 1; e < 8; e++) m = fmaxf(m, row[e]);
        float ex[8], ssum = 0.f;
#pragma unroll
        for (int e = 0; e < 8; e++) { ex[e] = expf(row[e] - m); ssum += ex[e]; }
        float inv = 1.0f / ssum;
#pragma unroll
        for (int e = 0; e < 8; e++) row[e] = ex[e] * inv;
    }
    cp_wait<1>();                             // wv arrived
    __syncthreads();
    {   // V gemm (W0) -> Vf fp32
        float acc[4][4];
        zero_acc(&acc[0][0], 16);
        gemm_h<68, 68, 4>(acc, As, W0, mbase, nbase, 64, q, t);
#pragma unroll
        for (int nt = 0; nt < 4; nt++) {
            int rr = mbase + q, cc = nbase + nt * 8 + 2 * t;
            float b0 = bv[cc], b1 = bv[cc + 1];
            Vf[rr * 136 + cc]           = acc[nt][0] + b0;
            Vf[rr * 136 + cc + 1]       = acc[nt][1] + b1;
            Vf[(rr + 8) * 136 + cc]     = acc[nt][2] + b0;
            Vf[(rr + 8) * 136 + cc + 1] = acc[nt][3] + b1;
        }
    }
    __syncthreads();                          // Vf final
    {   // o = attn @ V -> As (fp16), in place
        int rr = tid >> 3, d0 = (tid & 7) * 16;
        const float* vb = Vf + (rr & ~7) * 136;
        float a[8];
#pragma unroll
        for (int e = 0; e < 8; e++) a[e] = sc[rr * 8 + e];
        uint32_t* ar = As + rr * 68 + (d0 >> 1);
#pragma unroll
        for (int j = 0; j < 16; j += 4) {
            float4 o = make_float4(0.f, 0.f, 0.f, 0.f);
#pragma unroll
            for (int e = 0; e < 8; e++) {
                float4 v = *(const float4*)&vb[e * 136 + d0 + j];
                o.x += a[e] * v.x; o.y += a[e] * v.y;
                o.z += a[e] * v.z; o.w += a[e] * v.w;
            }
            ar[(j >> 1)]     = pack2(o.x, o.y);
            ar[(j >> 1) + 1] = pack2(o.z, o.w);
        }
    }
    cp_wait<0>();                             // wo arrived
    __syncthreads();                          // As(o) final
    {   // wo gemm (W1) + residual -> g_xa
        float acc[4][4];
        zero_acc(&acc[0][0], 16);
        gemm_h<68, 68, 4>(acc, As, W1, mbase, nbase, 64, q, t);
#pragma unroll
        for (int nt = 0; nt < 4; nt++) {
            int rr = mbase + q, cc = nbase + nt * 8 + 2 * t;
            float b0 = bo[cc], b1 = bo[cc + 1];
            size_t o0 = (rowbase + rr) * 128 + cc;
            size_t o1 = (rowbase + rr + 8) * 128 + cc;
            float2 x0 = *(const float2*)&x[o0];
            float2 x1 = *(const float2*)&x[o1];
            *(float2*)&g_xa[o0] = make_float2(x0.x + acc[nt][0] + b0,
                                              x0.y + acc[nt][1] + b1);
            *(float2*)&g_xa[o1] = make_float2(x1.x + acc[nt][2] + b0,
                                              x1.y + acc[nt][3] + b1);
        }
    }
}

// ===========================================================================
// K2: mega per-group kernel: small + MLP(H128 chunks) + post.  grid (16,64), 512 thr.
// words: As 8704 | Zs 4608 | Ds 4608 | B0 8704 | B1 8704 | misc 512
// Us overlays Zs+Ds (8704 <= 9216).
// ===========================================================================
__global__ __launch_bounds__(512, 1)
void k_mega(const float* __restrict__ zhp,
            const float* __restrict__ lng, const float* __restrict__ lnb,
            const float* __restrict__ encb, const float* __restrict__ predb,
            const float* __restrict__ gainb, const float* __restrict__ upb,
            const float* __restrict__ dwb, const float* __restrict__ pb,
            float* out) {
    extern __shared__ uint32_t sm[];
    uint32_t* As = sm;                  // 128 x 68 (half)
    uint32_t* Zs = As + 8704;           // 128 x 36 (half)
    uint32_t* Ds = Zs + 4608;           // 128 x 36 (half)
    uint32_t* B0 = Ds + 4608;           // 8704
    uint32_t* B1 = B0 + 8704;           // 8704
    float* smu = (float*)(B1 + 8704);   // 128
    float* srs = smu + 128;             // 128
    float* pr  = srs + 128;             // 256
    const int tid = threadIdx.x;
    const int g = blockIdx.y, p0 = blockIdx.x * 128;

    cpy68(B0, gw_enc + (size_t)g * 4096, 64, tid);   cp_commit();
    cpy36(B1, gw_pred + (size_t)g * 2048, 64, tid);  cp_commit();

    {   // As = fp16(x_attn), stats
        const int r = tid >> 2, h = tid & 3;
        const float* xr = g_xa + ((size_t)(p0 + r) * 64 + g) * 128 + h * 32;
        float xv[32];
        float s = 0.f, s2 = 0.f;
#pragma unroll
        for (int j = 0; j < 32; j += 4) {
            float4 v = *(const float4*)&xr[j];
            xv[j] = v.x; xv[j + 1] = v.y; xv[j + 2] = v.z; xv[j + 3] = v.w;
            s += v.x + v.y + v.z + v.w;
            s2 += v.x * v.x + v.y * v.y + v.z * v.z + v.w * v.w;
        }
        uint32_t* ar = As + r * 68 + h * 16;
#pragma unroll
        for (int j = 0; j < 32; j += 2)
            ar[j >> 1] = pack2(xv[j], xv[j + 1]);
        s  += __shfl_xor_sync(0xffffffffu, s, 1);
        s  += __shfl_xor_sync(0xffffffffu, s, 2);
        s2 += __shfl_xor_sync(0xffffffffu, s2, 1);
        s2 += __shfl_xor_sync(0xffffffffu, s2, 2);
        float mu = s * (1.f / 128.f);
        if (h == 0) {
            smu[r] = mu;
            srs[r] = rsqrtf(s2 * (1.f / 128.f) - mu * mu + 1e-5f);
        }
    }
    cp_wait<1>();     // enc ready
    __syncthreads();

    const int w = tid >> 5, lane = tid & 31, q = lane >> 2, t = lane & 3;
    const int mbase = (w & 7) * 16, wn = w >> 3;

    {   // enc GEMM: z = x @ enc_w  (16 x 32 per warp, Kw=64)
        float acc[4][4];
        zero_acc(&acc[0][0], 16);
        gemm_h<68, 68, 4>(acc, As, B0, mbase, wn * 32, 64, q, t);
        float sl = 0.f, sh = 0.f;
#pragma unroll
        for (int nt = 0; nt < 4; nt++) {
            int cc = wn * 32 + nt * 8 + 2 * t;
            int rlo = mbase + q, rhi = rlo + 8;
            float z0 = acc[nt][0] + encb[g * 64 + cc];
            float z1 = acc[nt][1] + encb[g * 64 + cc + 1];
            float z2 = acc[nt][2] + encb[g * 64 + cc];
            float z3 = acc[nt][3] + encb[g * 64 + cc + 1];
            size_t qlo = (size_t)(p0 + rlo) * 64 + g;
            size_t qhi = (size_t)(p0 + rhi) * 64 + g;
            *(float2*)&out[OFF_Z + qlo * 64 + cc] = make_float2(z0, z1);
            *(float2*)&out[OFF_Z + qhi * 64 + cc] = make_float2(z2, z3);
            float2 plo = *(const float2*)&zhp[qlo * 64 + cc];
            float2 phi = *(const float2*)&zhp[qhi * 64 + cc];
            float d0 = z0 - plo.x, d1 = z1 - plo.y;
            float d2 = z2 - phi.x, d3 = z3 - phi.y;
            int wi = cc >> 1;
            Zs[rlo * 36 + wi] = pack2(z0, z1);
            Zs[rhi * 36 + wi] = pack2(z2, z3);
            Ds[rlo * 36 + wi] = pack2(d0, d1);
            Ds[rhi * 36 + wi] = pack2(d2, d3);
            sl += d0 * d0 + d1 * d1;
            sh += d2 * d2 + d3 * d3;
        }
        sl += __shfl_xor_sync(0xffffffffu, sl, 1);
        sl += __shfl_xor_sync(0xffffffffu, sl, 2);
        sh += __shfl_xor_sync(0xffffffffu, sh, 1);
        sh += __shfl_xor_sync(0xffffffffu, sh, 2);
        if (t == 0) {
            pr[wn * 128 + mbase + q] = sl;
            pr[wn * 128 + mbase + q + 8] = sh;
        }
    }
    __syncthreads();                                    // Zs/Ds/pr visible; B0 free
    if (tid < 128) {   // surprise + gate
        float sp = sqrtf(pr[tid] + pr[128 + tid]);
        size_t qq = (size_t)(p0 + tid) * 64 + g;
        out[OFF_S + qq] = sp;
        out[OFF_G + qq] = fminf(sp, 1.0f);
    }
    cpy68(B0, gw_up + (size_t)g * 32768, 128, tid);     cp_commit();   // up0 (H128)
    cp_wait<1>();                                       // pred ready
    __syncthreads();
    {   // pred GEMM (Zs @ pred, Kw=32)
        float acc[4][4];
        zero_acc(&acc[0][0], 16);
        gemm_h<36, 36, 4>(acc, Zs, B1, mbase, wn * 32, 32, q, t);
#pragma unroll
        for (int nt = 0; nt < 4; nt++) {
            int cc = wn * 32 + nt * 8 + 2 * t;
            size_t qlo = (size_t)(p0 + mbase + q) * 64 + g;
            size_t qhi = (size_t)(p0 + mbase + q + 8) * 64 + g;
            float b0 = predb[g * 64 + cc], b1 = predb[g * 64 + cc + 1];
            *(float2*)&out[OFF_ZH + qlo * 64 + cc] =
                make_float2(acc[nt][0] + b0, acc[nt][1] + b1);
            *(float2*)&out[OFF_ZH + qhi * 64 + cc] =
                make_float2(acc[nt][2] + b0, acc[nt][3] + b1);
        }
    }
    __syncthreads();                                    // B1 free
    cpy36(B1, gw_gain + (size_t)g * 4096, 128, tid);    cp_commit();   // gain
    cp_wait<0>();                                       // up0 + gain ready
    __syncthreads();
    {   // gain GEMM (Ds @ gain, 16x64, Kw=32) + GLN epilogue -> As := fp16(hh)
        float acc[8][4];
        zero_acc(&acc[0][0], 32);
        gemm_h<36, 36, 8>(acc, Ds, B1, mbase, wn * 64, 32, q, t);
        int rlo = mbase + q, rhi = rlo + 8;
        float mlo = smu[rlo], rslo = srs[rlo];
        float mhi = smu[rhi], rshi = srs[rhi];
#pragma unroll
        for (int nt = 0; nt < 8; nt++) {
            int cc = wn * 64 + nt * 8 + 2 * t, wi = cc >> 1;
            float lg0 = lng[(size_t)g * 128 + cc], lb0 = lnb[(size_t)g * 128 + cc];
            float lg1 = lng[(size_t)g * 128 + cc + 1], lb1 = lnb[(size_t)g * 128 + cc + 1];
            float gb0 = gainb[(size_t)g * 128 + cc], gb1 = gainb[(size_t)g * 128 + cc + 1];
            float2 xlo = unp2(As[rlo * 68 + wi]);
            float2 xhi = unp2(As[rhi * 68 + wi]);
            float h00 = ((xlo.x - mlo) * rslo * lg0 + lb0)
                        * (1.0f + 0.1f * tanhf(acc[nt][0] + gb0));
            float h01 = ((xlo.y - mlo) * rslo * lg1 + lb1)
                        * (1.0f + 0.1f * tanhf(acc[nt][1] + gb1));
            float h10 = ((xhi.x - mhi) * rshi * lg0 + lb0)
                        * (1.0f + 0.1f * tanhf(acc[nt][2] + gb0));
            float h11 = ((xhi.y - mhi) * rshi * lg1 + lb1)
                        * (1.0f + 0.1f * tanhf(acc[nt][3] + gb1));
            As[rlo * 68 + wi] = pack2(h00, h01);
            As[rhi * 68 + wi] = pack2(h10, h11);
        }
    }
    __syncthreads();                                    // As(hh); B1/Zs/Ds free
    cpy68(B1, gw_down + (size_t)g * 32768, 128, tid);   cp_commit();   // down0 (H128)

    uint32_t* Us = Zs;   // 128 x 68, overlays Zs+Ds
    float oacc[8][4];
    zero_acc(&oacc[0][0], 32);
    for (int ch = 0; ch < 4; ch++) {
        float uacc[8][4];
        zero_acc(&uacc[0][0], 32);
        gemm_h<68, 68, 8>(uacc, As, B0, mbase, wn * 64, 64, q, t);
#pragma unroll
        for (int nt = 0; nt < 8; nt++) {
            int cc = wn * 64 + nt * 8 + 2 * t, wi = cc >> 1;
            int rlo = mbase + q, rhi = rlo + 8;
            float b0 = upb[(size_t)g * 512 + ch * 128 + cc];
            float b1 = upb[(size_t)g * 512 + ch * 128 + cc + 1];
            float u00 = uacc[nt][0] + b0, u01 = uacc[nt][1] + b1;
            float u10 = uacc[nt][2] + b0, u11 = uacc[nt][3] + b1;
            u00 = 0.5f * u00 * (1.0f + erff(u00 * 0.70710678118654752f));
            u01 = 0.5f * u01 * (1.0f + erff(u01 * 0.70710678118654752f));
            u10 = 0.5f * u10 * (1.0f + erff(u10 * 0.70710678118654752f));
            u11 = 0.5f * u11 * (1.0f + erff(u11 * 0.70710678118654752f));
            Us[rlo * 68 + wi] = pack2(u00, u01);
            Us[rhi * 68 + wi] = pack2(u10, u11);
        }
        __syncthreads();                 // Us visible; B0 reads done
        if (ch < 3) {
            cpy68(B0, gw_up + (size_t)g * 32768 + (ch + 1) * 8192, 128, tid);
            cp_commit();
            cp_wait<1>();                // down_ch ready
        } else {
            cp_wait<0>();
        }
        __syncthreads();
        gemm_h<68, 68, 8>(oacc, Us, B1, mbase, wn * 64, 64, q, t);
        if (ch < 3) {
            __syncthreads();             // B1 reads done
            cpy68(B1, gw_down + (size_t)g * 32768 + (ch + 1) * 8192, 128, tid);
            cp_commit();
            cp_wait<1>();                // up_{ch+1} ready
            __syncthreads();
        }
    }
    __syncthreads();                     // last down gemm reads done
    {   // MLP epilogue -> gmem x_out AND As := fp16(x_out)
#pragma unroll
        for (int nt = 0; nt < 8; nt++) {
            int cc = wn * 64 + nt * 8 + 2 * t, wi = cc >> 1;
            int rlo = mbase + q, rhi = rlo + 8;
            float b0 = dwb[(size_t)g * 128 + cc], b1 = dwb[(size_t)g * 128 + cc + 1];
            size_t o0 = ((size_t)(p0 + rlo) * 64 + g) * 128 + cc;
            size_t o1 = ((size_t)(p0 + rhi) * 64 + g) * 128 + cc;
            float2 x0 = *(const float2*)&g_xa[o0];
            float2 x1 = *(const float2*)&g_xa[o1];
            float v00 = x0.x + oacc[nt][0] + b0, v01 = x0.y + oacc[nt][1] + b1;
            float v10 = x1.x + oacc[nt][2] + b0, v11 = x1.y + oacc[nt][3] + b1;
            *(float2*)&out[OFF_XOUT + o0] = make_float2(v00, v01);
            *(float2*)&out[OFF_XOUT + o1] = make_float2(v10, v11);
            As[rlo * 68 + wi] = pack2(v00, v01);
            As[rhi * 68 + wi] = pack2(v10, v11);
        }
    }
    __syncthreads();                     // As(x_out); B0/B1 free
    cpy68(B0, gw_post + (size_t)g * 32768, 128, tid);         cp_commit();
    cpy68(B1, gw_post + (size_t)g * 32768 + 8192, 128, tid);  cp_commit();

    if (tid < 128) {   // w_nov
        const float* wl = gw_plast + g * 128;
        float s = 0.f;
        for (int kw = 0; kw < 64; kw++) {
            float2 xv = unp2(As[tid * 68 + kw]);
            s += xv.x * wl[2 * kw] + xv.y * wl[2 * kw + 1];
        }
        s += pb[(size_t)g * 513 + 512];
        out[OFF_WN + (size_t)(p0 + tid) * 64 + g] = 1.0f / (1.0f + expf(-s));
    }

    for (int ch = 0; ch < 4; ch++) {
        if (ch < 3) cp_wait<1>(); else cp_wait<0>();
        __syncthreads();
        uint32_t* Bs = (ch & 1) ? B1 : B0;
        float acc[8][4];
        zero_acc(&acc[0][0], 32);
        gemm_h<68, 68, 8>(acc, As, Bs, mbase, wn * 64, 64, q, t);
#pragma unroll
        for (int nt = 0; nt < 8; nt++) {
            int cc = wn * 64 + nt * 8 + 2 * t;
            float b0 = pb[(size_t)g * 513 + ch * 128 + cc];
            float b1 = pb[(size_t)g * 513 + ch * 128 + cc + 1];
            acc[nt][0] += b0; acc[nt][1] += b1;
            acc[nt][2] += b0; acc[nt][3] += b1;
        }
        if (ch == 1 || ch == 3) {
            size_t off = (ch == 1) ? OFF_VP : OFF_VC;
#pragma unroll
            for (int nt = 0; nt < 8; nt++) {
                int rr = mbase + q, cc = wn * 64 + nt * 8 + 2 * t;
                size_t o0 = off + ((size_t)(p0 + rr) * 64 + g) * 128 + cc;
                size_t o1 = off + ((size_t)(p0 + rr + 8) * 64 + g) * 128 + cc;
                *(float2*)&out[o0] = make_float2(acc[nt][0], acc[nt][1]);
                *(float2*)&out[o1] = make_float2(acc[nt][2], acc[nt][3]);
            }
        } else {
            float sl = 0.f, sh = 0.f;
#pragma unroll
            for (int nt = 0; nt < 8; nt++) {
                sl += acc[nt][0] * acc[nt][0] + acc[nt][1] * acc[nt][1];
                sh += acc[nt][2] * acc[nt][2] + acc[nt][3] * acc[nt][3];
            }
            sl += __shfl_xor_sync(0xffffffffu, sl, 1);
            sl += __shfl_xor_sync(0xffffffffu, sl, 2);
            sh += __shfl_xor_sync(0xffffffffu, sh, 1);
            sh += __shfl_xor_sync(0xffffffffu, sh, 2);
            if (t == 0) {
                pr[wn * 128 + mbase + q] = sl;
                pr[wn * 128 + mbase + q + 8] = sh;
            }
            __syncthreads();
            size_t off = (ch == 0) ? OFF_KC : OFF_QN;
#pragma unroll
            for (int nt = 0; nt < 8; nt++) {
                int rr = mbase + q, cc = wn * 64 + nt * 8 + 2 * t;
                float i0 = 1.0f / fmaxf(sqrtf(pr[rr] + pr[128 + rr]), 1e-6f);
                float i1 = 1.0f / fmaxf(sqrtf(pr[rr + 8] + pr[128 + rr + 8]), 1e-6f);
                size_t o0 = off + ((size_t)(p0 + rr) * 64 + g) * 128 + cc;
                size_t o1 = off + ((size_t)(p0 + rr + 8) * 64 + g) * 128 + cc;
                *(float2*)&out[o0] = make_float2(acc[nt][0] * i0, acc[nt][1] * i0);
                *(float2*)&out[o1] = make_float2(acc[nt][2] * i1, acc[nt][3] * i1);
            }
        }
        if (ch < 2) {
            __syncthreads();
            cpy68((ch & 1) ? B1 : B0,
                  gw_post + (size_t)g * 32768 + (ch + 2) * 8192, 128, tid);
            cp_commit();
        }
    }
}

// ===========================================================================
extern "C" void kernel_launch(void* const* d_in, const int* in_sizes, int n_in,
                              void* d_out, int out_size) {
    const float* x_col  = (const float*)d_in[0];
    const float* zhp    = (const float*)d_in[1];
    const float* ln_g   = (const float*)d_in[2];
    const float* ln_b   = (const float*)d_in[3];
    const float* up_w   = (const float*)d_in[4];
    const float* up_b   = (const float*)d_in[5];
    const float* down_w = (const float*)d_in[6];
    const float* down_b = (const float*)d_in[7];
    const float* lat_g  = (const float*)d_in[8];
    const float* lat_b  = (const float*)d_in[9];
    const float* wq     = (const float*)d_in[10];
    const float* bq     = (const float*)d_in[11];
    const float* wk     = (const float*)d_in[12];
    const float* bk     = (const float*)d_in[13];
    const float* wv     = (const float*)d_in[14];
    const float* bv     = (const float*)d_in[15];
    const float* wo     = (const float*)d_in[16];
    const float* bo     = (const float*)d_in[17];
    const float* post_w = (const float*)d_in[18];
    const float* post_b = (const float*)d_in[19];
    const float* enc_w  = (const float*)d_in[20];
    const float* enc_b  = (const float*)d_in[21];
    const float* pred_w = (const float*)d_in[22];
    const float* pred_b = (const float*)d_in[23];
    const float* gain_w = (const float*)d_in[24];
    const float* gain_b = (const float*)d_in[25];
    float* out = (float*)d_out;

    const int SM_FA   = 48384 * 4;   // 193536
    const int SM_MEGA = 35840 * 4;   // 143360

    cudaFuncSetAttribute(k_fattn, cudaFuncAttributeMaxDynamicSharedMemorySize, SM_FA);
    cudaFuncSetAttribute(k_mega,  cudaFuncAttributeMaxDynamicSharedMemorySize, SM_MEGA);

    uint32_t* d_enc;  cudaGetSymbolAddress((void**)&d_enc,  gw_enc);
    uint32_t* d_pred; cudaGetSymbolAddress((void**)&d_pred, gw_pred);
    uint32_t* d_gain; cudaGetSymbolAddress((void**)&d_gain, gw_gain);
    uint32_t* d_up;   cudaGetSymbolAddress((void**)&d_up,   gw_up);
    uint32_t* d_down; cudaGetSymbolAddress((void**)&d_down, gw_down);
    uint32_t* d_post; cudaGetSymbolAddress((void**)&d_post, gw_post);

    k_tcvt_qkvo2<<<dim3(4, 4, 4), 256>>>(wq, wk, wv, wo);
    k_tcvt2<<<dim3(4, 2, 64), 256>>>(enc_w, d_enc, 8192, 64, 4096,
                                     6, 0, 7, 0, 63, 64, 127);
    k_tcvt2<<<dim3(2, 2, 64), 256>>>(pred_w, d_pred, 4096, 64, 2048,
                                     6, 0, 6, 0, 63, 32, 63);
    k_tcvt2<<<dim3(2, 4, 64), 256>>>(gain_w, d_gain, 8192, 128, 4096,
                                     7, 0, 6, 0, 127, 32, 63);
    // up: [k128][n512] -> [g][n>>7][n&127][k/2]
    k_tcvt2<<<dim3(4, 16, 64), 256>>>(up_w, d_up, 65536, 512, 32768,
                                      7, 8192, 7, 0, 127, 64, 127);
    // down: [k512][n128] -> [g][k>>7][n][(k&127)/2]
    k_tcvt2<<<dim3(16, 4, 64), 256>>>(down_w, d_down, 65536, 128, 32768,
                                      7, 0, 7, 8192, 127, 64, 127);
    k_tcvt2<<<dim3(4, 16, 64), 256>>>(post_w, d_post, 65664, 513, 32768,
                                      7, 8192, 7, 0, 127, 64, 127);
    k_plast<<<32, 256>>>(post_w);

    k_fattn<<<R_TOT / 64, 512, SM_FA>>>(x_col, lat_g, lat_b, bq, bk, bv, bo);
    k_mega<<<dim3(TOKS / 128, 64), 512, SM_MEGA>>>(zhp, ln_g, ln_b,
                                                   enc_b, pred_b, gain_b,
                                                   up_b, down_b, post_b, out);
}

// round 12
// speedup vs baseline: 1.4769x; 1.0331x over previous
#include <cuda_runtime.h>
#include <cuda_fp16.h>
#include <math.h>
#include <stdint.h>

#define R_TOT 131072   // BS*N*G rows
#define TOKS  2048     // BS*N tokens

static constexpr size_t OFF_XOUT = 0;
static constexpr size_t OFF_Z    = 16777216;
static constexpr size_t OFF_ZH   = 25165824;
static constexpr size_t OFF_S    = 33554432;
static constexpr size_t OFF_KC   = 33685504;
static constexpr size_t OFF_VP   = 50462720;
static constexpr size_t OFF_G    = 67239936;
static constexpr size_t OFF_QN   = 67371008;
static constexpr size_t OFF_VC   = 84148224;
static constexpr size_t OFF_WN   = 100925440;

// Scratch
__device__ float g_xa[16777216];

// fp16 weights (half2-packed uint32), n-major [n][k]
__device__ uint32_t gw_qkvo[32768];       // [sel][n128][k128/2]
__device__ uint32_t gw_enc [262144];      // [g][n64][k128/2]
__device__ uint32_t gw_pred[131072];      // [g][n64][k64/2]
__device__ uint32_t gw_gain[262144];      // [g][n128][k64/2]
__device__ uint32_t gw_up  [2097152];     // [g][ch4][n128][k128/2]  (8192/chunk)
__device__ uint32_t gw_down[2097152];     // [g][ch4][n128][k128/2]  (8192/chunk)
__device__ uint32_t gw_post[2097152];     // [g][ch4][n128][k128/2]  (8192/chunk)
__device__ float    gw_plast[8192];       // [g][k128]

// ===========================================================================
__device__ __forceinline__ uint32_t pack2(float lo, float hi) {
    uint32_t r;
    asm("cvt.rn.f16x2.f32 %0, %1, %2;" : "=r"(r) : "f"(hi), "f"(lo));
    return r;
}
__device__ __forceinline__ float2 unp2(uint32_t v) {
    __half2 h = *reinterpret_cast<__half2*>(&v);
    return __half22float2(h);
}
__device__ __forceinline__ void mma_h(float* c, uint32_t a0, uint32_t a1,
                                      uint32_t a2, uint32_t a3,
                                      uint32_t b0, uint32_t b1) {
    asm volatile(
        "mma.sync.aligned.m16n8k16.row.col.f32.f16.f16.f32 "
        "{%0,%1,%2,%3}, {%4,%5,%6,%7}, {%8,%9}, {%0,%1,%2,%3};"
        : "+f"(c[0]), "+f"(c[1]), "+f"(c[2]), "+f"(c[3])
        : "r"(a0), "r"(a1), "r"(a2), "r"(a3), "r"(b0), "r"(b1));
}
__device__ __forceinline__ void cp16(void* smem, const void* gmem) {
    uint32_t s = (uint32_t)__cvta_generic_to_shared(smem);
    asm volatile("cp.async.cg.shared.global [%0], [%1], 16;" :: "r"(s), "l"(gmem));
}
__device__ __forceinline__ void cp_commit() {
    asm volatile("cp.async.commit_group;" ::: "memory");
}
template<int N> __device__ __forceinline__ void cp_wait() {
    asm volatile("cp.async.wait_group %0;" :: "n"(N) : "memory");
}
__device__ __forceinline__ void cpy68(uint32_t* dst, const uint32_t* src,
                                      int rows, int tid) {
    for (int i = tid; i < rows * 16; i += 512) {
        int r = i >> 4, c = (i & 15) * 4;
        cp16(dst + r * 68 + c, src + r * 64 + c);
    }
}
__device__ __forceinline__ void cpy36(uint32_t* dst, const uint32_t* src,
                                      int rows, int tid) {
    for (int i = tid; i < rows * 8; i += 512) {
        int r = i >> 3, c = (i & 7) * 4;
        cp16(dst + r * 36 + c, src + r * 32 + c);
    }
}
template<int LDA, int LDB, int NT>
__device__ __forceinline__ void gemm_h(float acc[NT][4],
        const uint32_t* __restrict__ As, const uint32_t* __restrict__ Bs,
        int mbase, int nbase, int Kw, int q, int t) {
#pragma unroll 2
    for (int kw = 0; kw < Kw; kw += 8) {
        const uint32_t* ap0 = As + (mbase + q) * LDA + kw + t;
        const uint32_t* ap1 = As + (mbase + q + 8) * LDA + kw + t;
        uint32_t a0 = ap0[0], a2 = ap0[4];
        uint32_t a1 = ap1[0], a3 = ap1[4];
#pragma unroll
        for (int nt = 0; nt < NT; nt++) {
            const uint32_t* bp = Bs + (nbase + nt * 8 + q) * LDB + kw + t;
            mma_h(acc[nt], a0, a1, a2, a3, bp[0], bp[4]);
        }
    }
}
__device__ __forceinline__ void zero_acc(float* a, int n) {
#pragma unroll
    for (int i = 0; i < n; i++) a[i] = 0.f;
}

// ===========================================================================
// Weight prep
// ===========================================================================
__global__ void k_tcvt2(const float* __restrict__ src, uint32_t* __restrict__ dst,
                        long sgs, int sld, long gs,
                        int ns, int nchs, int ks, int kchs,
                        int cm, int ldn, int km) {
    __shared__ float tile[32][33];
    int g = blockIdx.z;
    int k0 = blockIdx.x * 32, n0 = blockIdx.y * 32;
    int tr = threadIdx.x >> 5, tc = threadIdx.x & 31;
    const float* s = src + (size_t)g * sgs;
#pragma unroll
    for (int i = 0; i < 4; i++)
        tile[tr + i * 8][tc] = s[(size_t)(k0 + tr + i * 8) * sld + n0 + tc];
    __syncthreads();
    uint32_t* d = dst + (size_t)g * gs;
    int np = threadIdx.x >> 4, kp = threadIdx.x & 15;
#pragma unroll
    for (int ii = 0; ii < 2; ii++) {
        int n = n0 + np + ii * 16, k = k0 + 2 * kp;
        uint32_t v = pack2(tile[2 * kp][np + ii * 16], tile[2 * kp + 1][np + ii * 16]);
        d[(size_t)(n >> ns) * nchs + (size_t)(k >> ks) * kchs
          + (n & cm) * ldn + ((k & km) >> 1)] = v;
    }
}
__global__ void k_tcvt_qkvo2(const float* __restrict__ wq, const float* __restrict__ wk,
                             const float* __restrict__ wv, const float* __restrict__ wo) {
    __shared__ float tile[32][33];
    int sel = blockIdx.z;
    const float* s = (sel == 0) ? wq : (sel == 1) ? wk : (sel == 2) ? wv : wo;
    int k0 = blockIdx.x * 32, n0 = blockIdx.y * 32;
    int tr = threadIdx.x >> 5, tc = threadIdx.x & 31;
#pragma unroll
    for (int i = 0; i < 4; i++)
        tile[tr + i * 8][tc] = s[(size_t)(k0 + tr + i * 8) * 128 + n0 + tc];
    __syncthreads();
    uint32_t* d = gw_qkvo + sel * 8192;
    int np = threadIdx.x >> 4, kp = threadIdx.x & 15;
#pragma unroll
    for (int ii = 0; ii < 2; ii++) {
        int n = n0 + np + ii * 16, k = k0 + 2 * kp;
        d[n * 64 + (k >> 1)] =
            pack2(tile[2 * kp][np + ii * 16], tile[2 * kp + 1][np + ii * 16]);
    }
}
__global__ void k_plast(const float* __restrict__ pw) {
    int i = blockIdx.x * 256 + threadIdx.x;
    if (i < 8192)
        gw_plast[i] = pw[(size_t)i * 513 + 512];
}

// ===========================================================================
// K1: fused LN + QKV + attention + wo.  grid 1024 (128 rows), 512 thr.
// words: As 8704 | W0 8704 | W1 8704 | Qh 8704 | KVf 17408 | sc 1024 | sg/sb 256
// ===========================================================================
__global__ __launch_bounds__(512, 1)
void k_fattn(const float* __restrict__ x,
             const float* __restrict__ latg, const float* __restrict__ latb,
             const float* __restrict__ bq, const float* __restrict__ bk,
             const float* __restrict__ bv, const float* __restrict__ bo) {
    extern __shared__ uint32_t sm[];
    uint32_t* As = sm;                   // 128 x 68 (half)  h, later o
    uint32_t* W0 = As + 8704;            // weights
    uint32_t* W1 = W0 + 8704;
    uint32_t* Qh = W1 + 8704;            // 128 x 68 (half)  Q
    float* KVf = (float*)(Qh + 8704);    // 128 x 136 fp32   K then V
    float* sc = KVf + 17408;             // 1024 scores
    float* sg = sc + 1024;               // 128
    float* sb = sg + 128;                // 128
    const int tid = threadIdx.x;
    const size_t rowbase = (size_t)blockIdx.x * 128;

    cpy68(W0, gw_qkvo, 128, tid);         cp_commit();  // wq
    cpy68(W1, gw_qkvo + 8192, 128, tid);  cp_commit();  // wk

    if (tid < 128) { sg[tid] = latg[tid]; sb[tid] = latb[tid]; }
    {   // LN: 128 rows x 4 thr, 32 cols each -> As fp16
        const int r = tid >> 2, h = tid & 3;
        const float* xr = x + (rowbase + r) * 128 + h * 32;
        float xv[32];
        float s = 0.f, s2 = 0.f;
#pragma unroll
        for (int j = 0; j < 32; j += 4) {
            float4 v = *(const float4*)&xr[j];
            xv[j] = v.x; xv[j + 1] = v.y; xv[j + 2] = v.z; xv[j + 3] = v.w;
            s += v.x + v.y + v.z + v.w;
            s2 += v.x * v.x + v.y * v.y + v.z * v.z + v.w * v.w;
        }
        s  += __shfl_xor_sync(0xffffffffu, s, 1);
        s  += __shfl_xor_sync(0xffffffffu, s, 2);
        s2 += __shfl_xor_sync(0xffffffffu, s2, 1);
        s2 += __shfl_xor_sync(0xffffffffu, s2, 2);
        float mu = s * (1.f / 128.f);
        float rs = rsqrtf(s2 * (1.f / 128.f) - mu * mu + 1e-5f);
        __syncthreads();   // sg/sb visible
        uint32_t* ar = As + r * 68 + h * 16;
#pragma unroll
        for (int j = 0; j < 32; j += 2) {
            int c = h * 32 + j;
            float h0 = (xv[j] - mu) * rs * sg[c] + sb[c];
            float h1 = (xv[j + 1] - mu) * rs * sg[c + 1] + sb[c + 1];
            ar[j >> 1] = pack2(h0, h1);
        }
    }
    __syncthreads();       // As final
    cp_wait<1>();          // wq arrived
    __syncthreads();

    const int w = tid >> 5, lane = tid & 31, q = lane >> 2, t = lane & 3;
    const int mbase = (w & 7) * 16, nbase = (w >> 3) * 64;

    {   // Q gemm -> Qh fp16
        float acc[8][4];
        zero_acc(&acc[0][0], 32);
        gemm_h<68, 68, 8>(acc, As, W0, mbase, nbase, 64, q, t);
#pragma unroll
        for (int nt = 0; nt < 8; nt++) {
            int rr = mbase + q, cc = nbase + nt * 8 + 2 * t, wi = cc >> 1;
            float b0 = bq[cc], b1 = bq[cc + 1];
            Qh[rr * 68 + wi]       = pack2(acc[nt][0] + b0, acc[nt][1] + b1);
            Qh[(rr + 8) * 68 + wi] = pack2(acc[nt][2] + b0, acc[nt][3] + b1);
        }
    }
    __syncthreads();                          // W0 reads done
    cpy68(W0, gw_qkvo + 16384, 128, tid);     // wv
    cp_commit();
    cp_wait<1>();                             // wk arrived
    __syncthreads();
    {   // K gemm (W1) -> KVf fp32
        float acc[8][4];
        zero_acc(&acc[0][0], 32);
        gemm_h<68, 68, 8>(acc, As, W1, mbase, nbase, 64, q, t);
#pragma unroll
        for (int nt = 0; nt < 8; nt++) {
            int rr = mbase + q, cc = nbase + nt * 8 + 2 * t;
            float b0 = bk[cc], b1 = bk[cc + 1];
            KVf[rr * 136 + cc]           = acc[nt][0] + b0;
            KVf[rr * 136 + cc + 1]       = acc[nt][1] + b1;
            KVf[(rr + 8) * 136 + cc]     = acc[nt][2] + b0;
            KVf[(rr + 8) * 136 + cc + 1] = acc[nt][3] + b1;
        }
    }
    __syncthreads();                          // W1 reads done; K final
    cpy68(W1, gw_qkvo + 24576, 128, tid);     // wo
    cp_commit();
    {   // scores: 1024 (grp,c,e) pairs, two per thread
#pragma unroll
        for (int i = 0; i < 2; i++) {
            int p = tid + 512 * i;
            int rowq = p >> 3;
            int grp = p >> 6, e = p & 7;
            const uint32_t* qp = Qh + rowq * 68;
            const float* kp = KVf + (grp * 8 + e) * 136;
            float s = 0.f;
#pragma unroll 8
            for (int kw = 0; kw < 64; kw += 2) {
                float2 q0 = unp2(qp[kw]);
                float2 q1 = unp2(qp[kw + 1]);
                float4 kv = *(const float4*)&kp[2 * kw];
                s += q0.x * kv.x + q0.y * kv.y + q1.x * kv.z + q1.y * kv.w;
            }
            sc[p] = s * 0.088388347648318447f;
        }
    }
    __syncthreads();
    if (tid < 128) {    // softmax over e per (grp,c)
        float* row = sc + tid * 8;
        float m = row[0];
#pragma unroll
        for (int e = 1; e < 8; e++) m = fmaxf(m, row[e]);
        float ex[8], ssum = 0.f;
#pragma unroll
        for (int e = 0; e < 8; e++) { ex[e] = expf(row[e] - m); ssum += ex[e]; }
        float inv = 1.0f / ssum;
#pragma unroll
        for (int e = 0; e < 8; e++) row[e] = ex[e] * inv;
    }
    cp_wait<1>();                             // wv arrived
    __syncthreads();
    {   // V gemm (W0) -> regs, then overwrite KVf (K dead)
        float acc[8][4];
        zero_acc(&acc[0][0], 32);
        gemm_h<68, 68, 8>(acc, As, W0, mbase, nbase, 64, q, t);
        __syncthreads();                      // all K reads (scores) done
#pragma unroll
        for (int nt = 0; nt < 8; nt++) {
            int rr = mbase + q, cc = nbase + nt * 8 + 2 * t;
            float b0 = bv[cc], b1 = bv[cc + 1];
            KVf[rr * 136 + cc]           = acc[nt][0] + b0;
            KVf[rr * 136 + cc + 1]       = acc[nt][1] + b1;
            KVf[(rr + 8) * 136 + cc]     = acc[nt][2] + b0;
            KVf[(rr + 8) * 136 + cc + 1] = acc[nt][3] + b1;
        }
    }
    __syncthreads();                          // V final
    {   // o = attn @ V -> As (fp16), in place
        int rr = tid >> 2, d0 = (tid & 3) * 32;
        const float* vb = KVf + (rr & ~7) * 136;
        float a[8];
#pragma unroll
        for (int e = 0; e < 8; e++) a[e] = sc[rr * 8 + e];
        uint32_t* ar = As + rr * 68 + (d0 >> 1);
#pragma unroll
        for (int j = 0; j < 32; j += 4) {
            float4 o = make_float4(0.f, 0.f, 0.f, 0.f);
#pragma unroll
            for (int e = 0; e < 8; e++) {
                float4 v = *(const float4*)&vb[e * 136 + d0 + j];
                o.x += a[e] * v.x; o.y += a[e] * v.y;
                o.z += a[e] * v.z; o.w += a[e] * v.w;
            }
            ar[(j >> 1)]     = pack2(o.x, o.y);
            ar[(j >> 1) + 1] = pack2(o.z, o.w);
        }
    }
    cp_wait<0>();                             // wo arrived
    __syncthreads();                          // As(o) final
    {   // wo gemm (W1) + residual -> g_xa
        float acc[8][4];
        zero_acc(&acc[0][0], 32);
        gemm_h<68, 68, 8>(acc, As, W1, mbase, nbase, 64, q, t);
#pragma unroll
        for (int nt = 0; nt < 8; nt++) {
            int rr = mbase + q, cc = nbase + nt * 8 + 2 * t;
            float b0 = bo[cc], b1 = bo[cc + 1];
            size_t o0 = (rowbase + rr) * 128 + cc;
            size_t o1 = (rowbase + rr + 8) * 128 + cc;
            float2 x0 = *(const float2*)&x[o0];
            float2 x1 = *(const float2*)&x[o1];
            *(float2*)&g_xa[o0] = make_float2(x0.x + acc[nt][0] + b0,
                                              x0.y + acc[nt][1] + b1);
            *(float2*)&g_xa[o1] = make_float2(x1.x + acc[nt][2] + b0,
                                              x1.y + acc[nt][3] + b1);
        }
    }
}

// ===========================================================================
// K2: mega per-group kernel: small + MLP(H128 chunks) + post.  grid (16,64), 512 thr.
// ===========================================================================
__global__ __launch_bounds__(512, 1)
void k_mega(const float* __restrict__ zhp,
            const float* __restrict__ lng, const float* __restrict__ lnb,
            const float* __restrict__ encb, const float* __restrict__ predb,
            const float* __restrict__ gainb, const float* __restrict__ upb,
            const float* __restrict__ dwb, const float* __restrict__ pb,
            float* out) {
    extern __shared__ uint32_t sm[];
    uint32_t* As = sm;                  // 128 x 68 (half)
    uint32_t* Zs = As + 8704;           // 128 x 36 (half)
    uint32_t* Ds = Zs + 4608;           // 128 x 36 (half)
    uint32_t* B0 = Ds + 4608;           // 8704
    uint32_t* B1 = B0 + 8704;           // 8704
    float* smu = (float*)(B1 + 8704);   // 128
    float* srs = smu + 128;             // 128
    float* pr  = srs + 128;             // 256
    const int tid = threadIdx.x;
    const int g = blockIdx.y, p0 = blockIdx.x * 128;

    cpy68(B0, gw_enc + (size_t)g * 4096, 64, tid);   cp_commit();
    cpy36(B1, gw_pred + (size_t)g * 2048, 64, tid);  cp_commit();

    {   // As = fp16(x_attn), stats
        const int r = tid >> 2, h = tid & 3;
        const float* xr = g_xa + ((size_t)(p0 + r) * 64 + g) * 128 + h * 32;
        float xv[32];
        float s = 0.f, s2 = 0.f;
#pragma unroll
        for (int j = 0; j < 32; j += 4) {
            float4 v = *(const float4*)&xr[j];
            xv[j] = v.x; xv[j + 1] = v.y; xv[j + 2] = v.z; xv[j + 3] = v.w;
            s += v.x + v.y + v.z + v.w;
            s2 += v.x * v.x + v.y * v.y + v.z * v.z + v.w * v.w;
        }
        uint32_t* ar = As + r * 68 + h * 16;
#pragma unroll
        for (int j = 0; j < 32; j += 2)
            ar[j >> 1] = pack2(xv[j], xv[j + 1]);
        s  += __shfl_xor_sync(0xffffffffu, s, 1);
        s  += __shfl_xor_sync(0xffffffffu, s, 2);
        s2 += __shfl_xor_sync(0xffffffffu, s2, 1);
        s2 += __shfl_xor_sync(0xffffffffu, s2, 2);
        float mu = s * (1.f / 128.f);
        if (h == 0) {
            smu[r] = mu;
            srs[r] = rsqrtf(s2 * (1.f / 128.f) - mu * mu + 1e-5f);
        }
    }
    cp_wait<1>();     // enc ready
    __syncthreads();

    const int w = tid >> 5, lane = tid & 31, q = lane >> 2, t = lane & 3;
    const int mbase = (w & 7) * 16, wn = w >> 3;

    {   // enc GEMM
        float acc[4][4];
        zero_acc(&acc[0][0], 16);
        gemm_h<68, 68, 4>(acc, As, B0, mbase, wn * 32, 64, q, t);
        float sl = 0.f, sh = 0.f;
#pragma unroll
        for (int nt = 0; nt < 4; nt++) {
            int cc = wn * 32 + nt * 8 + 2 * t;
            int rlo = mbase + q, rhi = rlo + 8;
            float z0 = acc[nt][0] + encb[g * 64 + cc];
            float z1 = acc[nt][1] + encb[g * 64 + cc + 1];
            float z2 = acc[nt][2] + encb[g * 64 + cc];
            float z3 = acc[nt][3] + encb[g * 64 + cc + 1];
            size_t qlo = (size_t)(p0 + rlo) * 64 + g;
            size_t qhi = (size_t)(p0 + rhi) * 64 + g;
            *(float2*)&out[OFF_Z + qlo * 64 + cc] = make_float2(z0, z1);
            *(float2*)&out[OFF_Z + qhi * 64 + cc] = make_float2(z2, z3);
            float2 plo = *(const float2*)&zhp[qlo * 64 + cc];
            float2 phi = *(const float2*)&zhp[qhi * 64 + cc];
            float d0 = z0 - plo.x, d1 = z1 - plo.y;
            float d2 = z2 - phi.x, d3 = z3 - phi.y;
            int wi = cc >> 1;
            Zs[rlo * 36 + wi] = pack2(z0, z1);
            Zs[rhi * 36 + wi] = pack2(z2, z3);
            Ds[rlo * 36 + wi] = pack2(d0, d1);
            Ds[rhi * 36 + wi] = pack2(d2, d3);
            sl += d0 * d0 + d1 * d1;
            sh += d2 * d2 + d3 * d3;
        }
        sl += __shfl_xor_sync(0xffffffffu, sl, 1);
        sl += __shfl_xor_sync(0xffffffffu, sl, 2);
        sh += __shfl_xor_sync(0xffffffffu, sh, 1);
        sh += __shfl_xor_sync(0xffffffffu, sh, 2);
        if (t == 0) {
            pr[wn * 128 + mbase + q] = sl;
            pr[wn * 128 + mbase + q + 8] = sh;
        }
    }
    __syncthreads();
    if (tid < 128) {   // surprise + gate
        float sp = sqrtf(pr[tid] + pr[128 + tid]);
        size_t qq = (size_t)(p0 + tid) * 64 + g;
        out[OFF_S + qq] = sp;
        out[OFF_G + qq] = fminf(sp, 1.0f);
    }
    cpy68(B0, gw_up + (size_t)g * 32768, 128, tid);     cp_commit();   // up0
    cp_wait<1>();                                       // pred ready
    __syncthreads();
    {   // pred GEMM
        float acc[4][4];
        zero_acc(&acc[0][0], 16);
        gemm_h<36, 36, 4>(acc, Zs, B1, mbase, wn * 32, 32, q, t);
#pragma unroll
        for (int nt = 0; nt < 4; nt++) {
            int cc = wn * 32 + nt * 8 + 2 * t;
            size_t qlo = (size_t)(p0 + mbase + q) * 64 + g;
            size_t qhi = (size_t)(p0 + mbase + q + 8) * 64 + g;
            float b0 = predb[g * 64 + cc], b1 = predb[g * 64 + cc + 1];
            *(float2*)&out[OFF_ZH + qlo * 64 + cc] =
                make_float2(acc[nt][0] + b0, acc[nt][1] + b1);
            *(float2*)&out[OFF_ZH + qhi * 64 + cc] =
                make_float2(acc[nt][2] + b0, acc[nt][3] + b1);
        }
    }
    __syncthreads();
    cpy36(B1, gw_gain + (size_t)g * 4096, 128, tid);    cp_commit();   // gain
    cp_wait<0>();
    __syncthreads();
    {   // gain GEMM + GLN epilogue -> As := fp16(hh)
        float acc[8][4];
        zero_acc(&acc[0][0], 32);
        gemm_h<36, 36, 8>(acc, Ds, B1, mbase, wn * 64, 32, q, t);
        int rlo = mbase + q, rhi = rlo + 8;
        float mlo = smu[rlo], rslo = srs[rlo];
        float mhi = smu[rhi], rshi = srs[rhi];
#pragma unroll
        for (int nt = 0; nt < 8; nt++) {
            int cc = wn * 64 + nt * 8 + 2 * t, wi = cc >> 1;
            float lg0 = lng[(size_t)g * 128 + cc], lb0 = lnb[(size_t)g * 128 + cc];
            float lg1 = lng[(size_t)g * 128 + cc + 1], lb1 = lnb[(size_t)g * 128 + cc + 1];
            float gb0 = gainb[(size_t)g * 128 + cc], gb1 = gainb[(size_t)g * 128 + cc + 1];
            float2 xlo = unp2(As[rlo * 68 + wi]);
            float2 xhi = unp2(As[rhi * 68 + wi]);
            float h00 = ((xlo.x - mlo) * rslo * lg0 + lb0)
                        * (1.0f + 0.1f * tanhf(acc[nt][0] + gb0));
            float h01 = ((xlo.y - mlo) * rslo * lg1 + lb1)
                        * (1.0f + 0.1f * tanhf(acc[nt][1] + gb1));
            float h10 = ((xhi.x - mhi) * rshi * lg0 + lb0)
                        * (1.0f + 0.1f * tanhf(acc[nt][2] + gb0));
            float h11 = ((xhi.y - mhi) * rshi * lg1 + lb1)
                        * (1.0f + 0.1f * tanhf(acc[nt][3] + gb1));
            As[rlo * 68 + wi] = pack2(h00, h01);
            As[rhi * 68 + wi] = pack2(h10, h11);
        }
    }
    __syncthreads();
    cpy68(B1, gw_down + (size_t)g * 32768, 128, tid);   cp_commit();   // down0

    uint32_t* Us = Zs;   // 128 x 68 overlays Zs+Ds
    float oacc[8][4];
    zero_acc(&oacc[0][0], 32);
    for (int ch = 0; ch < 4; ch++) {
        float uacc[8][4];
        zero_acc(&uacc[0][0], 32);
        gemm_h<68, 68, 8>(uacc, As, B0, mbase, wn * 64, 64, q, t);
#pragma unroll
        for (int nt = 0; nt < 8; nt++) {
            int cc = wn * 64 + nt * 8 + 2 * t, wi = cc >> 1;
            int rlo = mbase + q, rhi = rlo + 8;
            float b0 = upb[(size_t)g * 512 + ch * 128 + cc];
            float b1 = upb[(size_t)g * 512 + ch * 128 + cc + 1];
            float u00 = uacc[nt][0] + b0, u01 = uacc[nt][1] + b1;
            float u10 = uacc[nt][2] + b0, u11 = uacc[nt][3] + b1;
            u00 = 0.5f * u00 * (1.0f + erff(u00 * 0.70710678118654752f));
            u01 = 0.5f * u01 * (1.0f + erff(u01 * 0.70710678118654752f));
            u10 = 0.5f * u10 * (1.0f + erff(u10 * 0.70710678118654752f));
            u11 = 0.5f * u11 * (1.0f + erff(u11 * 0.70710678118654752f));
            Us[rlo * 68 + wi] = pack2(u00, u01);
            Us[rhi * 68 + wi] = pack2(u10, u11);
        }
        __syncthreads();
        if (ch < 3) {
            cpy68(B0, gw_up + (size_t)g * 32768 + (ch + 1) * 8192, 128, tid);
            cp_commit();
            cp_wait<1>();
        } else {
            cp_wait<0>();
        }
        __syncthreads();
        gemm_h<68, 68, 8>(oacc, Us, B1, mbase, wn * 64, 64, q, t);
        if (ch < 3) {
            __syncthreads();
            cpy68(B1, gw_down + (size_t)g * 32768 + (ch + 1) * 8192, 128, tid);
            cp_commit();
            cp_wait<1>();
            __syncthreads();
        }
    }
    __syncthreads();
    {   // MLP epilogue -> gmem x_out AND As := fp16(x_out)
#pragma unroll
        for (int nt = 0; nt < 8; nt++) {
            int cc = wn * 64 + nt * 8 + 2 * t, wi = cc >> 1;
            int rlo = mbase + q, rhi = rlo + 8;
            float b0 = dwb[(size_t)g * 128 + cc], b1 = dwb[(size_t)g * 128 + cc + 1];
            size_t o0 = ((size_t)(p0 + rlo) * 64 + g) * 128 + cc;
            size_t o1 = ((size_t)(p0 + rhi) * 64 + g) * 128 + cc;
            float2 x0 = *(const float2*)&g_xa[o0];
            float2 x1 = *(const float2*)&g_xa[o1];
            float v00 = x0.x + oacc[nt][0] + b0, v01 = x0.y + oacc[nt][1] + b1;
            float v10 = x1.x + oacc[nt][2] + b0, v11 = x1.y + oacc[nt][3] + b1;
            *(float2*)&out[OFF_XOUT + o0] = make_float2(v00, v01);
            *(float2*)&out[OFF_XOUT + o1] = make_float2(v10, v11);
            As[rlo * 68 + wi] = pack2(v00, v01);
            As[rhi * 68 + wi] = pack2(v10, v11);
        }
    }
    __syncthreads();
    cpy68(B0, gw_post + (size_t)g * 32768, 128, tid);         cp_commit();
    cpy68(B1, gw_post + (size_t)g * 32768 + 8192, 128, tid);  cp_commit();

    if (tid < 128) {   // w_nov
        const float* wl = gw_plast + g * 128;
        float s = 0.f;
        for (int kw = 0; kw < 64; kw++) {
            float2 xv = unp2(As[tid * 68 + kw]);
            s += xv.x * wl[2 * kw] + xv.y * wl[2 * kw + 1];
        }
        s += pb[(size_t)g * 513 + 512];
        out[OFF_WN + (size_t)(p0 + tid) * 64 + g] = 1.0f / (1.0f + expf(-s));
    }

    for (int ch = 0; ch < 4; ch++) {
        if (ch < 3) cp_wait<1>(); else cp_wait<0>();
        __syncthreads();
        uint32_t* Bs = (ch & 1) ? B1 : B0;
        float acc[8][4];
        zero_acc(&acc[0][0], 32);
        gemm_h<68, 68, 8>(acc, As, Bs, mbase, wn * 64, 64, q, t);
#pragma unroll
        for (int nt = 0; nt < 8; nt++) {
            int cc = wn * 64 + nt * 8 + 2 * t;
            float b0 = pb[(size_t)g * 513 + ch * 128 + cc];
            float b1 = pb[(size_t)g * 513 + ch * 128 + cc + 1];
            acc[nt][0] += b0; acc[nt][1] += b1;
            acc[nt][2] += b0; acc[nt][3] += b1;
        }
        if (ch == 1 || ch == 3) {
            size_t off = (ch == 1) ? OFF_VP : OFF_VC;
#pragma unroll
            for (int nt = 0; nt < 8; nt++) {
                int rr = mbase + q, cc = wn * 64 + nt * 8 + 2 * t;
                size_t o0 = off + ((size_t)(p0 + rr) * 64 + g) * 128 + cc;
                size_t o1 = off + ((size_t)(p0 + rr + 8) * 64 + g) * 128 + cc;
                *(float2*)&out[o0] = make_float2(acc[nt][0], acc[nt][1]);
                *(float2*)&out[o1] = make_float2(acc[nt][2], acc[nt][3]);
            }
        } else {
            float sl = 0.f, sh = 0.f;
#pragma unroll
            for (int nt = 0; nt < 8; nt++) {
                sl += acc[nt][0] * acc[nt][0] + acc[nt][1] * acc[nt][1];
                sh += acc[nt][2] * acc[nt][2] + acc[nt][3] * acc[nt][3];
            }
            sl += __shfl_xor_sync(0xffffffffu, sl, 1);
            sl += __shfl_xor_sync(0xffffffffu, sl, 2);
            sh += __shfl_xor_sync(0xffffffffu, sh, 1);
            sh += __shfl_xor_sync(0xffffffffu, sh, 2);
            if (t == 0) {
                pr[wn * 128 + mbase + q] = sl;
                pr[wn * 128 + mbase + q + 8] = sh;
            }
            __syncthreads();
            size_t off = (ch == 0) ? OFF_KC : OFF_QN;
#pragma unroll
            for (int nt = 0; nt < 8; nt++) {
                int rr = mbase + q, cc = wn * 64 + nt * 8 + 2 * t;
                float i0 = 1.0f / fmaxf(sqrtf(pr[rr] + pr[128 + rr]), 1e-6f);
                float i1 = 1.0f / fmaxf(sqrtf(pr[rr + 8] + pr[128 + rr + 8]), 1e-6f);
                size_t o0 = off + ((size_t)(p0 + rr) * 64 + g) * 128 + cc;
                size_t o1 = off + ((size_t)(p0 + rr + 8) * 64 + g) * 128 + cc;
                *(float2*)&out[o0] = make_float2(acc[nt][0] * i0, acc[nt][1] * i0);
                *(float2*)&out[o1] = make_float2(acc[nt][2] * i1, acc[nt][3] * i1);
            }
        }
        if (ch < 2) {
            __syncthreads();
            cpy68((ch & 1) ? B1 : B0,
                  gw_post + (size_t)g * 32768 + (ch + 2) * 8192, 128, tid);
            cp_commit();
        }
    }
}

// ===========================================================================
extern "C" void kernel_launch(void* const* d_in, const int* in_sizes, int n_in,
                              void* d_out, int out_size) {
    const float* x_col  = (const float*)d_in[0];
    const float* zhp    = (const float*)d_in[1];
    const float* ln_g   = (const float*)d_in[2];
    const float* ln_b   = (const float*)d_in[3];
    const float* up_w   = (const float*)d_in[4];
    const float* up_b   = (const float*)d_in[5];
    const float* down_w = (const float*)d_in[6];
    const float* down_b = (const float*)d_in[7];
    const float* lat_g  = (const float*)d_in[8];
    const float* lat_b  = (const float*)d_in[9];
    const float* wq     = (const float*)d_in[10];
    const float* bq     = (const float*)d_in[11];
    const float* wk     = (const float*)d_in[12];
    const float* bk     = (const float*)d_in[13];
    const float* wv     = (const float*)d_in[14];
    const float* bv     = (const float*)d_in[15];
    const float* wo     = (const float*)d_in[16];
    const float* bo     = (const float*)d_in[17];
    const float* post_w = (const float*)d_in[18];
    const float* post_b = (const float*)d_in[19];
    const float* enc_w  = (const float*)d_in[20];
    const float* enc_b  = (const float*)d_in[21];
    const float* pred_w = (const float*)d_in[22];
    const float* pred_b = (const float*)d_in[23];
    const float* gain_w = (const float*)d_in[24];
    const float* gain_b = (const float*)d_in[25];
    float* out = (float*)d_out;

    const int SM_FA   = 53504 * 4;   // 214016
    const int SM_MEGA = 35840 * 4;   // 143360

    cudaFuncSetAttribute(k_fattn, cudaFuncAttributeMaxDynamicSharedMemorySize, SM_FA);
    cudaFuncSetAttribute(k_mega,  cudaFuncAttributeMaxDynamicSharedMemorySize, SM_MEGA);

    uint32_t* d_enc;  cudaGetSymbolAddress((void**)&d_enc,  gw_enc);
    uint32_t* d_pred; cudaGetSymbolAddress((void**)&d_pred, gw_pred);
    uint32_t* d_gain; cudaGetSymbolAddress((void**)&d_gain, gw_gain);
    uint32_t* d_up;   cudaGetSymbolAddress((void**)&d_up,   gw_up);
    uint32_t* d_down; cudaGetSymbolAddress((void**)&d_down, gw_down);
    uint32_t* d_post; cudaGetSymbolAddress((void**)&d_post, gw_post);

    k_tcvt_qkvo2<<<dim3(4, 4, 4), 256>>>(wq, wk, wv, wo);
    k_tcvt2<<<dim3(4, 2, 64), 256>>>(enc_w, d_enc, 8192, 64, 4096,
                                     6, 0, 7, 0, 63, 64, 127);
    k_tcvt2<<<dim3(2, 2, 64), 256>>>(pred_w, d_pred, 4096, 64, 2048,
                                     6, 0, 6, 0, 63, 32, 63);
    k_tcvt2<<<dim3(2, 4, 64), 256>>>(gain_w, d_gain, 8192, 128, 4096,
                                     7, 0, 6, 0, 127, 32, 63);
    k_tcvt2<<<dim3(4, 16, 64), 256>>>(up_w, d_up, 65536, 512, 32768,
                                      7, 8192, 7, 0, 127, 64, 127);
    k_tcvt2<<<dim3(16, 4, 64), 256>>>(down_w, d_down, 65536, 128, 32768,
                                      7, 0, 7, 8192, 127, 64, 127);
    k_tcvt2<<<dim3(4, 16, 64), 256>>>(post_w, d_post, 65664, 513, 32768,
                                      7, 8192, 7, 0, 127, 64, 127);
    k_plast<<<32, 256>>>(post_w);

    k_fattn<<<R_TOT / 128, 512, SM_FA>>>(x_col, lat_g, lat_b, bq, bk, bv, bo);
    k_mega<<<dim3(TOKS / 128, 64), 512, SM_MEGA>>>(zhp, ln_g, ln_b,
                                                   enc_b, pred_b, gain_b,
                                                   up_b, down_b, post_b, out);
}

// round 13
// speedup vs baseline: 1.5531x; 1.0516x over previous
#include <cuda_runtime.h>
#include <cuda_fp16.h>
#include <math.h>
#include <stdint.h>

#define R_TOT 131072   // BS*N*G rows
#define TOKS  2048     // BS*N tokens

static constexpr size_t OFF_XOUT = 0;
static constexpr size_t OFF_Z    = 16777216;
static constexpr size_t OFF_ZH   = 25165824;
static constexpr size_t OFF_S    = 33554432;
static constexpr size_t OFF_KC   = 33685504;
static constexpr size_t OFF_VP   = 50462720;
static constexpr size_t OFF_G    = 67239936;
static constexpr size_t OFF_QN   = 67371008;
static constexpr size_t OFF_VC   = 84148224;
static constexpr size_t OFF_WN   = 100925440;

// Scratch
__device__ float g_xa[16777216];

// fp16 weights (half2-packed uint32), n-major [n][k]
__device__ uint32_t gw_qkvo[32768];       // [sel][n128][k128/2]
__device__ uint32_t gw_enc [262144];      // [g][n64][k128/2]
__device__ uint32_t gw_pred[131072];      // [g][n64][k64/2]
__device__ uint32_t gw_gain[262144];      // [g][n128][k64/2]
__device__ uint32_t gw_up  [2097152];     // [g][ch4][n128][k128/2]  (8192/chunk)
__device__ uint32_t gw_down[2097152];     // [g][ch4][n128][k128/2]  (8192/chunk)
__device__ uint32_t gw_post[2097152];     // [g][ch4][n128][k128/2]  (8192/chunk)
__device__ float    gw_plast[8192];       // [g][k128]

// ===========================================================================
__device__ __forceinline__ uint32_t pack2(float lo, float hi) {
    uint32_t r;
    asm("cvt.rn.f16x2.f32 %0, %1, %2;" : "=r"(r) : "f"(hi), "f"(lo));
    return r;
}
__device__ __forceinline__ float2 unp2(uint32_t v) {
    __half2 h = *reinterpret_cast<__half2*>(&v);
    return __half22float2(h);
}
__device__ __forceinline__ void mma_h(float* c, uint32_t a0, uint32_t a1,
                                      uint32_t a2, uint32_t a3,
                                      uint32_t b0, uint32_t b1) {
    asm volatile(
        "mma.sync.aligned.m16n8k16.row.col.f32.f16.f16.f32 "
        "{%0,%1,%2,%3}, {%4,%5,%6,%7}, {%8,%9}, {%0,%1,%2,%3};"
        : "+f"(c[0]), "+f"(c[1]), "+f"(c[2]), "+f"(c[3])
        : "r"(a0), "r"(a1), "r"(a2), "r"(a3), "r"(b0), "r"(b1));
}
__device__ __forceinline__ void cp16(void* smem, const void* gmem) {
    uint32_t s = (uint32_t)__cvta_generic_to_shared(smem);
    asm volatile("cp.async.cg.shared.global [%0], [%1], 16;" :: "r"(s), "l"(gmem));
}
__device__ __forceinline__ void cp_commit() {
    asm volatile("cp.async.commit_group;" ::: "memory");
}
template<int N> __device__ __forceinline__ void cp_wait() {
    asm volatile("cp.async.wait_group %0;" :: "n"(N) : "memory");
}
template<int NTHR>
__device__ __forceinline__ void cpy68(uint32_t* dst, const uint32_t* src,
                                      int rows, int tid) {
    for (int i = tid; i < rows * 16; i += NTHR) {
        int r = i >> 4, c = (i & 15) * 4;
        cp16(dst + r * 68 + c, src + r * 64 + c);
    }
}
template<int NTHR>
__device__ __forceinline__ void cpy36(uint32_t* dst, const uint32_t* src,
                                      int rows, int tid) {
    for (int i = tid; i < rows * 8; i += NTHR) {
        int r = i >> 3, c = (i & 7) * 4;
        cp16(dst + r * 36 + c, src + r * 32 + c);
    }
}
template<int LDA, int LDB, int NT>
__device__ __forceinline__ void gemm_h(float acc[NT][4],
        const uint32_t* __restrict__ As, const uint32_t* __restrict__ Bs,
        int mbase, int nbase, int Kw, int q, int t) {
#pragma unroll 2
    for (int kw = 0; kw < Kw; kw += 8) {
        const uint32_t* ap0 = As + (mbase + q) * LDA + kw + t;
        const uint32_t* ap1 = As + (mbase + q + 8) * LDA + kw + t;
        uint32_t a0 = ap0[0], a2 = ap0[4];
        uint32_t a1 = ap1[0], a3 = ap1[4];
#pragma unroll
        for (int nt = 0; nt < NT; nt++) {
            const uint32_t* bp = Bs + (nbase + nt * 8 + q) * LDB + kw + t;
            mma_h(acc[nt], a0, a1, a2, a3, bp[0], bp[4]);
        }
    }
}
__device__ __forceinline__ void zero_acc(float* a, int n) {
#pragma unroll
    for (int i = 0; i < n; i++) a[i] = 0.f;
}

// ===========================================================================
// Weight prep
// ===========================================================================
__global__ void k_tcvt2(const float* __restrict__ src, uint32_t* __restrict__ dst,
                        long sgs, int sld, long gs,
                        int ns, int nchs, int ks, int kchs,
                        int cm, int ldn, int km) {
    __shared__ float tile[32][33];
    int g = blockIdx.z;
    int k0 = blockIdx.x * 32, n0 = blockIdx.y * 32;
    int tr = threadIdx.x >> 5, tc = threadIdx.x & 31;
    const float* s = src + (size_t)g * sgs;
#pragma unroll
    for (int i = 0; i < 4; i++)
        tile[tr + i * 8][tc] = s[(size_t)(k0 + tr + i * 8) * sld + n0 + tc];
    __syncthreads();
    uint32_t* d = dst + (size_t)g * gs;
    int np = threadIdx.x >> 4, kp = threadIdx.x & 15;
#pragma unroll
    for (int ii = 0; ii < 2; ii++) {
        int n = n0 + np + ii * 16, k = k0 + 2 * kp;
        uint32_t v = pack2(tile[2 * kp][np + ii * 16], tile[2 * kp + 1][np + ii * 16]);
        d[(size_t)(n >> ns) * nchs + (size_t)(k >> ks) * kchs
          + (n & cm) * ldn + ((k & km) >> 1)] = v;
    }
}
__global__ void k_tcvt_qkvo2(const float* __restrict__ wq, const float* __restrict__ wk,
                             const float* __restrict__ wv, const float* __restrict__ wo) {
    __shared__ float tile[32][33];
    int sel = blockIdx.z;
    const float* s = (sel == 0) ? wq : (sel == 1) ? wk : (sel == 2) ? wv : wo;
    int k0 = blockIdx.x * 32, n0 = blockIdx.y * 32;
    int tr = threadIdx.x >> 5, tc = threadIdx.x & 31;
#pragma unroll
    for (int i = 0; i < 4; i++)
        tile[tr + i * 8][tc] = s[(size_t)(k0 + tr + i * 8) * 128 + n0 + tc];
    __syncthreads();
    uint32_t* d = gw_qkvo + sel * 8192;
    int np = threadIdx.x >> 4, kp = threadIdx.x & 15;
#pragma unroll
    for (int ii = 0; ii < 2; ii++) {
        int n = n0 + np + ii * 16, k = k0 + 2 * kp;
        d[n * 64 + (k >> 1)] =
            pack2(tile[2 * kp][np + ii * 16], tile[2 * kp + 1][np + ii * 16]);
    }
}
__global__ void k_plast(const float* __restrict__ pw) {
    int i = blockIdx.x * 256 + threadIdx.x;
    if (i < 8192)
        gw_plast[i] = pw[(size_t)i * 513 + 512];
}

// ===========================================================================
// K1: fused LN + QKV + attention + wo.  grid 1024 (128 rows), 512 thr.
// ===========================================================================
__global__ __launch_bounds__(512, 1)
void k_fattn(const float* __restrict__ x,
             const float* __restrict__ latg, const float* __restrict__ latb,
             const float* __restrict__ bq, const float* __restrict__ bk,
             const float* __restrict__ bv, const float* __restrict__ bo) {
    extern __shared__ uint32_t sm[];
    uint32_t* As = sm;                   // 128 x 68 (half)  h, later o
    uint32_t* W0 = As + 8704;
    uint32_t* W1 = W0 + 8704;
    uint32_t* Qh = W1 + 8704;            // 128 x 68 (half)
    float* KVf = (float*)(Qh + 8704);    // 128 x 136 fp32
    float* sc = KVf + 17408;             // 1024
    float* sg = sc + 1024;               // 128
    float* sb = sg + 128;                // 128
    const int tid = threadIdx.x;
    const size_t rowbase = (size_t)blockIdx.x * 128;

    cpy68<512>(W0, gw_qkvo, 128, tid);         cp_commit();  // wq
    cpy68<512>(W1, gw_qkvo + 8192, 128, tid);  cp_commit();  // wk

    if (tid < 128) { sg[tid] = latg[tid]; sb[tid] = latb[tid]; }
    {   // LN -> As fp16
        const int r = tid >> 2, h = tid & 3;
        const float* xr = x + (rowbase + r) * 128 + h * 32;
        float xv[32];
        float s = 0.f, s2 = 0.f;
#pragma unroll
        for (int j = 0; j < 32; j += 4) {
            float4 v = *(const float4*)&xr[j];
            xv[j] = v.x; xv[j + 1] = v.y; xv[j + 2] = v.z; xv[j + 3] = v.w;
            s += v.x + v.y + v.z + v.w;
            s2 += v.x * v.x + v.y * v.y + v.z * v.z + v.w * v.w;
        }
        s  += __shfl_xor_sync(0xffffffffu, s, 1);
        s  += __shfl_xor_sync(0xffffffffu, s, 2);
        s2 += __shfl_xor_sync(0xffffffffu, s2, 1);
        s2 += __shfl_xor_sync(0xffffffffu, s2, 2);
        float mu = s * (1.f / 128.f);
        float rs = rsqrtf(s2 * (1.f / 128.f) - mu * mu + 1e-5f);
        __syncthreads();
        uint32_t* ar = As + r * 68 + h * 16;
#pragma unroll
        for (int j = 0; j < 32; j += 2) {
            int c = h * 32 + j;
            float h0 = (xv[j] - mu) * rs * sg[c] + sb[c];
            float h1 = (xv[j + 1] - mu) * rs * sg[c + 1] + sb[c + 1];
            ar[j >> 1] = pack2(h0, h1);
        }
    }
    __syncthreads();
    cp_wait<1>();
    __syncthreads();

    const int w = tid >> 5, lane = tid & 31, q = lane >> 2, t = lane & 3;
    const int mbase = (w & 7) * 16, nbase = (w >> 3) * 64;

    {   // Q gemm -> Qh fp16
        float acc[8][4];
        zero_acc(&acc[0][0], 32);
        gemm_h<68, 68, 8>(acc, As, W0, mbase, nbase, 64, q, t);
#pragma unroll
        for (int nt = 0; nt < 8; nt++) {
            int rr = mbase + q, cc = nbase + nt * 8 + 2 * t, wi = cc >> 1;
            float b0 = bq[cc], b1 = bq[cc + 1];
            Qh[rr * 68 + wi]       = pack2(acc[nt][0] + b0, acc[nt][1] + b1);
            Qh[(rr + 8) * 68 + wi] = pack2(acc[nt][2] + b0, acc[nt][3] + b1);
        }
    }
    __syncthreads();
    cpy68<512>(W0, gw_qkvo + 16384, 128, tid);     // wv
    cp_commit();
    cp_wait<1>();
    __syncthreads();
    {   // K gemm -> KVf fp32
        float acc[8][4];
        zero_acc(&acc[0][0], 32);
        gemm_h<68, 68, 8>(acc, As, W1, mbase, nbase, 64, q, t);
#pragma unroll
        for (int nt = 0; nt < 8; nt++) {
            int rr = mbase + q, cc = nbase + nt * 8 + 2 * t;
            float b0 = bk[cc], b1 = bk[cc + 1];
            KVf[rr * 136 + cc]           = acc[nt][0] + b0;
            KVf[rr * 136 + cc + 1]       = acc[nt][1] + b1;
            KVf[(rr + 8) * 136 + cc]     = acc[nt][2] + b0;
            KVf[(rr + 8) * 136 + cc + 1] = acc[nt][3] + b1;
        }
    }
    __syncthreads();
    cpy68<512>(W1, gw_qkvo + 24576, 128, tid);     // wo
    cp_commit();
    {   // scores
#pragma unroll
        for (int i = 0; i < 2; i++) {
            int p = tid + 512 * i;
            int rowq = p >> 3;
            int grp = p >> 6, e = p & 7;
            const uint32_t* qp = Qh + rowq * 68;
            const float* kp = KVf + (grp * 8 + e) * 136;
            float s = 0.f;
#pragma unroll 8
            for (int kw = 0; kw < 64; kw += 2) {
                float2 q0 = unp2(qp[kw]);
                float2 q1 = unp2(qp[kw + 1]);
                float4 kv = *(const float4*)&kp[2 * kw];
                s += q0.x * kv.x + q0.y * kv.y + q1.x * kv.z + q1.y * kv.w;
            }
            sc[p] = s * 0.088388347648318447f;
        }
    }
    __syncthreads();
    if (tid < 128) {    // softmax
        float* row = sc + tid * 8;
        float m = row[0];
#pragma unroll
        for (int e = 1; e < 8; e++) m = fmaxf(m, row[e]);
        float ex[8], ssum = 0.f;
#pragma unroll
        for (int e = 0; e < 8; e++) { ex[e] = expf(row[e] - m); ssum += ex[e]; }
        float inv = 1.0f / ssum;
#pragma unroll
        for (int e = 0; e < 8; e++) row[e] = ex[e] * inv;
    }
    cp_wait<1>();
    __syncthreads();
    {   // V gemm -> regs -> overwrite KVf
        float acc[8][4];
        zero_acc(&acc[0][0], 32);
        gemm_h<68, 68, 8>(acc, As, W0, mbase, nbase, 64, q, t);
        __syncthreads();
#pragma unroll
        for (int nt = 0; nt < 8; nt++) {
            int rr = mbase + q, cc = nbase + nt * 8 + 2 * t;
            float b0 = bv[cc], b1 = bv[cc + 1];
            KVf[rr * 136 + cc]           = acc[nt][0] + b0;
            KVf[rr * 136 + cc + 1]       = acc[nt][1] + b1;
            KVf[(rr + 8) * 136 + cc]     = acc[nt][2] + b0;
            KVf[(rr + 8) * 136 + cc + 1] = acc[nt][3] + b1;
        }
    }
    __syncthreads();
    {   // o = attn @ V -> As fp16
        int rr = tid >> 2, d0 = (tid & 3) * 32;
        const float* vb = KVf + (rr & ~7) * 136;
        float a[8];
#pragma unroll
        for (int e = 0; e < 8; e++) a[e] = sc[rr * 8 + e];
        uint32_t* ar = As + rr * 68 + (d0 >> 1);
#pragma unroll
        for (int j = 0; j < 32; j += 4) {
            float4 o = make_float4(0.f, 0.f, 0.f, 0.f);
#pragma unroll
            for (int e = 0; e < 8; e++) {
                float4 v = *(const float4*)&vb[e * 136 + d0 + j];
                o.x += a[e] * v.x; o.y += a[e] * v.y;
                o.z += a[e] * v.z; o.w += a[e] * v.w;
            }
            ar[(j >> 1)]     = pack2(o.x, o.y);
            ar[(j >> 1) + 1] = pack2(o.z, o.w);
        }
    }
    cp_wait<0>();
    __syncthreads();
    {   // wo gemm + residual -> g_xa
        float acc[8][4];
        zero_acc(&acc[0][0], 32);
        gemm_h<68, 68, 8>(acc, As, W1, mbase, nbase, 64, q, t);
#pragma unroll
        for (int nt = 0; nt < 8; nt++) {
            int rr = mbase + q, cc = nbase + nt * 8 + 2 * t;
            float b0 = bo[cc], b1 = bo[cc + 1];
            size_t o0 = (rowbase + rr) * 128 + cc;
            size_t o1 = (rowbase + rr + 8) * 128 + cc;
            float2 x0 = *(const float2*)&x[o0];
            float2 x1 = *(const float2*)&x[o1];
            *(float2*)&g_xa[o0] = make_float2(x0.x + acc[nt][0] + b0,
                                              x0.y + acc[nt][1] + b1);
            *(float2*)&g_xa[o1] = make_float2(x1.x + acc[nt][2] + b0,
                                              x1.y + acc[nt][3] + b1);
        }
    }
}

// ===========================================================================
// K2: mega per-group kernel, 64-token tiles, 256 thr, 2 CTAs/SM.
// grid (32, 64). words: As 4352 | Zs 2304 | Ds 2304 | B0 8704 | B1 8704 | 256
// ===========================================================================
__global__ __launch_bounds__(256, 2)
void k_mega(const float* __restrict__ zhp,
            const float* __restrict__ lng, const float* __restrict__ lnb,
            const float* __restrict__ encb, const float* __restrict__ predb,
            const float* __restrict__ gainb, const float* __restrict__ upb,
            const float* __restrict__ dwb, const float* __restrict__ pb,
            float* out) {
    extern __shared__ uint32_t sm[];
    uint32_t* As = sm;                  // 64 x 68 (half)
    uint32_t* Zs = As + 4352;           // 64 x 36 (half)
    uint32_t* Ds = Zs + 2304;           // 64 x 36 (half)
    uint32_t* B0 = Ds + 2304;           // 8704
    uint32_t* B1 = B0 + 8704;           // 8704
    float* smu = (float*)(B1 + 8704);   // 64
    float* srs = smu + 64;              // 64
    float* pr  = srs + 64;              // 128
    const int tid = threadIdx.x;
    const int g = blockIdx.y, p0 = blockIdx.x * 64;

    cpy68<256>(B0, gw_enc + (size_t)g * 4096, 64, tid);   cp_commit();
    cpy36<256>(B1, gw_pred + (size_t)g * 2048, 64, tid);  cp_commit();

    {   // As = fp16(x_attn), stats: 64 rows x 4 thr, 32 cols each
        const int r = tid >> 2, h = tid & 3;
        const float* xr = g_xa + ((size_t)(p0 + r) * 64 + g) * 128 + h * 32;
        float xv[32];
        float s = 0.f, s2 = 0.f;
#pragma unroll
        for (int j = 0; j < 32; j += 4) {
            float4 v = *(const float4*)&xr[j];
            xv[j] = v.x; xv[j + 1] = v.y; xv[j + 2] = v.z; xv[j + 3] = v.w;
            s += v.x + v.y + v.z + v.w;
            s2 += v.x * v.x + v.y * v.y + v.z * v.z + v.w * v.w;
        }
        uint32_t* ar = As + r * 68 + h * 16;
#pragma unroll
        for (int j = 0; j < 32; j += 2)
            ar[j >> 1] = pack2(xv[j], xv[j + 1]);
        s  += __shfl_xor_sync(0xffffffffu, s, 1);
        s  += __shfl_xor_sync(0xffffffffu, s, 2);
        s2 += __shfl_xor_sync(0xffffffffu, s2, 1);
        s2 += __shfl_xor_sync(0xffffffffu, s2, 2);
        float mu = s * (1.f / 128.f);
        if (h == 0) {
            smu[r] = mu;
            srs[r] = rsqrtf(s2 * (1.f / 128.f) - mu * mu + 1e-5f);
        }
    }
    cp_wait<1>();     // enc ready
    __syncthreads();

    const int w = tid >> 5, lane = tid & 31, q = lane >> 2, t = lane & 3;
    const int mbase = (w & 3) * 16, wn = w >> 2;

    {   // enc GEMM (16 x 32 per warp, Kw=64)
        float acc[4][4];
        zero_acc(&acc[0][0], 16);
        gemm_h<68, 68, 4>(acc, As, B0, mbase, wn * 32, 64, q, t);
        float sl = 0.f, sh = 0.f;
#pragma unroll
        for (int nt = 0; nt < 4; nt++) {
            int cc = wn * 32 + nt * 8 + 2 * t;
            int rlo = mbase + q, rhi = rlo + 8;
            float z0 = acc[nt][0] + encb[g * 64 + cc];
            float z1 = acc[nt][1] + encb[g * 64 + cc + 1];
            float z2 = acc[nt][2] + encb[g * 64 + cc];
            float z3 = acc[nt][3] + encb[g * 64 + cc + 1];
            size_t qlo = (size_t)(p0 + rlo) * 64 + g;
            size_t qhi = (size_t)(p0 + rhi) * 64 + g;
            *(float2*)&out[OFF_Z + qlo * 64 + cc] = make_float2(z0, z1);
            *(float2*)&out[OFF_Z + qhi * 64 + cc] = make_float2(z2, z3);
            float2 plo = *(const float2*)&zhp[qlo * 64 + cc];
            float2 phi = *(const float2*)&zhp[qhi * 64 + cc];
            float d0 = z0 - plo.x, d1 = z1 - plo.y;
            float d2 = z2 - phi.x, d3 = z3 - phi.y;
            int wi = cc >> 1;
            Zs[rlo * 36 + wi] = pack2(z0, z1);
            Zs[rhi * 36 + wi] = pack2(z2, z3);
            Ds[rlo * 36 + wi] = pack2(d0, d1);
            Ds[rhi * 36 + wi] = pack2(d2, d3);
            sl += d0 * d0 + d1 * d1;
            sh += d2 * d2 + d3 * d3;
        }
        sl += __shfl_xor_sync(0xffffffffu, sl, 1);
        sl += __shfl_xor_sync(0xffffffffu, sl, 2);
        sh += __shfl_xor_sync(0xffffffffu, sh, 1);
        sh += __shfl_xor_sync(0xffffffffu, sh, 2);
        if (t == 0) {
            pr[wn * 64 + mbase + q] = sl;
            pr[wn * 64 + mbase + q + 8] = sh;
        }
    }
    __syncthreads();
    if (tid < 64) {   // surprise + gate
        float sp = sqrtf(pr[tid] + pr[64 + tid]);
        size_t qq = (size_t)(p0 + tid) * 64 + g;
        out[OFF_S + qq] = sp;
        out[OFF_G + qq] = fminf(sp, 1.0f);
    }
    cpy68<256>(B0, gw_up + (size_t)g * 32768, 128, tid);     cp_commit();   // up0
    cp_wait<1>();                                            // pred ready
    __syncthreads();
    {   // pred GEMM (Kw=32)
        float acc[4][4];
        zero_acc(&acc[0][0], 16);
        gemm_h<36, 36, 4>(acc, Zs, B1, mbase, wn * 32, 32, q, t);
#pragma unroll
        for (int nt = 0; nt < 4; nt++) {
            int cc = wn * 32 + nt * 8 + 2 * t;
            size_t qlo = (size_t)(p0 + mbase + q) * 64 + g;
            size_t qhi = (size_t)(p0 + mbase + q + 8) * 64 + g;
            float b0 = predb[g * 64 + cc], b1 = predb[g * 64 + cc + 1];
            *(float2*)&out[OFF_ZH + qlo * 64 + cc] =
                make_float2(acc[nt][0] + b0, acc[nt][1] + b1);
            *(float2*)&out[OFF_ZH + qhi * 64 + cc] =
                make_float2(acc[nt][2] + b0, acc[nt][3] + b1);
        }
    }
    __syncthreads();
    cpy36<256>(B1, gw_gain + (size_t)g * 4096, 128, tid);    cp_commit();   // gain
    cp_wait<0>();
    __syncthreads();
    {   // gain GEMM (16x64 per warp, Kw=32) + GLN epilogue -> As := fp16(hh)
        float acc[8][4];
        zero_acc(&acc[0][0], 32);
        gemm_h<36, 36, 8>(acc, Ds, B1, mbase, wn * 64, 32, q, t);
        int rlo = mbase + q, rhi = rlo + 8;
        float mlo = smu[rlo], rslo = srs[rlo];
        float mhi = smu[rhi], rshi = srs[rhi];
#pragma unroll
        for (int nt = 0; nt < 8; nt++) {
            int cc = wn * 64 + nt * 8 + 2 * t, wi = cc >> 1;
            float lg0 = lng[(size_t)g * 128 + cc], lb0 = lnb[(size_t)g * 128 + cc];
            float lg1 = lng[(size_t)g * 128 + cc + 1], lb1 = lnb[(size_t)g * 128 + cc + 1];
            float gb0 = gainb[(size_t)g * 128 + cc], gb1 = gainb[(size_t)g * 128 + cc + 1];
            float2 xlo = unp2(As[rlo * 68 + wi]);
            float2 xhi = unp2(As[rhi * 68 + wi]);
            float h00 = ((xlo.x - mlo) * rslo * lg0 + lb0)
                        * (1.0f + 0.1f * tanhf(acc[nt][0] + gb0));
            float h01 = ((xlo.y - mlo) * rslo * lg1 + lb1)
                        * (1.0f + 0.1f * tanhf(acc[nt][1] + gb1));
            float h10 = ((xhi.x - mhi) * rshi * lg0 + lb0)
                        * (1.0f + 0.1f * tanhf(acc[nt][2] + gb0));
            float h11 = ((xhi.y - mhi) * rshi * lg1 + lb1)
                        * (1.0f + 0.1f * tanhf(acc[nt][3] + gb1));
            As[rlo * 68 + wi] = pack2(h00, h01);
            As[rhi * 68 + wi] = pack2(h10, h11);
        }
    }
    __syncthreads();
    cpy68<256>(B1, gw_down + (size_t)g * 32768, 128, tid);   cp_commit();   // down0

    uint32_t* Us = Zs;   // 64 x 68 overlays Zs+Ds (4352 <= 4608)
    float oacc[8][4];
    zero_acc(&oacc[0][0], 32);
    for (int ch = 0; ch < 4; ch++) {
        float uacc[8][4];
        zero_acc(&uacc[0][0], 32);
        gemm_h<68, 68, 8>(uacc, As, B0, mbase, wn * 64, 64, q, t);
#pragma unroll
        for (int nt = 0; nt < 8; nt++) {
            int cc = wn * 64 + nt * 8 + 2 * t, wi = cc >> 1;
            int rlo = mbase + q, rhi = rlo + 8;
            float b0 = upb[(size_t)g * 512 + ch * 128 + cc];
            float b1 = upb[(size_t)g * 512 + ch * 128 + cc + 1];
            float u00 = uacc[nt][0] + b0, u01 = uacc[nt][1] + b1;
            float u10 = uacc[nt][2] + b0, u11 = uacc[nt][3] + b1;
            u00 = 0.5f * u00 * (1.0f + erff(u00 * 0.70710678118654752f));
            u01 = 0.5f * u01 * (1.0f + erff(u01 * 0.70710678118654752f));
            u10 = 0.5f * u10 * (1.0f + erff(u10 * 0.70710678118654752f));
            u11 = 0.5f * u11 * (1.0f + erff(u11 * 0.70710678118654752f));
            Us[rlo * 68 + wi] = pack2(u00, u01);
            Us[rhi * 68 + wi] = pack2(u10, u11);
        }
        __syncthreads();
        if (ch < 3) {
            cpy68<256>(B0, gw_up + (size_t)g * 32768 + (ch + 1) * 8192, 128, tid);
            cp_commit();
            cp_wait<1>();
        } else {
            cp_wait<0>();
        }
        __syncthreads();
        gemm_h<68, 68, 8>(oacc, Us, B1, mbase, wn * 64, 64, q, t);
        if (ch < 3) {
            __syncthreads();
            cpy68<256>(B1, gw_down + (size_t)g * 32768 + (ch + 1) * 8192, 128, tid);
            cp_commit();
            cp_wait<1>();
            __syncthreads();
        }
    }
    __syncthreads();
    {   // MLP epilogue -> gmem x_out AND As := fp16(x_out)
#pragma unroll
        for (int nt = 0; nt < 8; nt++) {
            int cc = wn * 64 + nt * 8 + 2 * t, wi = cc >> 1;
            int rlo = mbase + q, rhi = rlo + 8;
            float b0 = dwb[(size_t)g * 128 + cc], b1 = dwb[(size_t)g * 128 + cc + 1];
            size_t o0 = ((size_t)(p0 + rlo) * 64 + g) * 128 + cc;
            size_t o1 = ((size_t)(p0 + rhi) * 64 + g) * 128 + cc;
            float2 x0 = *(const float2*)&g_xa[o0];
            float2 x1 = *(const float2*)&g_xa[o1];
            float v00 = x0.x + oacc[nt][0] + b0, v01 = x0.y + oacc[nt][1] + b1;
            float v10 = x1.x + oacc[nt][2] + b0, v11 = x1.y + oacc[nt][3] + b1;
            *(float2*)&out[OFF_XOUT + o0] = make_float2(v00, v01);
            *(float2*)&out[OFF_XOUT + o1] = make_float2(v10, v11);
            As[rlo * 68 + wi] = pack2(v00, v01);
            As[rhi * 68 + wi] = pack2(v10, v11);
        }
    }
    __syncthreads();
    cpy68<256>(B0, gw_post + (size_t)g * 32768, 128, tid);         cp_commit();
    cpy68<256>(B1, gw_post + (size_t)g * 32768 + 8192, 128, tid);  cp_commit();

    if (tid < 64) {   // w_nov
        const float* wl = gw_plast + g * 128;
        float s = 0.f;
        for (int kw = 0; kw < 64; kw++) {
            float2 xv = unp2(As[tid * 68 + kw]);
            s += xv.x * wl[2 * kw] + xv.y * wl[2 * kw + 1];
        }
        s += pb[(size_t)g * 513 + 512];
        out[OFF_WN + (size_t)(p0 + tid) * 64 + g] = 1.0f / (1.0f + expf(-s));
    }

    for (int ch = 0; ch < 4; ch++) {
        if (ch < 3) cp_wait<1>(); else cp_wait<0>();
        __syncthreads();
        uint32_t* Bs = (ch & 1) ? B1 : B0;
        float acc[8][4];
        zero_acc(&acc[0][0], 32);
        gemm_h<68, 68, 8>(acc, As, Bs, mbase, wn * 64, 64, q, t);
#pragma unroll
        for (int nt = 0; nt < 8; nt++) {
            int cc = wn * 64 + nt * 8 + 2 * t;
            float b0 = pb[(size_t)g * 513 + ch * 128 + cc];
            float b1 = pb[(size_t)g * 513 + ch * 128 + cc + 1];
            acc[nt][0] += b0; acc[nt][1] += b1;
            acc[nt][2] += b0; acc[nt][3] += b1;
        }
        if (ch == 1 || ch == 3) {
            size_t off = (ch == 1) ? OFF_VP : OFF_VC;
#pragma unroll
            for (int nt = 0; nt < 8; nt++) {
                int rr = mbase + q, cc = wn * 64 + nt * 8 + 2 * t;
                size_t o0 = off + ((size_t)(p0 + rr) * 64 + g) * 128 + cc;
                size_t o1 = off + ((size_t)(p0 + rr + 8) * 64 + g) * 128 + cc;
                *(float2*)&out[o0] = make_float2(acc[nt][0], acc[nt][1]);
                *(float2*)&out[o1] = make_float2(acc[nt][2], acc[nt][3]);
            }
        } else {
            float sl = 0.f, sh = 0.f;
#pragma unroll
            for (int nt = 0; nt < 8; nt++) {
                sl += acc[nt][0] * acc[nt][0] + acc[nt][1] * acc[nt][1];
                sh += acc[nt][2] * acc[nt][2] + acc[nt][3] * acc[nt][3];
            }
            sl += __shfl_xor_sync(0xffffffffu, sl, 1);
            sl += __shfl_xor_sync(0xffffffffu, sl, 2);
            sh += __shfl_xor_sync(0xffffffffu, sh, 1);
            sh += __shfl_xor_sync(0xffffffffu, sh, 2);
            if (t == 0) {
                pr[wn * 64 + mbase + q] = sl;
                pr[wn * 64 + mbase + q + 8] = sh;
            }
            __syncthreads();
            size_t off = (ch == 0) ? OFF_KC : OFF_QN;
#pragma unroll
            for (int nt = 0; nt < 8; nt++) {
                int rr = mbase + q, cc = wn * 64 + nt * 8 + 2 * t;
                float i0 = 1.0f / fmaxf(sqrtf(pr[rr] + pr[64 + rr]), 1e-6f);
                float i1 = 1.0f / fmaxf(sqrtf(pr[rr + 8] + pr[64 + rr + 8]), 1e-6f);
                size_t o0 = off + ((size_t)(p0 + rr) * 64 + g) * 128 + cc;
                size_t o1 = off + ((size_t)(p0 + rr + 8) * 64 + g) * 128 + cc;
                *(float2*)&out[o0] = make_float2(acc[nt][0] * i0, acc[nt][1] * i0);
                *(float2*)&out[o1] = make_float2(acc[nt][2] * i1, acc[nt][3] * i1);
            }
        }
        if (ch < 2) {
            __syncthreads();
            cpy68<256>((ch & 1) ? B1 : B0,
                       gw_post + (size_t)g * 32768 + (ch + 2) * 8192, 128, tid);
            cp_commit();
        }
    }
}

// ===========================================================================
extern "C" void kernel_launch(void* const* d_in, const int* in_sizes, int n_in,
                              void* d_out, int out_size) {
    const float* x_col  = (const float*)d_in[0];
    const float* zhp    = (const float*)d_in[1];
    const float* ln_g   = (const float*)d_in[2];
    const float* ln_b   = (const float*)d_in[3];
    const float* up_w   = (const float*)d_in[4];
    const float* up_b   = (const float*)d_in[5];
    const float* down_w = (const float*)d_in[6];
    const float* down_b = (const float*)d_in[7];
    const float* lat_g  = (const float*)d_in[8];
    const float* lat_b  = (const float*)d_in[9];
    const float* wq     = (const float*)d_in[10];
    const float* bq     = (const float*)d_in[11];
    const float* wk     = (const float*)d_in[12];
    const float* bk     = (const float*)d_in[13];
    const float* wv     = (const float*)d_in[14];
    const float* bv     = (const float*)d_in[15];
    const float* wo     = (const float*)d_in[16];
    const float* bo     = (const float*)d_in[17];
    const float* post_w = (const float*)d_in[18];
    const float* post_b = (const float*)d_in[19];
    const float* enc_w  = (const float*)d_in[20];
    const float* enc_b  = (const float*)d_in[21];
    const float* pred_w = (const float*)d_in[22];
    const float* pred_b = (const float*)d_in[23];
    const float* gain_w = (const float*)d_in[24];
    const float* gain_b = (const float*)d_in[25];
    float* out = (float*)d_out;

    const int SM_FA   = 53504 * 4;   // 214016
    const int SM_MEGA = 26624 * 4;   // 106496  (2 CTAs/SM)

    cudaFuncSetAttribute(k_fattn, cudaFuncAttributeMaxDynamicSharedMemorySize, SM_FA);
    cudaFuncSetAttribute(k_mega,  cudaFuncAttributeMaxDynamicSharedMemorySize, SM_MEGA);

    uint32_t* d_enc;  cudaGetSymbolAddress((void**)&d_enc,  gw_enc);
    uint32_t* d_pred; cudaGetSymbolAddress((void**)&d_pred, gw_pred);
    uint32_t* d_gain; cudaGetSymbolAddress((void**)&d_gain, gw_gain);
    uint32_t* d_up;   cudaGetSymbolAddress((void**)&d_up,   gw_up);
    uint32_t* d_down; cudaGetSymbolAddress((void**)&d_down, gw_down);
    uint32_t* d_post; cudaGetSymbolAddress((void**)&d_post, gw_post);

    k_tcvt_qkvo2<<<dim3(4, 4, 4), 256>>>(wq, wk, wv, wo);
    k_tcvt2<<<dim3(4, 2, 64), 256>>>(enc_w, d_enc, 8192, 64, 4096,
                                     6, 0, 7, 0, 63, 64, 127);
    k_tcvt2<<<dim3(2, 2, 64), 256>>>(pred_w, d_pred, 4096, 64, 2048,
                                     6, 0, 6, 0, 63, 32, 63);
    k_tcvt2<<<dim3(2, 4, 64), 256>>>(gain_w, d_gain, 8192, 128, 4096,
                                     7, 0, 6, 0, 127, 32, 63);
    k_tcvt2<<<dim3(4, 16, 64), 256>>>(up_w, d_up, 65536, 512, 32768,
                                      7, 8192, 7, 0, 127, 64, 127);
    k_tcvt2<<<dim3(16, 4, 64), 256>>>(down_w, d_down, 65536, 128, 32768,
                                      7, 0, 7, 8192, 127, 64, 127);
    k_tcvt2<<<dim3(4, 16, 64), 256>>>(post_w, d_post, 65664, 513, 32768,
                                      7, 8192, 7, 0, 127, 64, 127);
    k_plast<<<32, 256>>>(post_w);

    k_fattn<<<R_TOT / 128, 512, SM_FA>>>(x_col, lat_g, lat_b, bq, bk, bv, bo);
    k_mega<<<dim3(TOKS / 64, 64), 256, SM_MEGA>>>(zhp, ln_g, ln_b,
                                                  enc_b, pred_b, gain_b,
                                                  up_b, down_b, post_b, out);
}